// round 1
// baseline (speedup 1.0000x reference)
#include <cuda_runtime.h>
#include <cuda_bf16.h>
#include <math.h>

#define HIDDEN 2048
#define NHEADS 16
#define HD 128
#define RD 64
#define DQK 192
#define KVC 512
#define QC 1536
#define BATCH 2
#define SEQ 2048
#define ROWS (BATCH*SEQ)   // 4096

// ---------------- scratch (static device memory; no allocation allowed) -----
__device__ float g_kvc[ROWS*KVC];
__device__ float g_qlat[ROWS*QC];
__device__ float g_kc [ROWS*NHEADS*HD];
__device__ float g_vc [ROWS*NHEADS*HD];
__device__ float g_kr [ROWS*NHEADS*RD];
__device__ float g_qcu[ROWS*NHEADS*HD];
__device__ float g_qru[ROWS*NHEADS*RD];
__device__ float g_K  [(size_t)BATCH*NHEADS*SEQ*DQK];
__device__ float g_Q  [(size_t)BATCH*NHEADS*SEQ*DQK];
__device__ float g_V  [(size_t)BATCH*NHEADS*SEQ*HD];
__device__ float g_ctx[ROWS*NHEADS*HD];

// ---------------- generic SGEMM: C[M,N] = A[M,K] @ B[K,N] + bias ------------
// 128x128 tile, BK=16, 256 threads, 8x8 per thread. All dims multiples.
__global__ void __launch_bounds__(256) sgemm_bias(
    const float* __restrict__ A, const float* __restrict__ B,
    const float* __restrict__ bias, float* __restrict__ C,
    int M, int N, int K)
{
    __shared__ float As[16*132];   // transposed, padded (stride 132)
    __shared__ float Bs[16*128];

    const int tid = threadIdx.x;
    const int tx = tid & 15, ty = tid >> 4;
    const int m0 = blockIdx.y * 128, n0 = blockIdx.x * 128;

    float acc[8][8];
#pragma unroll
    for (int i = 0; i < 8; i++)
#pragma unroll
        for (int j = 0; j < 8; j++) acc[i][j] = 0.f;

    const int arow = tid >> 2, ac4 = tid & 3;    // A: 64 rows x 4 float4-cols
    const int brow = tid >> 5, bc4 = tid & 31;   // B: 8 rows x 32 float4-cols

    for (int kb = 0; kb < K; kb += 16) {
#pragma unroll
        for (int p = 0; p < 2; p++) {
            int row = arow + p * 64;
            float4 a = *(const float4*)&A[(size_t)(m0 + row) * K + kb + ac4 * 4];
            As[(ac4*4 + 0)*132 + row] = a.x;
            As[(ac4*4 + 1)*132 + row] = a.y;
            As[(ac4*4 + 2)*132 + row] = a.z;
            As[(ac4*4 + 3)*132 + row] = a.w;
        }
#pragma unroll
        for (int p = 0; p < 2; p++) {
            int row = brow + p * 8;
            float4 b = *(const float4*)&B[(size_t)(kb + row) * N + n0 + bc4 * 4];
            *(float4*)&Bs[row*128 + bc4*4] = b;
        }
        __syncthreads();
#pragma unroll
        for (int k = 0; k < 16; k++) {
            float4 a0 = *(const float4*)&As[k*132 + ty*8];
            float4 a1 = *(const float4*)&As[k*132 + ty*8 + 4];
            float4 b0 = *(const float4*)&Bs[k*128 + tx*8];
            float4 b1 = *(const float4*)&Bs[k*128 + tx*8 + 4];
            float av[8] = {a0.x,a0.y,a0.z,a0.w,a1.x,a1.y,a1.z,a1.w};
            float bv[8] = {b0.x,b0.y,b0.z,b0.w,b1.x,b1.y,b1.z,b1.w};
#pragma unroll
            for (int i = 0; i < 8; i++)
#pragma unroll
                for (int j = 0; j < 8; j++)
                    acc[i][j] = fmaf(av[i], bv[j], acc[i][j]);
        }
        __syncthreads();
    }

    float4 bb0 = *(const float4*)&bias[n0 + tx*8];
    float4 bb1 = *(const float4*)&bias[n0 + tx*8 + 4];
    float bv[8] = {bb0.x,bb0.y,bb0.z,bb0.w,bb1.x,bb1.y,bb1.z,bb1.w};
#pragma unroll
    for (int i = 0; i < 8; i++) {
        size_t off = (size_t)(m0 + ty*8 + i) * N + n0 + tx*8;
        float4 o0, o1;
        o0.x = acc[i][0]+bv[0]; o0.y = acc[i][1]+bv[1];
        o0.z = acc[i][2]+bv[2]; o0.w = acc[i][3]+bv[3];
        o1.x = acc[i][4]+bv[4]; o1.y = acc[i][5]+bv[5];
        o1.z = acc[i][6]+bv[6]; o1.w = acc[i][7]+bv[7];
        *(float4*)&C[off]     = o0;
        *(float4*)&C[off + 4] = o1;
    }
}

// ---------------- repack [B,S,H,D] -> [B,H,S,Dqk/Dv] ------------------------
__global__ void repack_c(const float* __restrict__ kc, const float* __restrict__ vc,
                         const float* __restrict__ qc,
                         float* __restrict__ K, float* __restrict__ V,
                         float* __restrict__ Q)
{
    int idx = blockIdx.x * blockDim.x + threadIdx.x;    // ROWS*NHEADS*HD
    if (idx >= ROWS*NHEADS*HD) return;
    int d  = idx & 127;
    int h  = (idx >> 7) & 15;
    int bs = idx >> 11;
    int b  = bs >> 11;          // SEQ = 2048
    int s  = bs & 2047;
    size_t o192 = (((size_t)b*NHEADS + h)*SEQ + s)*DQK + d;
    size_t o128 = (((size_t)b*NHEADS + h)*SEQ + s)*HD  + d;
    K[o192] = kc[idx];
    Q[o192] = qc[idx];
    V[o128] = vc[idx];
}

// ---------------- RoPE (interleaved pairs) into last 64 dims of K/Q ---------
__global__ void rope_pack(const float* __restrict__ kr, const float* __restrict__ qr,
                          float* __restrict__ K, float* __restrict__ Q)
{
    int idx = blockIdx.x * blockDim.x + threadIdx.x;    // ROWS*NHEADS*32
    if (idx >= ROWS*NHEADS*(RD/2)) return;
    int i  = idx & 31;
    int h  = (idx >> 5) & 15;
    int bs = idx >> 9;
    int b  = bs >> 11;
    int s  = bs & 2047;
    float inv_freq = powf(10000.f, -(float)(2*i) / 64.f);
    float ang = (float)s * inv_freq;
    float sn, cs;
    sincosf(ang, &sn, &cs);
    size_t ib = (size_t)bs * (NHEADS*RD) + h*RD + 2*i;
    size_t ob = (((size_t)b*NHEADS + h)*SEQ + s)*DQK + HD + 2*i;
    float x1 = kr[ib], x2 = kr[ib+1];
    K[ob]   = x1*cs - x2*sn;
    K[ob+1] = x1*sn + x2*cs;
    x1 = qr[ib]; x2 = qr[ib+1];
    Q[ob]   = x1*cs - x2*sn;
    Q[ob+1] = x1*sn + x2*cs;
}

// ---------------- causal flash attention -----------------------------------
// grid (SEQ/128, NHEADS, BATCH), 256 threads. BM=128 queries, BN=64 keys/iter.
#define KT_STRIDE 68
#define ATTN_SMEM ((128*192 + 192*KT_STRIDE + 64*128 + 128*64) * 4)

__global__ void __launch_bounds__(256, 1) attn_kernel(
    const float* __restrict__ Qg, const float* __restrict__ Kg,
    const float* __restrict__ Vg, float* __restrict__ ctx)
{
    extern __shared__ float sm[];
    float* Qs = sm;                       // [128][192]  natural
    float* Kt = Qs + 128*192;             // [192][KT_STRIDE] transposed, padded
    float* Vs = Kt + 192*KT_STRIDE;       // [64][128]   natural
    float* Ps = Vs + 64*128;              // [128][64]   natural

    const int b = blockIdx.z, h = blockIdx.y;
    const int q0 = blockIdx.x * 128;
    const int tid = threadIdx.x;
    const int tm = tid >> 4, tn = tid & 15;

    const float* Qbase = Qg + (((size_t)b*NHEADS + h)*SEQ + q0)*DQK;
    const float* Kbase = Kg + (((size_t)b*NHEADS + h)*SEQ)*DQK;
    const float* Vbase = Vg + (((size_t)b*NHEADS + h)*SEQ)*HD;

    // Q tile is one contiguous 128*192 float block
    {
        const float4* Q4 = (const float4*)Qbase;
        for (int i = tid; i < 128*48; i += 256)
            ((float4*)Qs)[i] = Q4[i];
    }

    float m_r[8], l_r[8], O[8][8];
#pragma unroll
    for (int r = 0; r < 8; r++) {
        m_r[r] = -INFINITY; l_r[r] = 0.f;
#pragma unroll
        for (int j = 0; j < 8; j++) O[r][j] = 0.f;
    }

    const float scale = 0.07216878364870323f;  // 1/sqrt(192)
    const int nt = q0 / 64 + 2;                // causal tile count

    for (int t = 0; t < nt; t++) {
        const int k0 = t * 64;
        __syncthreads();   // prior PV reads of Kt/Vs/Ps done (also covers Qs load 1st iter)

        {   // K tile -> transposed smem
            const float4* K4 = (const float4*)(Kbase + (size_t)k0 * DQK);
            for (int i = tid; i < 64*48; i += 256) {
                int n = i / 48, d4 = i % 48;
                float4 v = K4[i];
                int d = d4 * 4;
                Kt[(d+0)*KT_STRIDE + n] = v.x;
                Kt[(d+1)*KT_STRIDE + n] = v.y;
                Kt[(d+2)*KT_STRIDE + n] = v.z;
                Kt[(d+3)*KT_STRIDE + n] = v.w;
            }
            const float4* V4 = (const float4*)(Vbase + (size_t)k0 * HD);
            for (int i = tid; i < 64*32; i += 256)
                ((float4*)Vs)[i] = V4[i];
        }
        __syncthreads();

        // S = Q K^T for this tile: acc[8 rows][4 kcols]
        float acc[8][4];
#pragma unroll
        for (int r = 0; r < 8; r++)
#pragma unroll
            for (int c = 0; c < 4; c++) acc[r][c] = 0.f;

#pragma unroll 4
        for (int d = 0; d < DQK; d++) {
            float4 kv = *(const float4*)&Kt[d*KT_STRIDE + tn*4];
#pragma unroll
            for (int r = 0; r < 8; r++) {
                float qv = Qs[(tm*8 + r)*DQK + d];
                acc[r][0] = fmaf(qv, kv.x, acc[r][0]);
                acc[r][1] = fmaf(qv, kv.y, acc[r][1]);
                acc[r][2] = fmaf(qv, kv.z, acc[r][2]);
                acc[r][3] = fmaf(qv, kv.w, acc[r][3]);
            }
        }

        // online softmax per row (row = 16 threads sharing tm group)
#pragma unroll
        for (int r = 0; r < 8; r++) {
            int q = q0 + tm*8 + r;
            float s0 = (k0 + tn*4 + 0 <= q) ? acc[r][0]*scale : -INFINITY;
            float s1 = (k0 + tn*4 + 1 <= q) ? acc[r][1]*scale : -INFINITY;
            float s2 = (k0 + tn*4 + 2 <= q) ? acc[r][2]*scale : -INFINITY;
            float s3 = (k0 + tn*4 + 3 <= q) ? acc[r][3]*scale : -INFINITY;
            float tmax = fmaxf(fmaxf(s0, s1), fmaxf(s2, s3));
#pragma unroll
            for (int mk = 1; mk < 16; mk <<= 1)
                tmax = fmaxf(tmax, __shfl_xor_sync(0xffffffffu, tmax, mk));
            float mn = fmaxf(m_r[r], tmax);
            float alpha = __expf(m_r[r] - mn);
            s0 = __expf(s0 - mn); s1 = __expf(s1 - mn);
            s2 = __expf(s2 - mn); s3 = __expf(s3 - mn);
            float rs = s0 + s1 + s2 + s3;
#pragma unroll
            for (int mk = 1; mk < 16; mk <<= 1)
                rs += __shfl_xor_sync(0xffffffffu, rs, mk);
            l_r[r] = l_r[r]*alpha + rs;
            m_r[r] = mn;
#pragma unroll
            for (int j = 0; j < 8; j++) O[r][j] *= alpha;
            float* pr = &Ps[(tm*8 + r)*64 + tn*4];
            pr[0] = s0; pr[1] = s1; pr[2] = s2; pr[3] = s3;
        }
        __syncthreads();

        // O += P @ V   (P [128,64], V [64,128])
#pragma unroll 2
        for (int k = 0; k < 64; k++) {
            float4 v0 = *(const float4*)&Vs[k*128 + tn*8];
            float4 v1 = *(const float4*)&Vs[k*128 + tn*8 + 4];
#pragma unroll
            for (int r = 0; r < 8; r++) {
                float p = Ps[(tm*8 + r)*64 + k];
                O[r][0] = fmaf(p, v0.x, O[r][0]);
                O[r][1] = fmaf(p, v0.y, O[r][1]);
                O[r][2] = fmaf(p, v0.z, O[r][2]);
                O[r][3] = fmaf(p, v0.w, O[r][3]);
                O[r][4] = fmaf(p, v1.x, O[r][4]);
                O[r][5] = fmaf(p, v1.y, O[r][5]);
                O[r][6] = fmaf(p, v1.z, O[r][6]);
                O[r][7] = fmaf(p, v1.w, O[r][7]);
            }
        }
    }

    // write ctx in [b, s, h*128+d] layout (ready for the output GEMM)
#pragma unroll
    for (int r = 0; r < 8; r++) {
        float inv = 1.f / l_r[r];
        int q = q0 + tm*8 + r;
        float* dst = ctx + ((size_t)(b*SEQ + q))*(NHEADS*HD) + h*HD + tn*8;
#pragma unroll
        for (int j = 0; j < 8; j++) dst[j] = O[r][j] * inv;
    }
}

// ---------------- launch -----------------------------------------------------
extern "C" void kernel_launch(void* const* d_in, const int* in_sizes, int n_in,
                              void* d_out, int out_size)
{
    const float* x    = (const float*)d_in[0];
    // d_in[1] = attention_mask (all valid in this problem; causal-only)
    const float* kvdw = (const float*)d_in[2];
    const float* kvdb = (const float*)d_in[3];
    const float* kuw  = (const float*)d_in[4];
    const float* kub  = (const float*)d_in[5];
    const float* vuw  = (const float*)d_in[6];
    const float* vub  = (const float*)d_in[7];
    const float* krw  = (const float*)d_in[8];
    const float* krb  = (const float*)d_in[9];
    const float* qdw  = (const float*)d_in[10];
    const float* qdb  = (const float*)d_in[11];
    const float* quw  = (const float*)d_in[12];
    const float* qub  = (const float*)d_in[13];
    const float* qrw  = (const float*)d_in[14];
    const float* qrb  = (const float*)d_in[15];
    const float* ow   = (const float*)d_in[16];
    const float* obv  = (const float*)d_in[17];
    float* out = (float*)d_out;

    float *kvc, *qlat, *kc, *vc, *kr, *qcu, *qru, *K, *Q, *V, *ctx;
    cudaGetSymbolAddress((void**)&kvc,  g_kvc);
    cudaGetSymbolAddress((void**)&qlat, g_qlat);
    cudaGetSymbolAddress((void**)&kc,   g_kc);
    cudaGetSymbolAddress((void**)&vc,   g_vc);
    cudaGetSymbolAddress((void**)&kr,   g_kr);
    cudaGetSymbolAddress((void**)&qcu,  g_qcu);
    cudaGetSymbolAddress((void**)&qru,  g_qru);
    cudaGetSymbolAddress((void**)&K,    g_K);
    cudaGetSymbolAddress((void**)&Q,    g_Q);
    cudaGetSymbolAddress((void**)&V,    g_V);
    cudaGetSymbolAddress((void**)&ctx,  g_ctx);

    dim3 blk(256);

    // projections
    sgemm_bias<<<dim3(KVC/128,  ROWS/128), blk>>>(x,    kvdw, kvdb, kvc,  ROWS, KVC,        HIDDEN);
    sgemm_bias<<<dim3(2048/128, ROWS/128), blk>>>(kvc,  kuw,  kub,  kc,   ROWS, NHEADS*HD,  KVC);
    sgemm_bias<<<dim3(2048/128, ROWS/128), blk>>>(kvc,  vuw,  vub,  vc,   ROWS, NHEADS*HD,  KVC);
    sgemm_bias<<<dim3(1024/128, ROWS/128), blk>>>(kvc,  krw,  krb,  kr,   ROWS, NHEADS*RD,  KVC);
    sgemm_bias<<<dim3(QC/128,   ROWS/128), blk>>>(x,    qdw,  qdb,  qlat, ROWS, QC,         HIDDEN);
    sgemm_bias<<<dim3(2048/128, ROWS/128), blk>>>(qlat, quw,  qub,  qcu,  ROWS, NHEADS*HD,  QC);
    sgemm_bias<<<dim3(1024/128, ROWS/128), blk>>>(qlat, qrw,  qrb,  qru,  ROWS, NHEADS*RD,  QC);

    // layout change + rope
    repack_c<<<ROWS*NHEADS*HD/256, 256>>>(kc, vc, qcu, K, V, Q);
    rope_pack<<<ROWS*NHEADS*(RD/2)/256, 256>>>(kr, qru, K, Q);

    // attention
    cudaFuncSetAttribute(attn_kernel, cudaFuncAttributeMaxDynamicSharedMemorySize, ATTN_SMEM);
    attn_kernel<<<dim3(SEQ/128, NHEADS, BATCH), 256, ATTN_SMEM>>>(Q, K, V, ctx);

    // output projection
    sgemm_bias<<<dim3(2048/128, ROWS/128), blk>>>(ctx, ow, obv, out, ROWS, HIDDEN, NHEADS*HD);
}

// round 4
// speedup vs baseline: 1.5431x; 1.5431x over previous
#include <cuda_runtime.h>
#include <cuda_bf16.h>
#include <cstdint>
#include <math.h>

#define HIDDEN 2048
#define NHEADS 16
#define HD 128
#define RD 64
#define DQK 192
#define KVC 512
#define QC 1536
#define BATCH 2
#define SEQ 2048
#define ROWS (BATCH*SEQ)   // 4096

// ---------------- scratch (static device memory; no allocation allowed) -----
__device__ float g_kvc[ROWS*KVC];
__device__ float g_qlat[ROWS*QC];
__device__ float g_kc [ROWS*NHEADS*HD];
__device__ float g_vc [ROWS*NHEADS*HD];
__device__ float g_kr [ROWS*NHEADS*RD];
__device__ float g_qcu[ROWS*NHEADS*HD];
__device__ float g_qru[ROWS*NHEADS*RD];
__device__ float g_K  [(size_t)BATCH*NHEADS*SEQ*DQK];
__device__ float g_Q  [(size_t)BATCH*NHEADS*SEQ*DQK];
__device__ float g_V  [(size_t)BATCH*NHEADS*SEQ*HD];
__device__ float g_ctx[ROWS*NHEADS*HD];

// bf16 split buffers: activations (hi/lo), weights transposed to [N][K] (hi/lo)
__device__ __nv_bfloat16 g_xh [ROWS*HIDDEN],  g_xl [ROWS*HIDDEN];
__device__ __nv_bfloat16 g_kvch[ROWS*KVC],    g_kvcl[ROWS*KVC];
__device__ __nv_bfloat16 g_qlh [ROWS*QC],     g_qll [ROWS*QC];
__device__ __nv_bfloat16 g_cxh [ROWS*NHEADS*HD], g_cxl[ROWS*NHEADS*HD];

__device__ __nv_bfloat16 g_kvdwh[KVC*HIDDEN],        g_kvdwl[KVC*HIDDEN];
__device__ __nv_bfloat16 g_kuwh [NHEADS*HD*KVC],     g_kuwl [NHEADS*HD*KVC];
__device__ __nv_bfloat16 g_vuwh [NHEADS*HD*KVC],     g_vuwl [NHEADS*HD*KVC];
__device__ __nv_bfloat16 g_krwh [NHEADS*RD*KVC],     g_krwl [NHEADS*RD*KVC];
__device__ __nv_bfloat16 g_qdwh [QC*HIDDEN],         g_qdwl [QC*HIDDEN];
__device__ __nv_bfloat16 g_quwh [NHEADS*HD*QC],      g_quwl [NHEADS*HD*QC];
__device__ __nv_bfloat16 g_qrwh [NHEADS*RD*QC],      g_qrwl [NHEADS*RD*QC];
__device__ __nv_bfloat16 g_owh  [HIDDEN*NHEADS*HD],  g_owl  [HIDDEN*NHEADS*HD];

// ======================= mma / ldmatrix helpers =============================
__device__ __forceinline__ uint32_t s2u(const void* p) {
    return (uint32_t)__cvta_generic_to_shared(p);
}
__device__ __forceinline__ void ldsm4(uint32_t* r, uint32_t addr) {
    asm volatile("ldmatrix.sync.aligned.m8n8.x4.shared.b16 {%0,%1,%2,%3}, [%4];"
                 : "=r"(r[0]), "=r"(r[1]), "=r"(r[2]), "=r"(r[3]) : "r"(addr));
}
__device__ __forceinline__ void mma16816(float* c, const uint32_t* a, const uint32_t* b) {
    asm volatile(
        "mma.sync.aligned.m16n8k16.row.col.f32.bf16.bf16.f32 "
        "{%0,%1,%2,%3}, {%4,%5,%6,%7}, {%8,%9}, {%0,%1,%2,%3};"
        : "+f"(c[0]), "+f"(c[1]), "+f"(c[2]), "+f"(c[3])
        : "r"(a[0]), "r"(a[1]), "r"(a[2]), "r"(a[3]), "r"(b[0]), "r"(b[1]));
}
__device__ __forceinline__ void cpasync16(uint32_t dst, const void* src) {
    asm volatile("cp.async.cg.shared.global [%0], [%1], 16;"
                 :: "r"(dst), "l"(src) : "memory");
}

// ======================= fp32 -> bf16 hi/lo split ===========================
__global__ void split_fp32(const float* __restrict__ s,
                           __nv_bfloat16* __restrict__ h,
                           __nv_bfloat16* __restrict__ l, int n)
{
    int i = (blockIdx.x * blockDim.x + threadIdx.x) * 4;
    if (i >= n) return;
    float4 v = *(const float4*)(s + i);
    __nv_bfloat16 h0 = __float2bfloat16(v.x), h1 = __float2bfloat16(v.y);
    __nv_bfloat16 h2 = __float2bfloat16(v.z), h3 = __float2bfloat16(v.w);
    __nv_bfloat16 l0 = __float2bfloat16(v.x - __bfloat162float(h0));
    __nv_bfloat16 l1 = __float2bfloat16(v.y - __bfloat162float(h1));
    __nv_bfloat16 l2 = __float2bfloat16(v.z - __bfloat162float(h2));
    __nv_bfloat16 l3 = __float2bfloat16(v.w - __bfloat162float(h3));
    *(__nv_bfloat162*)(h + i)     = __halves2bfloat162(h0, h1);
    *(__nv_bfloat162*)(h + i + 2) = __halves2bfloat162(h2, h3);
    *(__nv_bfloat162*)(l + i)     = __halves2bfloat162(l0, l1);
    *(__nv_bfloat162*)(l + i + 2) = __halves2bfloat162(l2, l3);
}

// transpose + split: src[K][N] fp32 -> dst hi/lo [N][K] bf16
__global__ void transpose_split(const float* __restrict__ src,
                                __nv_bfloat16* __restrict__ dh,
                                __nv_bfloat16* __restrict__ dl,
                                int K, int N)
{
    __shared__ float t[32][33];
    int kb = blockIdx.y * 32, nb = blockIdx.x * 32;
    int tx = threadIdx.x, ty = threadIdx.y;    // 32 x 8
#pragma unroll
    for (int i = 0; i < 32; i += 8)
        t[ty + i][tx] = src[(size_t)(kb + ty + i) * N + nb + tx];
    __syncthreads();
#pragma unroll
    for (int i = 0; i < 32; i += 8) {
        float v = t[tx][ty + i];
        __nv_bfloat16 h = __float2bfloat16(v);
        __nv_bfloat16 l = __float2bfloat16(v - __bfloat162float(h));
        size_t o = (size_t)(nb + ty + i) * K + kb + tx;
        dh[o] = h; dl[o] = l;
    }
}

// ======================= HMMA split-bf16 GEMM ===============================
// C[M,N] = (Ah+Al)[M,K] @ (Bh+Bl)[N,K]^T + bias.
// CTA 128x128, BK=32, 8 warps (warp tile 32x64), double-buffered cp.async.
#define BKP 40                       // padded smem row stride (elements)
#define MAT_SMEM (128*BKP*2)         // 10240 B per matrix
#define STG_SMEM (4*MAT_SMEM)        // 40960 B per stage
#define GEMM_SMEM (2*STG_SMEM)       // 81920 B

__global__ void __launch_bounds__(256, 1) gemm_hmma_split(
    const __nv_bfloat16* __restrict__ Ah, const __nv_bfloat16* __restrict__ Al,
    const __nv_bfloat16* __restrict__ Bh, const __nv_bfloat16* __restrict__ Bl,
    const float* __restrict__ bias, float* __restrict__ C,
    int M, int N, int K)
{
    extern __shared__ char dsm[];
    const uint32_t sbase = s2u(dsm);

    const int tid  = threadIdx.x;
    const int warp = tid >> 5, lane = tid & 31;
    const int wm = (warp & 3) * 32;      // warp row offset in CTA tile
    const int wn = (warp >> 2) * 64;     // warp col offset
    const int m0 = blockIdx.y * 128, n0 = blockIdx.x * 128;

    // cp.async coordinates: per matrix, thread covers 2 rows x 1 chunk (16B)
    const int ldrow = tid >> 2;          // 0..63
    const int ldchk = (tid & 3) * 8;     // element offset of 16B chunk

    const __nv_bfloat16* gA[2] = { Ah + (size_t)m0 * K, Al + (size_t)m0 * K };
    const __nv_bfloat16* gB[2] = { Bh + (size_t)n0 * K, Bl + (size_t)n0 * K };

    const int nK = K >> 5;

    // ldmatrix per-lane address components
    const int a_r  = lane & 15;
    const int a_c8 = (lane >> 4) << 3;
    const int b_r  = (lane & 7) + ((lane >> 4) << 3);
    const int b_c8 = (lane & 8) ? 8 : 0;

    float acc[2][8][4];
#pragma unroll
    for (int mt = 0; mt < 2; mt++)
#pragma unroll
        for (int nt = 0; nt < 8; nt++)
#pragma unroll
            for (int q = 0; q < 4; q++) acc[mt][nt][q] = 0.f;

    auto load_stage = [&](int stg, int kb) {
        uint32_t sb = sbase + stg * STG_SMEM;
#pragma unroll
        for (int mat = 0; mat < 4; mat++) {
            const __nv_bfloat16* g = (mat < 2) ? gA[mat] : gB[mat - 2];
#pragma unroll
            for (int j = 0; j < 2; j++) {
                int row = ldrow + j * 64;
                cpasync16(sb + mat * MAT_SMEM + (row * BKP + ldchk) * 2,
                          g + (size_t)row * K + kb + ldchk);
            }
        }
        asm volatile("cp.async.commit_group;" ::: "memory");
    };

    load_stage(0, 0);
    load_stage(1, 32);

    for (int i = 0; i < nK; i++) {
        const int buf = i & 1;
        if (i + 1 < nK) asm volatile("cp.async.wait_group 1;" ::: "memory");
        else            asm volatile("cp.async.wait_group 0;" ::: "memory");
        __syncthreads();

        const uint32_t sAh = sbase + buf * STG_SMEM;
        const uint32_t sAl = sAh + MAT_SMEM;
        const uint32_t sBh = sAh + 2 * MAT_SMEM;
        const uint32_t sBl = sAh + 3 * MAT_SMEM;

#pragma unroll
        for (int kk = 0; kk < 32; kk += 16) {
            uint32_t ah[2][4], al[2][4], bh[4][4], bl[4][4];
#pragma unroll
            for (int mt = 0; mt < 2; mt++) {
                uint32_t off = ((wm + mt * 16 + a_r) * BKP + kk + a_c8) * 2;
                ldsm4(ah[mt], sAh + off);
                ldsm4(al[mt], sAl + off);
            }
#pragma unroll
            for (int p = 0; p < 4; p++) {
                uint32_t off = ((wn + p * 16 + b_r) * BKP + kk + b_c8) * 2;
                ldsm4(bh[p], sBh + off);
                ldsm4(bl[p], sBl + off);
            }
#pragma unroll
            for (int mt = 0; mt < 2; mt++)
#pragma unroll
                for (int nt = 0; nt < 8; nt++) {
                    const uint32_t* bhf = &bh[nt >> 1][(nt & 1) * 2];
                    const uint32_t* blf = &bl[nt >> 1][(nt & 1) * 2];
                    mma16816(acc[mt][nt], ah[mt], bhf);
                    mma16816(acc[mt][nt], ah[mt], blf);
                    mma16816(acc[mt][nt], al[mt], bhf);
                }
        }
        __syncthreads();
        if (i + 2 < nK) load_stage(buf, (i + 2) * 32);
    }

    // epilogue
    const int er = lane >> 2, ec = (lane & 3) * 2;
#pragma unroll
    for (int mt = 0; mt < 2; mt++) {
#pragma unroll
        for (int nt = 0; nt < 8; nt++) {
            int col = n0 + wn + nt * 8 + ec;
            float b0 = bias[col], b1 = bias[col + 1];
            int r0 = m0 + wm + mt * 16 + er;
            float2 v0 = { acc[mt][nt][0] + b0, acc[mt][nt][1] + b1 };
            float2 v1 = { acc[mt][nt][2] + b0, acc[mt][nt][3] + b1 };
            *(float2*)&C[(size_t)r0 * N + col]       = v0;
            *(float2*)&C[(size_t)(r0 + 8) * N + col] = v1;
        }
    }
}

// ---------------- repack [B,S,H,D] -> [B,H,S,Dqk/Dv] ------------------------
__global__ void repack_c(const float* __restrict__ kc, const float* __restrict__ vc,
                         const float* __restrict__ qc,
                         float* __restrict__ K, float* __restrict__ V,
                         float* __restrict__ Q)
{
    int idx = blockIdx.x * blockDim.x + threadIdx.x;
    if (idx >= ROWS*NHEADS*HD) return;
    int d  = idx & 127;
    int h  = (idx >> 7) & 15;
    int bs = idx >> 11;
    int b  = bs >> 11;
    int s  = bs & 2047;
    size_t o192 = (((size_t)b*NHEADS + h)*SEQ + s)*DQK + d;
    size_t o128 = (((size_t)b*NHEADS + h)*SEQ + s)*HD  + d;
    K[o192] = kc[idx];
    Q[o192] = qc[idx];
    V[o128] = vc[idx];
}

// ---------------- RoPE (interleaved pairs) into last 64 dims of K/Q ---------
__global__ void rope_pack(const float* __restrict__ kr, const float* __restrict__ qr,
                          float* __restrict__ K, float* __restrict__ Q)
{
    int idx = blockIdx.x * blockDim.x + threadIdx.x;
    if (idx >= ROWS*NHEADS*(RD/2)) return;
    int i  = idx & 31;
    int h  = (idx >> 5) & 15;
    int bs = idx >> 9;
    int b  = bs >> 11;
    int s  = bs & 2047;
    float inv_freq = powf(10000.f, -(float)(2*i) / 64.f);
    float ang = (float)s * inv_freq;
    float sn, cs;
    sincosf(ang, &sn, &cs);
    size_t ib = (size_t)bs * (NHEADS*RD) + h*RD + 2*i;
    size_t ob = (((size_t)b*NHEADS + h)*SEQ + s)*DQK + HD + 2*i;
    float x1 = kr[ib], x2 = kr[ib+1];
    K[ob]   = x1*cs - x2*sn;
    K[ob+1] = x1*sn + x2*cs;
    x1 = qr[ib]; x2 = qr[ib+1];
    Q[ob]   = x1*cs - x2*sn;
    Q[ob+1] = x1*sn + x2*cs;
}

// ---------------- causal flash attention (fp32 SIMT) ------------------------
#define KT_STRIDE 68
#define ATTN_SMEM ((128*192 + 192*KT_STRIDE + 64*128 + 128*64) * 4)

__global__ void __launch_bounds__(256, 1) attn_kernel(
    const float* __restrict__ Qg, const float* __restrict__ Kg,
    const float* __restrict__ Vg, float* __restrict__ ctx)
{
    extern __shared__ float sm[];
    float* Qs = sm;
    float* Kt = Qs + 128*192;
    float* Vs = Kt + 192*KT_STRIDE;
    float* Ps = Vs + 64*128;

    const int b = blockIdx.z, h = blockIdx.y;
    const int q0 = blockIdx.x * 128;
    const int tid = threadIdx.x;
    const int tm = tid >> 4, tn = tid & 15;

    const float* Qbase = Qg + (((size_t)b*NHEADS + h)*SEQ + q0)*DQK;
    const float* Kbase = Kg + (((size_t)b*NHEADS + h)*SEQ)*DQK;
    const float* Vbase = Vg + (((size_t)b*NHEADS + h)*SEQ)*HD;

    {
        const float4* Q4 = (const float4*)Qbase;
        for (int i = tid; i < 128*48; i += 256)
            ((float4*)Qs)[i] = Q4[i];
    }

    float m_r[8], l_r[8], O[8][8];
#pragma unroll
    for (int r = 0; r < 8; r++) {
        m_r[r] = -INFINITY; l_r[r] = 0.f;
#pragma unroll
        for (int j = 0; j < 8; j++) O[r][j] = 0.f;
    }

    const float scale = 0.07216878364870323f;
    const int nt = q0 / 64 + 2;

    for (int t = 0; t < nt; t++) {
        const int k0 = t * 64;
        __syncthreads();
        {
            const float4* K4 = (const float4*)(Kbase + (size_t)k0 * DQK);
            for (int i = tid; i < 64*48; i += 256) {
                int n = i / 48, d4 = i % 48;
                float4 v = K4[i];
                int d = d4 * 4;
                Kt[(d+0)*KT_STRIDE + n] = v.x;
                Kt[(d+1)*KT_STRIDE + n] = v.y;
                Kt[(d+2)*KT_STRIDE + n] = v.z;
                Kt[(d+3)*KT_STRIDE + n] = v.w;
            }
            const float4* V4 = (const float4*)(Vbase + (size_t)k0 * HD);
            for (int i = tid; i < 64*32; i += 256)
                ((float4*)Vs)[i] = V4[i];
        }
        __syncthreads();

        float acc[8][4];
#pragma unroll
        for (int r = 0; r < 8; r++)
#pragma unroll
            for (int c = 0; c < 4; c++) acc[r][c] = 0.f;

#pragma unroll 4
        for (int d = 0; d < DQK; d++) {
            float4 kv = *(const float4*)&Kt[d*KT_STRIDE + tn*4];
#pragma unroll
            for (int r = 0; r < 8; r++) {
                float qv = Qs[(tm*8 + r)*DQK + d];
                acc[r][0] = fmaf(qv, kv.x, acc[r][0]);
                acc[r][1] = fmaf(qv, kv.y, acc[r][1]);
                acc[r][2] = fmaf(qv, kv.z, acc[r][2]);
                acc[r][3] = fmaf(qv, kv.w, acc[r][3]);
            }
        }

#pragma unroll
        for (int r = 0; r < 8; r++) {
            int q = q0 + tm*8 + r;
            float s0 = (k0 + tn*4 + 0 <= q) ? acc[r][0]*scale : -INFINITY;
            float s1 = (k0 + tn*4 + 1 <= q) ? acc[r][1]*scale : -INFINITY;
            float s2 = (k0 + tn*4 + 2 <= q) ? acc[r][2]*scale : -INFINITY;
            float s3 = (k0 + tn*4 + 3 <= q) ? acc[r][3]*scale : -INFINITY;
            float tmax = fmaxf(fmaxf(s0, s1), fmaxf(s2, s3));
#pragma unroll
            for (int mk = 1; mk < 16; mk <<= 1)
                tmax = fmaxf(tmax, __shfl_xor_sync(0xffffffffu, tmax, mk));
            float mn = fmaxf(m_r[r], tmax);
            float alpha = __expf(m_r[r] - mn);
            s0 = __expf(s0 - mn); s1 = __expf(s1 - mn);
            s2 = __expf(s2 - mn); s3 = __expf(s3 - mn);
            float rs = s0 + s1 + s2 + s3;
#pragma unroll
            for (int mk = 1; mk < 16; mk <<= 1)
                rs += __shfl_xor_sync(0xffffffffu, rs, mk);
            l_r[r] = l_r[r]*alpha + rs;
            m_r[r] = mn;
#pragma unroll
            for (int j = 0; j < 8; j++) O[r][j] *= alpha;
            float* pr = &Ps[(tm*8 + r)*64 + tn*4];
            pr[0] = s0; pr[1] = s1; pr[2] = s2; pr[3] = s3;
        }
        __syncthreads();

#pragma unroll 2
        for (int k = 0; k < 64; k++) {
            float4 v0 = *(const float4*)&Vs[k*128 + tn*8];
            float4 v1 = *(const float4*)&Vs[k*128 + tn*8 + 4];
#pragma unroll
            for (int r = 0; r < 8; r++) {
                float p = Ps[(tm*8 + r)*64 + k];
                O[r][0] = fmaf(p, v0.x, O[r][0]);
                O[r][1] = fmaf(p, v0.y, O[r][1]);
                O[r][2] = fmaf(p, v0.z, O[r][2]);
                O[r][3] = fmaf(p, v0.w, O[r][3]);
                O[r][4] = fmaf(p, v1.x, O[r][4]);
                O[r][5] = fmaf(p, v1.y, O[r][5]);
                O[r][6] = fmaf(p, v1.z, O[r][6]);
                O[r][7] = fmaf(p, v1.w, O[r][7]);
            }
        }
    }

#pragma unroll
    for (int r = 0; r < 8; r++) {
        float inv = 1.f / l_r[r];
        int q = q0 + tm*8 + r;
        float* dst = ctx + ((size_t)(b*SEQ + q))*(NHEADS*HD) + h*HD + tn*8;
#pragma unroll
        for (int j = 0; j < 8; j++) dst[j] = O[r][j] * inv;
    }
}

// ---------------- launch -----------------------------------------------------
static inline void gemm_ts(const __nv_bfloat16* Ah, const __nv_bfloat16* Al,
                           const __nv_bfloat16* Bh, const __nv_bfloat16* Bl,
                           const float* bias, float* C, int M, int N, int K)
{
    gemm_hmma_split<<<dim3(N/128, M/128), 256, GEMM_SMEM>>>(Ah, Al, Bh, Bl, bias, C, M, N, K);
}

extern "C" void kernel_launch(void* const* d_in, const int* in_sizes, int n_in,
                              void* d_out, int out_size)
{
    const float* x    = (const float*)d_in[0];
    const float* kvdw = (const float*)d_in[2];
    const float* kvdb = (const float*)d_in[3];
    const float* kuw  = (const float*)d_in[4];
    const float* kub  = (const float*)d_in[5];
    const float* vuw  = (const float*)d_in[6];
    const float* vub  = (const float*)d_in[7];
    const float* krw  = (const float*)d_in[8];
    const float* krb  = (const float*)d_in[9];
    const float* qdw  = (const float*)d_in[10];
    const float* qdb  = (const float*)d_in[11];
    const float* quw  = (const float*)d_in[12];
    const float* qub  = (const float*)d_in[13];
    const float* qrw  = (const float*)d_in[14];
    const float* qrb  = (const float*)d_in[15];
    const float* ow   = (const float*)d_in[16];
    const float* obv  = (const float*)d_in[17];
    float* out = (float*)d_out;

    float *kvc, *qlat, *kc, *vc, *kr, *qcu, *qru, *K, *Q, *V, *ctx;
    cudaGetSymbolAddress((void**)&kvc,  g_kvc);
    cudaGetSymbolAddress((void**)&qlat, g_qlat);
    cudaGetSymbolAddress((void**)&kc,   g_kc);
    cudaGetSymbolAddress((void**)&vc,   g_vc);
    cudaGetSymbolAddress((void**)&kr,   g_kr);
    cudaGetSymbolAddress((void**)&qcu,  g_qcu);
    cudaGetSymbolAddress((void**)&qru,  g_qru);
    cudaGetSymbolAddress((void**)&K,    g_K);
    cudaGetSymbolAddress((void**)&Q,    g_Q);
    cudaGetSymbolAddress((void**)&V,    g_V);
    cudaGetSymbolAddress((void**)&ctx,  g_ctx);

    __nv_bfloat16 *xh,*xl,*kvch,*kvcl,*qlh,*qll,*cxh,*cxl;
    __nv_bfloat16 *kvdwh,*kvdwl,*kuwh,*kuwl,*vuwh,*vuwl,*krwh,*krwl;
    __nv_bfloat16 *qdwh,*qdwl,*quwh,*quwl,*qrwh,*qrwl,*owh,*owl;
    cudaGetSymbolAddress((void**)&xh, g_xh);     cudaGetSymbolAddress((void**)&xl, g_xl);
    cudaGetSymbolAddress((void**)&kvch, g_kvch); cudaGetSymbolAddress((void**)&kvcl, g_kvcl);
    cudaGetSymbolAddress((void**)&qlh, g_qlh);   cudaGetSymbolAddress((void**)&qll, g_qll);
    cudaGetSymbolAddress((void**)&cxh, g_cxh);   cudaGetSymbolAddress((void**)&cxl, g_cxl);
    cudaGetSymbolAddress((void**)&kvdwh, g_kvdwh); cudaGetSymbolAddress((void**)&kvdwl, g_kvdwl);
    cudaGetSymbolAddress((void**)&kuwh, g_kuwh);   cudaGetSymbolAddress((void**)&kuwl, g_kuwl);
    cudaGetSymbolAddress((void**)&vuwh, g_vuwh);   cudaGetSymbolAddress((void**)&vuwl, g_vuwl);
    cudaGetSymbolAddress((void**)&krwh, g_krwh);   cudaGetSymbolAddress((void**)&krwl, g_krwl);
    cudaGetSymbolAddress((void**)&qdwh, g_qdwh);   cudaGetSymbolAddress((void**)&qdwl, g_qdwl);
    cudaGetSymbolAddress((void**)&quwh, g_quwh);   cudaGetSymbolAddress((void**)&quwl, g_quwl);
    cudaGetSymbolAddress((void**)&qrwh, g_qrwh);   cudaGetSymbolAddress((void**)&qrwl, g_qrwl);
    cudaGetSymbolAddress((void**)&owh, g_owh);     cudaGetSymbolAddress((void**)&owl, g_owl);

    cudaFuncSetAttribute(gemm_hmma_split, cudaFuncAttributeMaxDynamicSharedMemorySize, GEMM_SMEM);
    cudaFuncSetAttribute(attn_kernel, cudaFuncAttributeMaxDynamicSharedMemorySize, ATTN_SMEM);

    dim3 tb(32, 8);

    // weight transpose+split: src [K][N] -> [N][K] hi/lo
    transpose_split<<<dim3(KVC/32,       HIDDEN/32), tb>>>(kvdw, kvdwh, kvdwl, HIDDEN, KVC);
    transpose_split<<<dim3(NHEADS*HD/32, KVC/32),    tb>>>(kuw,  kuwh,  kuwl,  KVC, NHEADS*HD);
    transpose_split<<<dim3(NHEADS*HD/32, KVC/32),    tb>>>(vuw,  vuwh,  vuwl,  KVC, NHEADS*HD);
    transpose_split<<<dim3(NHEADS*RD/32, KVC/32),    tb>>>(krw,  krwh,  krwl,  KVC, NHEADS*RD);
    transpose_split<<<dim3(QC/32,        HIDDEN/32), tb>>>(qdw,  qdwh,  qdwl,  HIDDEN, QC);
    transpose_split<<<dim3(NHEADS*HD/32, QC/32),     tb>>>(quw,  quwh,  quwl,  QC, NHEADS*HD);
    transpose_split<<<dim3(NHEADS*RD/32, QC/32),     tb>>>(qrw,  qrwh,  qrwl,  QC, NHEADS*RD);
    transpose_split<<<dim3(HIDDEN/32,    NHEADS*HD/32), tb>>>(ow, owh, owl, NHEADS*HD, HIDDEN);

    // x split
    split_fp32<<<ROWS*HIDDEN/4/256, 256>>>(x, xh, xl, ROWS*HIDDEN);

    // kv path
    gemm_ts(xh, xl, kvdwh, kvdwl, kvdb, kvc, ROWS, KVC, HIDDEN);
    split_fp32<<<ROWS*KVC/4/256, 256>>>(kvc, kvch, kvcl, ROWS*KVC);
    gemm_ts(kvch, kvcl, kuwh, kuwl, kub, kc, ROWS, NHEADS*HD, KVC);
    gemm_ts(kvch, kvcl, vuwh, vuwl, vub, vc, ROWS, NHEADS*HD, KVC);
    gemm_ts(kvch, kvcl, krwh, krwl, krb, kr, ROWS, NHEADS*RD, KVC);

    // q path
    gemm_ts(xh, xl, qdwh, qdwl, qdb, qlat, ROWS, QC, HIDDEN);
    split_fp32<<<ROWS*QC/4/256, 256>>>(qlat, qlh, qll, ROWS*QC);
    gemm_ts(qlh, qll, quwh, quwl, qub, qcu, ROWS, NHEADS*HD, QC);
    gemm_ts(qlh, qll, qrwh, qrwl, qrb, qru, ROWS, NHEADS*RD, QC);

    // layout change + rope
    repack_c<<<ROWS*NHEADS*HD/256, 256>>>(kc, vc, qcu, K, V, Q);
    rope_pack<<<ROWS*NHEADS*(RD/2)/256, 256>>>(kr, qru, K, Q);

    // attention (fp32)
    attn_kernel<<<dim3(SEQ/128, NHEADS, BATCH), 256, ATTN_SMEM>>>(Q, K, V, ctx);

    // output projection
    split_fp32<<<ROWS*NHEADS*HD/4/256, 256>>>(ctx, cxh, cxl, ROWS*NHEADS*HD);
    gemm_ts(cxh, cxl, owh, owl, obv, out, ROWS, HIDDEN, NHEADS*HD);
}

// round 5
// speedup vs baseline: 2.4605x; 1.5945x over previous
#include <cuda_runtime.h>
#include <cuda_bf16.h>
#include <cstdint>
#include <math.h>

#define HIDDEN 2048
#define NHEADS 16
#define HD 128
#define RD 64
#define DQK 192
#define KVC 512
#define QC 1536
#define BATCH 2
#define SEQ 2048
#define ROWS (BATCH*SEQ)   // 4096

// ---------------- scratch (static device memory; no allocation allowed) -----
__device__ float g_kvc[ROWS*KVC];
__device__ float g_qlat[ROWS*QC];
__device__ float g_kc [ROWS*NHEADS*HD];
__device__ float g_vc [ROWS*NHEADS*HD];
__device__ float g_kr [ROWS*NHEADS*RD];
__device__ float g_qcu[ROWS*NHEADS*HD];
__device__ float g_qru[ROWS*NHEADS*RD];

// split bf16 attention operands [B,H,S,*]
__device__ __nv_bfloat16 g_Qh[(size_t)BATCH*NHEADS*SEQ*DQK], g_Ql[(size_t)BATCH*NHEADS*SEQ*DQK];
__device__ __nv_bfloat16 g_Kh[(size_t)BATCH*NHEADS*SEQ*DQK], g_Kl[(size_t)BATCH*NHEADS*SEQ*DQK];
__device__ __nv_bfloat16 g_Vh[(size_t)BATCH*NHEADS*SEQ*HD],  g_Vl[(size_t)BATCH*NHEADS*SEQ*HD];

// bf16 split buffers: activations (hi/lo), weights transposed to [N][K] (hi/lo)
__device__ __nv_bfloat16 g_xh [ROWS*HIDDEN],  g_xl [ROWS*HIDDEN];
__device__ __nv_bfloat16 g_kvch[ROWS*KVC],    g_kvcl[ROWS*KVC];
__device__ __nv_bfloat16 g_qlh [ROWS*QC],     g_qll [ROWS*QC];
__device__ __nv_bfloat16 g_cxh [ROWS*NHEADS*HD], g_cxl[ROWS*NHEADS*HD];

__device__ __nv_bfloat16 g_kvdwh[KVC*HIDDEN],        g_kvdwl[KVC*HIDDEN];
__device__ __nv_bfloat16 g_kuwh [NHEADS*HD*KVC],     g_kuwl [NHEADS*HD*KVC];
__device__ __nv_bfloat16 g_vuwh [NHEADS*HD*KVC],     g_vuwl [NHEADS*HD*KVC];
__device__ __nv_bfloat16 g_krwh [NHEADS*RD*KVC],     g_krwl [NHEADS*RD*KVC];
__device__ __nv_bfloat16 g_qdwh [QC*HIDDEN],         g_qdwl [QC*HIDDEN];
__device__ __nv_bfloat16 g_quwh [NHEADS*HD*QC],      g_quwl [NHEADS*HD*QC];
__device__ __nv_bfloat16 g_qrwh [NHEADS*RD*QC],      g_qrwl [NHEADS*RD*QC];
__device__ __nv_bfloat16 g_owh  [HIDDEN*NHEADS*HD],  g_owl  [HIDDEN*NHEADS*HD];

// ======================= mma / ldmatrix helpers =============================
__device__ __forceinline__ uint32_t s2u(const void* p) {
    return (uint32_t)__cvta_generic_to_shared(p);
}
__device__ __forceinline__ void ldsm4(uint32_t* r, uint32_t addr) {
    asm volatile("ldmatrix.sync.aligned.m8n8.x4.shared.b16 {%0,%1,%2,%3}, [%4];"
                 : "=r"(r[0]), "=r"(r[1]), "=r"(r[2]), "=r"(r[3]) : "r"(addr));
}
__device__ __forceinline__ void ldsm4t(uint32_t* r, uint32_t addr) {
    asm volatile("ldmatrix.sync.aligned.m8n8.x4.trans.shared.b16 {%0,%1,%2,%3}, [%4];"
                 : "=r"(r[0]), "=r"(r[1]), "=r"(r[2]), "=r"(r[3]) : "r"(addr));
}
__device__ __forceinline__ void mma16816(float* c, const uint32_t* a, const uint32_t* b) {
    asm volatile(
        "mma.sync.aligned.m16n8k16.row.col.f32.bf16.bf16.f32 "
        "{%0,%1,%2,%3}, {%4,%5,%6,%7}, {%8,%9}, {%0,%1,%2,%3};"
        : "+f"(c[0]), "+f"(c[1]), "+f"(c[2]), "+f"(c[3])
        : "r"(a[0]), "r"(a[1]), "r"(a[2]), "r"(a[3]), "r"(b[0]), "r"(b[1]));
}
__device__ __forceinline__ void mma16816s(float* c, const uint32_t* a, uint32_t b0, uint32_t b1) {
    asm volatile(
        "mma.sync.aligned.m16n8k16.row.col.f32.bf16.bf16.f32 "
        "{%0,%1,%2,%3}, {%4,%5,%6,%7}, {%8,%9}, {%0,%1,%2,%3};"
        : "+f"(c[0]), "+f"(c[1]), "+f"(c[2]), "+f"(c[3])
        : "r"(a[0]), "r"(a[1]), "r"(a[2]), "r"(a[3]), "r"(b0), "r"(b1));
}
__device__ __forceinline__ void cpasync16(uint32_t dst, const void* src) {
    asm volatile("cp.async.cg.shared.global [%0], [%1], 16;"
                 :: "r"(dst), "l"(src) : "memory");
}
__device__ __forceinline__ uint32_t pack2bf(float x, float y) {
    __nv_bfloat162 t = __floats2bfloat162_rn(x, y);
    return *(uint32_t*)&t;
}

// ======================= fp32 -> bf16 hi/lo split ===========================
__global__ void split_fp32(const float* __restrict__ s,
                           __nv_bfloat16* __restrict__ h,
                           __nv_bfloat16* __restrict__ l, int n)
{
    int i = (blockIdx.x * blockDim.x + threadIdx.x) * 4;
    if (i >= n) return;
    float4 v = *(const float4*)(s + i);
    __nv_bfloat16 h0 = __float2bfloat16(v.x), h1 = __float2bfloat16(v.y);
    __nv_bfloat16 h2 = __float2bfloat16(v.z), h3 = __float2bfloat16(v.w);
    __nv_bfloat16 l0 = __float2bfloat16(v.x - __bfloat162float(h0));
    __nv_bfloat16 l1 = __float2bfloat16(v.y - __bfloat162float(h1));
    __nv_bfloat16 l2 = __float2bfloat16(v.z - __bfloat162float(h2));
    __nv_bfloat16 l3 = __float2bfloat16(v.w - __bfloat162float(h3));
    *(__nv_bfloat162*)(h + i)     = __halves2bfloat162(h0, h1);
    *(__nv_bfloat162*)(h + i + 2) = __halves2bfloat162(h2, h3);
    *(__nv_bfloat162*)(l + i)     = __halves2bfloat162(l0, l1);
    *(__nv_bfloat162*)(l + i + 2) = __halves2bfloat162(l2, l3);
}

// transpose + split: src[K][N] fp32 -> dst hi/lo [N][K] bf16
__global__ void transpose_split(const float* __restrict__ src,
                                __nv_bfloat16* __restrict__ dh,
                                __nv_bfloat16* __restrict__ dl,
                                int K, int N)
{
    __shared__ float t[32][33];
    int kb = blockIdx.y * 32, nb = blockIdx.x * 32;
    int tx = threadIdx.x, ty = threadIdx.y;    // 32 x 8
#pragma unroll
    for (int i = 0; i < 32; i += 8)
        t[ty + i][tx] = src[(size_t)(kb + ty + i) * N + nb + tx];
    __syncthreads();
#pragma unroll
    for (int i = 0; i < 32; i += 8) {
        float v = t[tx][ty + i];
        __nv_bfloat16 h = __float2bfloat16(v);
        __nv_bfloat16 l = __float2bfloat16(v - __bfloat162float(h));
        size_t o = (size_t)(nb + ty + i) * K + kb + tx;
        dh[o] = h; dl[o] = l;
    }
}

// ======================= HMMA split-bf16 GEMM ===============================
#define BKP 40
#define MAT_SMEM (128*BKP*2)
#define STG_SMEM (4*MAT_SMEM)
#define GEMM_SMEM (2*STG_SMEM)

__global__ void __launch_bounds__(256, 1) gemm_hmma_split(
    const __nv_bfloat16* __restrict__ Ah, const __nv_bfloat16* __restrict__ Al,
    const __nv_bfloat16* __restrict__ Bh, const __nv_bfloat16* __restrict__ Bl,
    const float* __restrict__ bias, float* __restrict__ C,
    int M, int N, int K)
{
    extern __shared__ char dsm[];
    const uint32_t sbase = s2u(dsm);

    const int tid  = threadIdx.x;
    const int warp = tid >> 5, lane = tid & 31;
    const int wm = (warp & 3) * 32;
    const int wn = (warp >> 2) * 64;
    const int m0 = blockIdx.y * 128, n0 = blockIdx.x * 128;

    const int ldrow = tid >> 2;
    const int ldchk = (tid & 3) * 8;

    const __nv_bfloat16* gA[2] = { Ah + (size_t)m0 * K, Al + (size_t)m0 * K };
    const __nv_bfloat16* gB[2] = { Bh + (size_t)n0 * K, Bl + (size_t)n0 * K };

    const int nK = K >> 5;

    const int a_r  = lane & 15;
    const int a_c8 = (lane >> 4) << 3;
    const int b_r  = (lane & 7) + ((lane >> 4) << 3);
    const int b_c8 = (lane & 8) ? 8 : 0;

    float acc[2][8][4];
#pragma unroll
    for (int mt = 0; mt < 2; mt++)
#pragma unroll
        for (int nt = 0; nt < 8; nt++)
#pragma unroll
            for (int q = 0; q < 4; q++) acc[mt][nt][q] = 0.f;

    auto load_stage = [&](int stg, int kb) {
        uint32_t sb = sbase + stg * STG_SMEM;
#pragma unroll
        for (int mat = 0; mat < 4; mat++) {
            const __nv_bfloat16* g = (mat < 2) ? gA[mat] : gB[mat - 2];
#pragma unroll
            for (int j = 0; j < 2; j++) {
                int row = ldrow + j * 64;
                cpasync16(sb + mat * MAT_SMEM + (row * BKP + ldchk) * 2,
                          g + (size_t)row * K + kb + ldchk);
            }
        }
        asm volatile("cp.async.commit_group;" ::: "memory");
    };

    load_stage(0, 0);
    load_stage(1, 32);

    for (int i = 0; i < nK; i++) {
        const int buf = i & 1;
        if (i + 1 < nK) asm volatile("cp.async.wait_group 1;" ::: "memory");
        else            asm volatile("cp.async.wait_group 0;" ::: "memory");
        __syncthreads();

        const uint32_t sAh = sbase + buf * STG_SMEM;
        const uint32_t sAl = sAh + MAT_SMEM;
        const uint32_t sBh = sAh + 2 * MAT_SMEM;
        const uint32_t sBl = sAh + 3 * MAT_SMEM;

#pragma unroll
        for (int kk = 0; kk < 32; kk += 16) {
            uint32_t ah[2][4], al[2][4], bh[4][4], bl[4][4];
#pragma unroll
            for (int mt = 0; mt < 2; mt++) {
                uint32_t off = ((wm + mt * 16 + a_r) * BKP + kk + a_c8) * 2;
                ldsm4(ah[mt], sAh + off);
                ldsm4(al[mt], sAl + off);
            }
#pragma unroll
            for (int p = 0; p < 4; p++) {
                uint32_t off = ((wn + p * 16 + b_r) * BKP + kk + b_c8) * 2;
                ldsm4(bh[p], sBh + off);
                ldsm4(bl[p], sBl + off);
            }
#pragma unroll
            for (int mt = 0; mt < 2; mt++)
#pragma unroll
                for (int nt = 0; nt < 8; nt++) {
                    const uint32_t* bhf = &bh[nt >> 1][(nt & 1) * 2];
                    const uint32_t* blf = &bl[nt >> 1][(nt & 1) * 2];
                    mma16816(acc[mt][nt], ah[mt], bhf);
                    mma16816(acc[mt][nt], ah[mt], blf);
                    mma16816(acc[mt][nt], al[mt], bhf);
                }
        }
        __syncthreads();
        if (i + 2 < nK) load_stage(buf, (i + 2) * 32);
    }

    const int er = lane >> 2, ec = (lane & 3) * 2;
#pragma unroll
    for (int mt = 0; mt < 2; mt++) {
#pragma unroll
        for (int nt = 0; nt < 8; nt++) {
            int col = n0 + wn + nt * 8 + ec;
            float b0 = bias[col], b1 = bias[col + 1];
            int r0 = m0 + wm + mt * 16 + er;
            float2 v0 = { acc[mt][nt][0] + b0, acc[mt][nt][1] + b1 };
            float2 v1 = { acc[mt][nt][2] + b0, acc[mt][nt][3] + b1 };
            *(float2*)&C[(size_t)r0 * N + col]       = v0;
            *(float2*)&C[(size_t)(r0 + 8) * N + col] = v1;
        }
    }
}

// ------- repack [B,S,H,D] fp32 -> [B,H,S,*] split bf16 ----------------------
__global__ void repack_csplit(const float* __restrict__ kc, const float* __restrict__ vc,
                              const float* __restrict__ qc,
                              __nv_bfloat16* __restrict__ Kh, __nv_bfloat16* __restrict__ Kl,
                              __nv_bfloat16* __restrict__ Vh, __nv_bfloat16* __restrict__ Vl,
                              __nv_bfloat16* __restrict__ Qh, __nv_bfloat16* __restrict__ Ql)
{
    int idx = blockIdx.x * blockDim.x + threadIdx.x;
    if (idx >= ROWS*NHEADS*HD) return;
    int d  = idx & 127;
    int h  = (idx >> 7) & 15;
    int bs = idx >> 11;
    int b  = bs >> 11;
    int s  = bs & 2047;
    size_t o192 = (((size_t)b*NHEADS + h)*SEQ + s)*DQK + d;
    size_t o128 = (((size_t)b*NHEADS + h)*SEQ + s)*HD  + d;
    float k = kc[idx];
    __nv_bfloat16 kh = __float2bfloat16(k);
    Kh[o192] = kh; Kl[o192] = __float2bfloat16(k - __bfloat162float(kh));
    float v = vc[idx];
    __nv_bfloat16 vh = __float2bfloat16(v);
    Vh[o128] = vh; Vl[o128] = __float2bfloat16(v - __bfloat162float(vh));
    float q = qc[idx];
    __nv_bfloat16 qh = __float2bfloat16(q);
    Qh[o192] = qh; Ql[o192] = __float2bfloat16(q - __bfloat162float(qh));
}

// ------- RoPE into last 64 dims of split K/Q --------------------------------
__global__ void rope_packsplit(const float* __restrict__ kr, const float* __restrict__ qr,
                               __nv_bfloat16* __restrict__ Kh, __nv_bfloat16* __restrict__ Kl,
                               __nv_bfloat16* __restrict__ Qh, __nv_bfloat16* __restrict__ Ql)
{
    int idx = blockIdx.x * blockDim.x + threadIdx.x;
    if (idx >= ROWS*NHEADS*(RD/2)) return;
    int i  = idx & 31;
    int h  = (idx >> 5) & 15;
    int bs = idx >> 9;
    int b  = bs >> 11;
    int s  = bs & 2047;
    float inv_freq = powf(10000.f, -(float)(2*i) / 64.f);
    float ang = (float)s * inv_freq;
    float sn, cs;
    sincosf(ang, &sn, &cs);
    size_t ib = (size_t)bs * (NHEADS*RD) + h*RD + 2*i;
    size_t ob = (((size_t)b*NHEADS + h)*SEQ + s)*DQK + HD + 2*i;
    float x1 = kr[ib], x2 = kr[ib+1];
    float r0 = x1*cs - x2*sn, r1 = x1*sn + x2*cs;
    __nv_bfloat16 h0 = __float2bfloat16(r0), h1 = __float2bfloat16(r1);
    Kh[ob] = h0; Kh[ob+1] = h1;
    Kl[ob]   = __float2bfloat16(r0 - __bfloat162float(h0));
    Kl[ob+1] = __float2bfloat16(r1 - __bfloat162float(h1));
    x1 = qr[ib]; x2 = qr[ib+1];
    r0 = x1*cs - x2*sn; r1 = x1*sn + x2*cs;
    h0 = __float2bfloat16(r0); h1 = __float2bfloat16(r1);
    Qh[ob] = h0; Qh[ob+1] = h1;
    Ql[ob]   = __float2bfloat16(r0 - __bfloat162float(h0));
    Ql[ob+1] = __float2bfloat16(r1 - __bfloat162float(h1));
}

// ================= HMMA split-bf16 causal flash attention ===================
// CTA: 128 queries x full head. 8 warps, warp = 16 query rows.
// smem: Qh/Ql [128x192], K double-buffered [64x192]x2(hi+lo), V single [64x128](hi+lo)
#define AQH 0
#define AQL 49152
#define AKB(buf) (98304 + (buf)*49152)     // Kh at +0, Kl at +24576
#define AVB 196608                          // Vh at +0, Vl at +16384
#define ATTN_SMEM 229376

__global__ void __launch_bounds__(256, 1) attn_hmma(
    const __nv_bfloat16* __restrict__ Qhg, const __nv_bfloat16* __restrict__ Qlg,
    const __nv_bfloat16* __restrict__ Khg, const __nv_bfloat16* __restrict__ Klg,
    const __nv_bfloat16* __restrict__ Vhg, const __nv_bfloat16* __restrict__ Vlg,
    __nv_bfloat16* __restrict__ cxh, __nv_bfloat16* __restrict__ cxl)
{
    extern __shared__ char smc[];
    const uint32_t sb = s2u(smc);
    const int b = blockIdx.z, h = blockIdx.y;
    const int q0 = blockIdx.x * 128;
    const int tid = threadIdx.x, w = tid >> 5, lane = tid & 31;
    const int ntiles = (q0 >> 6) + 2;

    const size_t hb = (size_t)(b*NHEADS + h) * SEQ;
    const __nv_bfloat16* gQh = Qhg + (hb + q0) * DQK;
    const __nv_bfloat16* gQl = Qlg + (hb + q0) * DQK;
    const __nv_bfloat16* gKh = Khg + hb * DQK;
    const __nv_bfloat16* gKl = Klg + hb * DQK;
    const __nv_bfloat16* gVh = Vhg + hb * HD;
    const __nv_bfloat16* gVl = Vlg + hb * HD;

    auto ldQ = [&](uint32_t dst, const __nv_bfloat16* g) {
        for (int i = tid; i < 128*24; i += 256) {
            int r = i / 24, c = i % 24;
            int cs = (c & ~7) | ((c ^ r) & 7);
            cpasync16(dst + (r*24 + cs)*16, g + r*192 + c*8);
        }
    };
    auto ldK = [&](uint32_t dst, const __nv_bfloat16* g) {
        for (int i = tid; i < 64*24; i += 256) {
            int r = i / 24, c = i % 24;
            int cs = (c & ~7) | ((c ^ r) & 7);
            cpasync16(dst + (r*24 + cs)*16, g + r*192 + c*8);
        }
    };
    auto ldV = [&](uint32_t dst, const __nv_bfloat16* g) {
        for (int i = tid; i < 64*16; i += 256) {
            int r = i / 16, c = i % 16;
            int cs = (c & ~7) | ((c ^ r) & 7);
            cpasync16(dst + (r*16 + cs)*16, g + r*128 + c*8);
        }
    };

    // prologue: group0 = {Q, K0, V0}, group1 = {K1}
    ldQ(sb + AQH, gQh);
    ldQ(sb + AQL, gQl);
    ldK(sb + AKB(0),         gKh);
    ldK(sb + AKB(0) + 24576, gKl);
    ldV(sb + AVB,            gVh);
    ldV(sb + AVB + 16384,    gVl);
    asm volatile("cp.async.commit_group;" ::: "memory");
    ldK(sb + AKB(1),         gKh + 64*192);
    ldK(sb + AKB(1) + 24576, gKl + 64*192);
    asm volatile("cp.async.commit_group;" ::: "memory");

    float O[16][4];
#pragma unroll
    for (int t = 0; t < 16; t++)
#pragma unroll
        for (int j = 0; j < 4; j++) O[t][j] = 0.f;
    float m0r = -1e30f, m1r = -1e30f, l0 = 0.f, l1 = 0.f;

    const float scale = 0.07216878364870323f;  // 1/sqrt(192)
    const int lrow = lane & 15, lhi = lane >> 4;
    const int qr0 = q0 + w*16 + (lane >> 2);

    for (int i = 0; i < ntiles; i++) {
        const int k0 = i * 64;
        asm volatile("cp.async.wait_group 1;" ::: "memory");
        __syncthreads();

        const uint32_t kbh = sb + AKB(i & 1);
        const uint32_t kbl = kbh + 24576;

        float s[8][4];
#pragma unroll
        for (int t = 0; t < 8; t++)
#pragma unroll
            for (int j = 0; j < 4; j++) s[t][j] = 0.f;

        // ---- S = Q K^T  (3 split products) ----
#pragma unroll
        for (int kc = 0; kc < 12; kc++) {
            uint32_t ah[4], al[4];
            {
                int r = w*16 + lrow;
                int c = kc*2 + lhi;
                int cs = (c & ~7) | ((c ^ r) & 7);
                ldsm4(ah, sb + AQH + (r*24 + cs)*16);
                ldsm4(al, sb + AQL + (r*24 + cs)*16);
            }
#pragma unroll
            for (int kg = 0; kg < 4; kg++) {
                uint32_t bh[4], bl[4];
                int r = kg*16 + lrow;
                int c = kc*2 + lhi;
                int cs = (c & ~7) | ((c ^ r) & 7);
                ldsm4(bh, kbh + (r*24 + cs)*16);
                ldsm4(bl, kbl + (r*24 + cs)*16);
                mma16816s(s[kg*2],   ah, bh[0], bh[2]);
                mma16816s(s[kg*2],   ah, bl[0], bl[2]);
                mma16816s(s[kg*2],   al, bh[0], bh[2]);
                mma16816s(s[kg*2+1], ah, bh[1], bh[3]);
                mma16816s(s[kg*2+1], ah, bl[1], bl[3]);
                mma16816s(s[kg*2+1], al, bh[1], bh[3]);
            }
        }

        // ---- online softmax ----
        if (k0 + 63 > q0 + w*16) {
#pragma unroll
            for (int t = 0; t < 8; t++) {
                int kb = k0 + t*8 + ((lane & 3) << 1);
                s[t][0] = (kb     <= qr0    ) ? s[t][0]*scale : -1e30f;
                s[t][1] = (kb + 1 <= qr0    ) ? s[t][1]*scale : -1e30f;
                s[t][2] = (kb     <= qr0 + 8) ? s[t][2]*scale : -1e30f;
                s[t][3] = (kb + 1 <= qr0 + 8) ? s[t][3]*scale : -1e30f;
            }
        } else {
#pragma unroll
            for (int t = 0; t < 8; t++)
#pragma unroll
                for (int j = 0; j < 4; j++) s[t][j] *= scale;
        }

        float mx0 = -1e30f, mx1 = -1e30f;
#pragma unroll
        for (int t = 0; t < 8; t++) {
            mx0 = fmaxf(mx0, fmaxf(s[t][0], s[t][1]));
            mx1 = fmaxf(mx1, fmaxf(s[t][2], s[t][3]));
        }
        mx0 = fmaxf(mx0, __shfl_xor_sync(0xffffffffu, mx0, 1));
        mx0 = fmaxf(mx0, __shfl_xor_sync(0xffffffffu, mx0, 2));
        mx1 = fmaxf(mx1, __shfl_xor_sync(0xffffffffu, mx1, 1));
        mx1 = fmaxf(mx1, __shfl_xor_sync(0xffffffffu, mx1, 2));

        float mn0 = fmaxf(m0r, mx0), mn1 = fmaxf(m1r, mx1);
        float al0 = __expf(m0r - mn0), al1 = __expf(m1r - mn1);
        m0r = mn0; m1r = mn1;

        float sum0 = 0.f, sum1 = 0.f;
#pragma unroll
        for (int t = 0; t < 8; t++) {
            s[t][0] = __expf(s[t][0] - mn0); sum0 += s[t][0];
            s[t][1] = __expf(s[t][1] - mn0); sum0 += s[t][1];
            s[t][2] = __expf(s[t][2] - mn1); sum1 += s[t][2];
            s[t][3] = __expf(s[t][3] - mn1); sum1 += s[t][3];
        }
        l0 = l0*al0 + sum0;
        l1 = l1*al1 + sum1;
#pragma unroll
        for (int t = 0; t < 16; t++) {
            O[t][0] *= al0; O[t][1] *= al0;
            O[t][2] *= al1; O[t][3] *= al1;
        }

        // ---- O += P V  (3 split products) ----
#pragma unroll
        for (int kc2 = 0; kc2 < 4; kc2++) {
            uint32_t pha[4], pla[4];
            {
                const float* s0 = s[kc2*2];
                const float* s1 = s[kc2*2 + 1];
                float h00 = __bfloat162float(__float2bfloat16(s0[0]));
                float h01 = __bfloat162float(__float2bfloat16(s0[1]));
                float h02 = __bfloat162float(__float2bfloat16(s0[2]));
                float h03 = __bfloat162float(__float2bfloat16(s0[3]));
                float h10 = __bfloat162float(__float2bfloat16(s1[0]));
                float h11 = __bfloat162float(__float2bfloat16(s1[1]));
                float h12 = __bfloat162float(__float2bfloat16(s1[2]));
                float h13 = __bfloat162float(__float2bfloat16(s1[3]));
                pha[0] = pack2bf(s0[0], s0[1]);
                pha[1] = pack2bf(s0[2], s0[3]);
                pha[2] = pack2bf(s1[0], s1[1]);
                pha[3] = pack2bf(s1[2], s1[3]);
                pla[0] = pack2bf(s0[0]-h00, s0[1]-h01);
                pla[1] = pack2bf(s0[2]-h02, s0[3]-h03);
                pla[2] = pack2bf(s1[0]-h10, s1[1]-h11);
                pla[3] = pack2bf(s1[2]-h12, s1[3]-h13);
            }
#pragma unroll
            for (int dg = 0; dg < 8; dg++) {
                uint32_t vh[4], vl[4];
                int r = kc2*16 + lrow;
                int c = dg*2 + lhi;
                int cs = (c & ~7) | ((c ^ r) & 7);
                ldsm4t(vh, sb + AVB +         (r*16 + cs)*16);
                ldsm4t(vl, sb + AVB + 16384 + (r*16 + cs)*16);
                mma16816s(O[dg*2],   pha, vh[0], vh[1]);
                mma16816s(O[dg*2],   pha, vl[0], vl[1]);
                mma16816s(O[dg*2],   pla, vh[0], vh[1]);
                mma16816s(O[dg*2+1], pha, vh[2], vh[3]);
                mma16816s(O[dg*2+1], pha, vl[2], vl[3]);
                mma16816s(O[dg*2+1], pla, vh[2], vh[3]);
            }
        }
        __syncthreads();

        // issue next loads (V single buffer, K into freed buffer)
        if (i + 1 < ntiles) {
            ldV(sb + AVB,         gVh + (size_t)(k0 + 64)*HD);
            ldV(sb + AVB + 16384, gVl + (size_t)(k0 + 64)*HD);
        }
        asm volatile("cp.async.commit_group;" ::: "memory");
        if (i + 2 < ntiles) {
            ldK(sb + AKB(i & 1),         gKh + (size_t)(k0 + 128)*DQK);
            ldK(sb + AKB(i & 1) + 24576, gKl + (size_t)(k0 + 128)*DQK);
        }
        asm volatile("cp.async.commit_group;" ::: "memory");
    }

    // finalize
    l0 += __shfl_xor_sync(0xffffffffu, l0, 1);
    l0 += __shfl_xor_sync(0xffffffffu, l0, 2);
    l1 += __shfl_xor_sync(0xffffffffu, l1, 1);
    l1 += __shfl_xor_sync(0xffffffffu, l1, 2);
    float inv0 = 1.f / l0, inv1 = 1.f / l1;

#pragma unroll
    for (int t = 0; t < 16; t++) {
        int d = h*HD + t*8 + ((lane & 3) << 1);
        size_t ro0 = (size_t)(b*SEQ + qr0    ) * (NHEADS*HD) + d;
        size_t ro1 = (size_t)(b*SEQ + qr0 + 8) * (NHEADS*HD) + d;
        float o0 = O[t][0]*inv0, o1 = O[t][1]*inv0;
        float o2 = O[t][2]*inv1, o3 = O[t][3]*inv1;
        __nv_bfloat16 h0 = __float2bfloat16(o0), h1 = __float2bfloat16(o1);
        __nv_bfloat16 h2 = __float2bfloat16(o2), h3 = __float2bfloat16(o3);
        *(__nv_bfloat162*)&cxh[ro0] = __halves2bfloat162(h0, h1);
        *(__nv_bfloat162*)&cxh[ro1] = __halves2bfloat162(h2, h3);
        *(__nv_bfloat162*)&cxl[ro0] = __halves2bfloat162(
            __float2bfloat16(o0 - __bfloat162float(h0)),
            __float2bfloat16(o1 - __bfloat162float(h1)));
        *(__nv_bfloat162*)&cxl[ro1] = __halves2bfloat162(
            __float2bfloat16(o2 - __bfloat162float(h2)),
            __float2bfloat16(o3 - __bfloat162float(h3)));
    }
}

// ---------------- launch -----------------------------------------------------
static inline void gemm_ts(const __nv_bfloat16* Ah, const __nv_bfloat16* Al,
                           const __nv_bfloat16* Bh, const __nv_bfloat16* Bl,
                           const float* bias, float* C, int M, int N, int K)
{
    gemm_hmma_split<<<dim3(N/128, M/128), 256, GEMM_SMEM>>>(Ah, Al, Bh, Bl, bias, C, M, N, K);
}

extern "C" void kernel_launch(void* const* d_in, const int* in_sizes, int n_in,
                              void* d_out, int out_size)
{
    const float* x    = (const float*)d_in[0];
    const float* kvdw = (const float*)d_in[2];
    const float* kvdb = (const float*)d_in[3];
    const float* kuw  = (const float*)d_in[4];
    const float* kub  = (const float*)d_in[5];
    const float* vuw  = (const float*)d_in[6];
    const float* vub  = (const float*)d_in[7];
    const float* krw  = (const float*)d_in[8];
    const float* krb  = (const float*)d_in[9];
    const float* qdw  = (const float*)d_in[10];
    const float* qdb  = (const float*)d_in[11];
    const float* quw  = (const float*)d_in[12];
    const float* qub  = (const float*)d_in[13];
    const float* qrw  = (const float*)d_in[14];
    const float* qrb  = (const float*)d_in[15];
    const float* ow   = (const float*)d_in[16];
    const float* obv  = (const float*)d_in[17];
    float* out = (float*)d_out;

    float *kvc, *qlat, *kc, *vc, *kr, *qcu, *qru;
    cudaGetSymbolAddress((void**)&kvc,  g_kvc);
    cudaGetSymbolAddress((void**)&qlat, g_qlat);
    cudaGetSymbolAddress((void**)&kc,   g_kc);
    cudaGetSymbolAddress((void**)&vc,   g_vc);
    cudaGetSymbolAddress((void**)&kr,   g_kr);
    cudaGetSymbolAddress((void**)&qcu,  g_qcu);
    cudaGetSymbolAddress((void**)&qru,  g_qru);

    __nv_bfloat16 *Qh,*Ql,*Kh,*Kl,*Vh,*Vl;
    cudaGetSymbolAddress((void**)&Qh, g_Qh); cudaGetSymbolAddress((void**)&Ql, g_Ql);
    cudaGetSymbolAddress((void**)&Kh, g_Kh); cudaGetSymbolAddress((void**)&Kl, g_Kl);
    cudaGetSymbolAddress((void**)&Vh, g_Vh); cudaGetSymbolAddress((void**)&Vl, g_Vl);

    __nv_bfloat16 *xh,*xl,*kvch,*kvcl,*qlh,*qll,*cxh,*cxl;
    __nv_bfloat16 *kvdwh,*kvdwl,*kuwh,*kuwl,*vuwh,*vuwl,*krwh,*krwl;
    __nv_bfloat16 *qdwh,*qdwl,*quwh,*quwl,*qrwh,*qrwl,*owh,*owl;
    cudaGetSymbolAddress((void**)&xh, g_xh);     cudaGetSymbolAddress((void**)&xl, g_xl);
    cudaGetSymbolAddress((void**)&kvch, g_kvch); cudaGetSymbolAddress((void**)&kvcl, g_kvcl);
    cudaGetSymbolAddress((void**)&qlh, g_qlh);   cudaGetSymbolAddress((void**)&qll, g_qll);
    cudaGetSymbolAddress((void**)&cxh, g_cxh);   cudaGetSymbolAddress((void**)&cxl, g_cxl);
    cudaGetSymbolAddress((void**)&kvdwh, g_kvdwh); cudaGetSymbolAddress((void**)&kvdwl, g_kvdwl);
    cudaGetSymbolAddress((void**)&kuwh, g_kuwh);   cudaGetSymbolAddress((void**)&kuwl, g_kuwl);
    cudaGetSymbolAddress((void**)&vuwh, g_vuwh);   cudaGetSymbolAddress((void**)&vuwl, g_vuwl);
    cudaGetSymbolAddress((void**)&krwh, g_krwh);   cudaGetSymbolAddress((void**)&krwl, g_krwl);
    cudaGetSymbolAddress((void**)&qdwh, g_qdwh);   cudaGetSymbolAddress((void**)&qdwl, g_qdwl);
    cudaGetSymbolAddress((void**)&quwh, g_quwh);   cudaGetSymbolAddress((void**)&quwl, g_quwl);
    cudaGetSymbolAddress((void**)&qrwh, g_qrwh);   cudaGetSymbolAddress((void**)&qrwl, g_qrwl);
    cudaGetSymbolAddress((void**)&owh, g_owh);     cudaGetSymbolAddress((void**)&owl, g_owl);

    cudaFuncSetAttribute(gemm_hmma_split, cudaFuncAttributeMaxDynamicSharedMemorySize, GEMM_SMEM);
    cudaFuncSetAttribute(attn_hmma, cudaFuncAttributeMaxDynamicSharedMemorySize, ATTN_SMEM);

    dim3 tb(32, 8);

    // weight transpose+split: src [K][N] -> [N][K] hi/lo
    transpose_split<<<dim3(KVC/32,       HIDDEN/32), tb>>>(kvdw, kvdwh, kvdwl, HIDDEN, KVC);
    transpose_split<<<dim3(NHEADS*HD/32, KVC/32),    tb>>>(kuw,  kuwh,  kuwl,  KVC, NHEADS*HD);
    transpose_split<<<dim3(NHEADS*HD/32, KVC/32),    tb>>>(vuw,  vuwh,  vuwl,  KVC, NHEADS*HD);
    transpose_split<<<dim3(NHEADS*RD/32, KVC/32),    tb>>>(krw,  krwh,  krwl,  KVC, NHEADS*RD);
    transpose_split<<<dim3(QC/32,        HIDDEN/32), tb>>>(qdw,  qdwh,  qdwl,  HIDDEN, QC);
    transpose_split<<<dim3(NHEADS*HD/32, QC/32),     tb>>>(quw,  quwh,  quwl,  QC, NHEADS*HD);
    transpose_split<<<dim3(NHEADS*RD/32, QC/32),     tb>>>(qrw,  qrwh,  qrwl,  QC, NHEADS*RD);
    transpose_split<<<dim3(HIDDEN/32,    NHEADS*HD/32), tb>>>(ow, owh, owl, NHEADS*HD, HIDDEN);

    // x split
    split_fp32<<<ROWS*HIDDEN/4/256, 256>>>(x, xh, xl, ROWS*HIDDEN);

    // kv path
    gemm_ts(xh, xl, kvdwh, kvdwl, kvdb, kvc, ROWS, KVC, HIDDEN);
    split_fp32<<<ROWS*KVC/4/256, 256>>>(kvc, kvch, kvcl, ROWS*KVC);
    gemm_ts(kvch, kvcl, kuwh, kuwl, kub, kc, ROWS, NHEADS*HD, KVC);
    gemm_ts(kvch, kvcl, vuwh, vuwl, vub, vc, ROWS, NHEADS*HD, KVC);
    gemm_ts(kvch, kvcl, krwh, krwl, krb, kr, ROWS, NHEADS*RD, KVC);

    // q path
    gemm_ts(xh, xl, qdwh, qdwl, qdb, qlat, ROWS, QC, HIDDEN);
    split_fp32<<<ROWS*QC/4/256, 256>>>(qlat, qlh, qll, ROWS*QC);
    gemm_ts(qlh, qll, quwh, quwl, qub, qcu, ROWS, NHEADS*HD, QC);
    gemm_ts(qlh, qll, qrwh, qrwl, qrb, qru, ROWS, NHEADS*RD, QC);

    // layout change + rope (direct to split bf16)
    repack_csplit<<<ROWS*NHEADS*HD/256, 256>>>(kc, vc, qcu, Kh, Kl, Vh, Vl, Qh, Ql);
    rope_packsplit<<<ROWS*NHEADS*(RD/2)/256, 256>>>(kr, qru, Kh, Kl, Qh, Ql);

    // attention (HMMA split-bf16) — writes split ctx directly
    attn_hmma<<<dim3(SEQ/128, NHEADS, BATCH), 256, ATTN_SMEM>>>(Qh, Ql, Kh, Kl, Vh, Vl, cxh, cxl);

    // output projection
    gemm_ts(cxh, cxl, owh, owl, obv, out, ROWS, HIDDEN, NHEADS*HD);
}

// round 6
// speedup vs baseline: 2.5424x; 1.0333x over previous
#include <cuda_runtime.h>
#include <cuda_bf16.h>
#include <cstdint>
#include <math.h>

#define HIDDEN 2048
#define NHEADS 16
#define HD 128
#define RD 64
#define DQK 192
#define KVC 512
#define QC 1536
#define BATCH 2
#define SEQ 2048
#define ROWS (BATCH*SEQ)   // 4096

// ---------------- scratch (static device memory; no allocation allowed) -----
__device__ float g_kr [ROWS*NHEADS*RD];
__device__ float g_qru[ROWS*NHEADS*RD];

// split bf16 attention operands [B,H,S,*]
__device__ __nv_bfloat16 g_Qh[(size_t)BATCH*NHEADS*SEQ*DQK], g_Ql[(size_t)BATCH*NHEADS*SEQ*DQK];
__device__ __nv_bfloat16 g_Kh[(size_t)BATCH*NHEADS*SEQ*DQK], g_Kl[(size_t)BATCH*NHEADS*SEQ*DQK];
__device__ __nv_bfloat16 g_Vh[(size_t)BATCH*NHEADS*SEQ*HD],  g_Vl[(size_t)BATCH*NHEADS*SEQ*HD];

// bf16 split activations
__device__ __nv_bfloat16 g_xh [ROWS*HIDDEN],  g_xl [ROWS*HIDDEN];
__device__ __nv_bfloat16 g_kvch[ROWS*KVC],    g_kvcl[ROWS*KVC];
__device__ __nv_bfloat16 g_qlh [ROWS*QC],     g_qll [ROWS*QC];
__device__ __nv_bfloat16 g_cxh [ROWS*NHEADS*HD], g_cxl[ROWS*NHEADS*HD];

// weights transposed to [N][K] hi/lo
__device__ __nv_bfloat16 g_kvdwh[KVC*HIDDEN],        g_kvdwl[KVC*HIDDEN];
__device__ __nv_bfloat16 g_kuwh [NHEADS*HD*KVC],     g_kuwl [NHEADS*HD*KVC];
__device__ __nv_bfloat16 g_vuwh [NHEADS*HD*KVC],     g_vuwl [NHEADS*HD*KVC];
__device__ __nv_bfloat16 g_krwh [NHEADS*RD*KVC],     g_krwl [NHEADS*RD*KVC];
__device__ __nv_bfloat16 g_qdwh [QC*HIDDEN],         g_qdwl [QC*HIDDEN];
__device__ __nv_bfloat16 g_quwh [NHEADS*HD*QC],      g_quwl [NHEADS*HD*QC];
__device__ __nv_bfloat16 g_qrwh [NHEADS*RD*QC],      g_qrwl [NHEADS*RD*QC];
__device__ __nv_bfloat16 g_owh  [HIDDEN*NHEADS*HD],  g_owl  [HIDDEN*NHEADS*HD];

// ======================= mma / ldmatrix helpers =============================
__device__ __forceinline__ uint32_t s2u(const void* p) {
    return (uint32_t)__cvta_generic_to_shared(p);
}
__device__ __forceinline__ void ldsm4(uint32_t* r, uint32_t addr) {
    asm volatile("ldmatrix.sync.aligned.m8n8.x4.shared.b16 {%0,%1,%2,%3}, [%4];"
                 : "=r"(r[0]), "=r"(r[1]), "=r"(r[2]), "=r"(r[3]) : "r"(addr));
}
__device__ __forceinline__ void ldsm4t(uint32_t* r, uint32_t addr) {
    asm volatile("ldmatrix.sync.aligned.m8n8.x4.trans.shared.b16 {%0,%1,%2,%3}, [%4];"
                 : "=r"(r[0]), "=r"(r[1]), "=r"(r[2]), "=r"(r[3]) : "r"(addr));
}
__device__ __forceinline__ void mma16816(float* c, const uint32_t* a, const uint32_t* b) {
    asm volatile(
        "mma.sync.aligned.m16n8k16.row.col.f32.bf16.bf16.f32 "
        "{%0,%1,%2,%3}, {%4,%5,%6,%7}, {%8,%9}, {%0,%1,%2,%3};"
        : "+f"(c[0]), "+f"(c[1]), "+f"(c[2]), "+f"(c[3])
        : "r"(a[0]), "r"(a[1]), "r"(a[2]), "r"(a[3]), "r"(b[0]), "r"(b[1]));
}
__device__ __forceinline__ void mma16816s(float* c, const uint32_t* a, uint32_t b0, uint32_t b1) {
    asm volatile(
        "mma.sync.aligned.m16n8k16.row.col.f32.bf16.bf16.f32 "
        "{%0,%1,%2,%3}, {%4,%5,%6,%7}, {%8,%9}, {%0,%1,%2,%3};"
        : "+f"(c[0]), "+f"(c[1]), "+f"(c[2]), "+f"(c[3])
        : "r"(a[0]), "r"(a[1]), "r"(a[2]), "r"(a[3]), "r"(b0), "r"(b1));
}
__device__ __forceinline__ void cpasync16(uint32_t dst, const void* src) {
    asm volatile("cp.async.cg.shared.global [%0], [%1], 16;"
                 :: "r"(dst), "l"(src) : "memory");
}
__device__ __forceinline__ uint32_t pack2bf(float x, float y) {
    __nv_bfloat162 t = __floats2bfloat162_rn(x, y);
    return *(uint32_t*)&t;
}
__device__ __forceinline__ void wsplit2(__nv_bfloat16* __restrict__ H,
                                        __nv_bfloat16* __restrict__ L,
                                        size_t o, float a, float b) {
    __nv_bfloat16 ha = __float2bfloat16(a), hb = __float2bfloat16(b);
    *(__nv_bfloat162*)&H[o] = __halves2bfloat162(ha, hb);
    *(__nv_bfloat162*)&L[o] = __halves2bfloat162(
        __float2bfloat16(a - __bfloat162float(ha)),
        __float2bfloat16(b - __bfloat162float(hb)));
}

// ======================= fp32 -> bf16 hi/lo split ===========================
__global__ void split_fp32(const float* __restrict__ s,
                           __nv_bfloat16* __restrict__ h,
                           __nv_bfloat16* __restrict__ l, int n)
{
    int i = (blockIdx.x * blockDim.x + threadIdx.x) * 4;
    if (i >= n) return;
    float4 v = *(const float4*)(s + i);
    __nv_bfloat16 h0 = __float2bfloat16(v.x), h1 = __float2bfloat16(v.y);
    __nv_bfloat16 h2 = __float2bfloat16(v.z), h3 = __float2bfloat16(v.w);
    __nv_bfloat16 l0 = __float2bfloat16(v.x - __bfloat162float(h0));
    __nv_bfloat16 l1 = __float2bfloat16(v.y - __bfloat162float(h1));
    __nv_bfloat16 l2 = __float2bfloat16(v.z - __bfloat162float(h2));
    __nv_bfloat16 l3 = __float2bfloat16(v.w - __bfloat162float(h3));
    *(__nv_bfloat162*)(h + i)     = __halves2bfloat162(h0, h1);
    *(__nv_bfloat162*)(h + i + 2) = __halves2bfloat162(h2, h3);
    *(__nv_bfloat162*)(l + i)     = __halves2bfloat162(l0, l1);
    *(__nv_bfloat162*)(l + i + 2) = __halves2bfloat162(l2, l3);
}

// transpose + split: src[K][N] fp32 -> dst hi/lo [N][K] bf16
__global__ void transpose_split(const float* __restrict__ src,
                                __nv_bfloat16* __restrict__ dh,
                                __nv_bfloat16* __restrict__ dl,
                                int K, int N)
{
    __shared__ float t[32][33];
    int kb = blockIdx.y * 32, nb = blockIdx.x * 32;
    int tx = threadIdx.x, ty = threadIdx.y;    // 32 x 8
#pragma unroll
    for (int i = 0; i < 32; i += 8)
        t[ty + i][tx] = src[(size_t)(kb + ty + i) * N + nb + tx];
    __syncthreads();
#pragma unroll
    for (int i = 0; i < 32; i += 8) {
        float v = t[tx][ty + i];
        __nv_bfloat16 h = __float2bfloat16(v);
        __nv_bfloat16 l = __float2bfloat16(v - __bfloat162float(h));
        size_t o = (size_t)(nb + ty + i) * K + kb + tx;
        dh[o] = h; dl[o] = l;
    }
}

// ======================= HMMA split-bf16 GEMM ===============================
// 3-stage cp.async pipeline, one __syncthreads per K-iter.
// Epilogue modes: 0 = fp32 C; 1 = split bf16 [M,N]; 2 = split bf16 into
// [B,H,S,192] (d = col&127); 3 = split bf16 into [B,H,S,128].
#define BKP 40
#define MAT_SMEM (128*BKP*2)
#define STG_SMEM (4*MAT_SMEM)
#define GEMM_SMEM (3*STG_SMEM)    // 122880

__global__ void __launch_bounds__(256, 1) gemm_hmma_split(
    const __nv_bfloat16* __restrict__ Ah, const __nv_bfloat16* __restrict__ Al,
    const __nv_bfloat16* __restrict__ Bh, const __nv_bfloat16* __restrict__ Bl,
    const float* __restrict__ bias, float* __restrict__ C,
    __nv_bfloat16* __restrict__ Ch, __nv_bfloat16* __restrict__ Cl,
    int M, int N, int K, int mode)
{
    extern __shared__ char dsm[];
    const uint32_t sbase = s2u(dsm);

    const int tid  = threadIdx.x;
    const int warp = tid >> 5, lane = tid & 31;
    const int wm = (warp & 3) * 32;
    const int wn = (warp >> 2) * 64;
    const int m0 = blockIdx.y * 128, n0 = blockIdx.x * 128;

    const int ldrow = tid >> 2;
    const int ldchk = (tid & 3) * 8;

    const __nv_bfloat16* gA[2] = { Ah + (size_t)m0 * K, Al + (size_t)m0 * K };
    const __nv_bfloat16* gB[2] = { Bh + (size_t)n0 * K, Bl + (size_t)n0 * K };

    const int nK = K >> 5;

    const int a_r  = lane & 15;
    const int a_c8 = (lane >> 4) << 3;
    const int b_r  = (lane & 7) + ((lane >> 4) << 3);
    const int b_c8 = (lane & 8) ? 8 : 0;

    float acc[2][8][4];
#pragma unroll
    for (int mt = 0; mt < 2; mt++)
#pragma unroll
        for (int nt = 0; nt < 8; nt++)
#pragma unroll
            for (int q = 0; q < 4; q++) acc[mt][nt][q] = 0.f;

    auto load_stage = [&](int stg, int kb) {
        uint32_t sb = sbase + stg * STG_SMEM;
#pragma unroll
        for (int mat = 0; mat < 4; mat++) {
            const __nv_bfloat16* g = (mat < 2) ? gA[mat] : gB[mat - 2];
#pragma unroll
            for (int j = 0; j < 2; j++) {
                int row = ldrow + j * 64;
                cpasync16(sb + mat * MAT_SMEM + (row * BKP + ldchk) * 2,
                          g + (size_t)row * K + kb + ldchk);
            }
        }
        asm volatile("cp.async.commit_group;" ::: "memory");
    };

    load_stage(0, 0);
    load_stage(1, 32);

    int cur = 0, nxt = 2;   // nxt = (i+2)%3
    for (int i = 0; i < nK; i++) {
        if (i + 1 < nK) asm volatile("cp.async.wait_group 1;" ::: "memory");
        else            asm volatile("cp.async.wait_group 0;" ::: "memory");
        __syncthreads();
        if (i + 2 < nK) load_stage(nxt, (i + 2) * 32);

        const uint32_t sAh = sbase + cur * STG_SMEM;
        const uint32_t sAl = sAh + MAT_SMEM;
        const uint32_t sBh = sAh + 2 * MAT_SMEM;
        const uint32_t sBl = sAh + 3 * MAT_SMEM;

#pragma unroll
        for (int kk = 0; kk < 32; kk += 16) {
            uint32_t ah[2][4], al[2][4], bh[4][4], bl[4][4];
#pragma unroll
            for (int mt = 0; mt < 2; mt++) {
                uint32_t off = ((wm + mt * 16 + a_r) * BKP + kk + a_c8) * 2;
                ldsm4(ah[mt], sAh + off);
                ldsm4(al[mt], sAl + off);
            }
#pragma unroll
            for (int p = 0; p < 4; p++) {
                uint32_t off = ((wn + p * 16 + b_r) * BKP + kk + b_c8) * 2;
                ldsm4(bh[p], sBh + off);
                ldsm4(bl[p], sBl + off);
            }
#pragma unroll
            for (int mt = 0; mt < 2; mt++)
#pragma unroll
                for (int nt = 0; nt < 8; nt++) {
                    const uint32_t* bhf = &bh[nt >> 1][(nt & 1) * 2];
                    const uint32_t* blf = &bl[nt >> 1][(nt & 1) * 2];
                    mma16816(acc[mt][nt], ah[mt], bhf);
                    mma16816(acc[mt][nt], ah[mt], blf);
                    mma16816(acc[mt][nt], al[mt], bhf);
                }
        }
        cur = (cur == 2) ? 0 : cur + 1;
        nxt = (nxt == 2) ? 0 : nxt + 1;
    }

    // ---- epilogue ----
    const int er = lane >> 2, ec = (lane & 3) * 2;
#pragma unroll
    for (int mt = 0; mt < 2; mt++) {
#pragma unroll
        for (int nt = 0; nt < 8; nt++) {
            int col = n0 + wn + nt * 8 + ec;
            float b0 = bias[col], b1 = bias[col + 1];
            int r0 = m0 + wm + mt * 16 + er;
            int r1 = r0 + 8;
            float p0 = acc[mt][nt][0] + b0, p1 = acc[mt][nt][1] + b1;
            float p2 = acc[mt][nt][2] + b0, p3 = acc[mt][nt][3] + b1;
            if (mode == 0) {
                *(float2*)&C[(size_t)r0 * N + col] = make_float2(p0, p1);
                *(float2*)&C[(size_t)r1 * N + col] = make_float2(p2, p3);
            } else if (mode == 1) {
                wsplit2(Ch, Cl, (size_t)r0 * N + col, p0, p1);
                wsplit2(Ch, Cl, (size_t)r1 * N + col, p2, p3);
            } else {
                int hh = col >> 7, d = col & 127;
                int stride = (mode == 2) ? DQK : HD;
                size_t o0 = (((size_t)(r0 >> 11) * NHEADS + hh) * SEQ + (r0 & 2047)) * stride + d;
                size_t o1 = (((size_t)(r1 >> 11) * NHEADS + hh) * SEQ + (r1 & 2047)) * stride + d;
                wsplit2(Ch, Cl, o0, p0, p1);
                wsplit2(Ch, Cl, o1, p2, p3);
            }
        }
    }
}

// ------- RoPE into last 64 dims of split K/Q --------------------------------
__global__ void rope_packsplit(const float* __restrict__ kr, const float* __restrict__ qr,
                               __nv_bfloat16* __restrict__ Kh, __nv_bfloat16* __restrict__ Kl,
                               __nv_bfloat16* __restrict__ Qh, __nv_bfloat16* __restrict__ Ql)
{
    int idx = blockIdx.x * blockDim.x + threadIdx.x;
    if (idx >= ROWS*NHEADS*(RD/2)) return;
    int i  = idx & 31;
    int h  = (idx >> 5) & 15;
    int bs = idx >> 9;
    int b  = bs >> 11;
    int s  = bs & 2047;
    float inv_freq = powf(10000.f, -(float)(2*i) / 64.f);
    float ang = (float)s * inv_freq;
    float sn, cs;
    sincosf(ang, &sn, &cs);
    size_t ib = (size_t)bs * (NHEADS*RD) + h*RD + 2*i;
    size_t ob = (((size_t)b*NHEADS + h)*SEQ + s)*DQK + HD + 2*i;
    float x1 = kr[ib], x2 = kr[ib+1];
    float r0 = x1*cs - x2*sn, r1 = x1*sn + x2*cs;
    __nv_bfloat16 h0 = __float2bfloat16(r0), h1 = __float2bfloat16(r1);
    Kh[ob] = h0; Kh[ob+1] = h1;
    Kl[ob]   = __float2bfloat16(r0 - __bfloat162float(h0));
    Kl[ob+1] = __float2bfloat16(r1 - __bfloat162float(h1));
    x1 = qr[ib]; x2 = qr[ib+1];
    r0 = x1*cs - x2*sn; r1 = x1*sn + x2*cs;
    h0 = __float2bfloat16(r0); h1 = __float2bfloat16(r1);
    Qh[ob] = h0; Qh[ob+1] = h1;
    Ql[ob]   = __float2bfloat16(r0 - __bfloat162float(h0));
    Ql[ob+1] = __float2bfloat16(r1 - __bfloat162float(h1));
}

// ================= HMMA split-bf16 causal flash attention ===================
#define AQH 0
#define AQL 49152
#define AKB(buf) (98304 + (buf)*49152)     // Kh at +0, Kl at +24576
#define AVB 196608                          // Vh at +0, Vl at +16384
#define ATTN_SMEM 229376

__global__ void __launch_bounds__(256, 1) attn_hmma(
    const __nv_bfloat16* __restrict__ Qhg, const __nv_bfloat16* __restrict__ Qlg,
    const __nv_bfloat16* __restrict__ Khg, const __nv_bfloat16* __restrict__ Klg,
    const __nv_bfloat16* __restrict__ Vhg, const __nv_bfloat16* __restrict__ Vlg,
    __nv_bfloat16* __restrict__ cxh, __nv_bfloat16* __restrict__ cxl)
{
    extern __shared__ char smc[];
    const uint32_t sb = s2u(smc);
    const int b = blockIdx.z, h = blockIdx.y;
    const int q0 = blockIdx.x * 128;
    const int tid = threadIdx.x, w = tid >> 5, lane = tid & 31;
    const int ntiles = (q0 >> 6) + 2;

    const size_t hb = (size_t)(b*NHEADS + h) * SEQ;
    const __nv_bfloat16* gQh = Qhg + (hb + q0) * DQK;
    const __nv_bfloat16* gQl = Qlg + (hb + q0) * DQK;
    const __nv_bfloat16* gKh = Khg + hb * DQK;
    const __nv_bfloat16* gKl = Klg + hb * DQK;
    const __nv_bfloat16* gVh = Vhg + hb * HD;
    const __nv_bfloat16* gVl = Vlg + hb * HD;

    auto ldQ = [&](uint32_t dst, const __nv_bfloat16* g) {
        for (int i = tid; i < 128*24; i += 256) {
            int r = i / 24, c = i % 24;
            int cs = (c & ~7) | ((c ^ r) & 7);
            cpasync16(dst + (r*24 + cs)*16, g + r*192 + c*8);
        }
    };
    auto ldK = [&](uint32_t dst, const __nv_bfloat16* g) {
        for (int i = tid; i < 64*24; i += 256) {
            int r = i / 24, c = i % 24;
            int cs = (c & ~7) | ((c ^ r) & 7);
            cpasync16(dst + (r*24 + cs)*16, g + r*192 + c*8);
        }
    };
    auto ldV = [&](uint32_t dst, const __nv_bfloat16* g) {
        for (int i = tid; i < 64*16; i += 256) {
            int r = i / 16, c = i % 16;
            int cs = (c & ~7) | ((c ^ r) & 7);
            cpasync16(dst + (r*16 + cs)*16, g + r*128 + c*8);
        }
    };

    // prologue: group0 = {Q, K0, V0}, group1 = {K1}
    ldQ(sb + AQH, gQh);
    ldQ(sb + AQL, gQl);
    ldK(sb + AKB(0),         gKh);
    ldK(sb + AKB(0) + 24576, gKl);
    ldV(sb + AVB,            gVh);
    ldV(sb + AVB + 16384,    gVl);
    asm volatile("cp.async.commit_group;" ::: "memory");
    ldK(sb + AKB(1),         gKh + 64*192);
    ldK(sb + AKB(1) + 24576, gKl + 64*192);
    asm volatile("cp.async.commit_group;" ::: "memory");

    float O[16][4];
#pragma unroll
    for (int t = 0; t < 16; t++)
#pragma unroll
        for (int j = 0; j < 4; j++) O[t][j] = 0.f;
    float m0r = -1e30f, m1r = -1e30f, l0 = 0.f, l1 = 0.f;

    const float scale = 0.07216878364870323f;  // 1/sqrt(192)
    const int lrow = lane & 15, lhi = lane >> 4;
    const int qr0 = q0 + w*16 + (lane >> 2);

    for (int i = 0; i < ntiles; i++) {
        const int k0 = i * 64;
        asm volatile("cp.async.wait_group 1;" ::: "memory");
        __syncthreads();

        const uint32_t kbh = sb + AKB(i & 1);
        const uint32_t kbl = kbh + 24576;

        float s[8][4];
#pragma unroll
        for (int t = 0; t < 8; t++)
#pragma unroll
            for (int j = 0; j < 4; j++) s[t][j] = 0.f;

        // ---- S = Q K^T ----
#pragma unroll
        for (int kc = 0; kc < 12; kc++) {
            uint32_t ah[4], al[4];
            {
                int r = w*16 + lrow;
                int c = kc*2 + lhi;
                int cs = (c & ~7) | ((c ^ r) & 7);
                ldsm4(ah, sb + AQH + (r*24 + cs)*16);
                ldsm4(al, sb + AQL + (r*24 + cs)*16);
            }
#pragma unroll
            for (int kg = 0; kg < 4; kg++) {
                uint32_t bh[4], bl[4];
                int r = kg*16 + lrow;
                int c = kc*2 + lhi;
                int cs = (c & ~7) | ((c ^ r) & 7);
                ldsm4(bh, kbh + (r*24 + cs)*16);
                ldsm4(bl, kbl + (r*24 + cs)*16);
                mma16816s(s[kg*2],   ah, bh[0], bh[2]);
                mma16816s(s[kg*2],   ah, bl[0], bl[2]);
                mma16816s(s[kg*2],   al, bh[0], bh[2]);
                mma16816s(s[kg*2+1], ah, bh[1], bh[3]);
                mma16816s(s[kg*2+1], ah, bl[1], bl[3]);
                mma16816s(s[kg*2+1], al, bh[1], bh[3]);
            }
        }

        // ---- online softmax ----
        if (k0 + 63 > q0 + w*16) {
#pragma unroll
            for (int t = 0; t < 8; t++) {
                int kb = k0 + t*8 + ((lane & 3) << 1);
                s[t][0] = (kb     <= qr0    ) ? s[t][0]*scale : -1e30f;
                s[t][1] = (kb + 1 <= qr0    ) ? s[t][1]*scale : -1e30f;
                s[t][2] = (kb     <= qr0 + 8) ? s[t][2]*scale : -1e30f;
                s[t][3] = (kb + 1 <= qr0 + 8) ? s[t][3]*scale : -1e30f;
            }
        } else {
#pragma unroll
            for (int t = 0; t < 8; t++)
#pragma unroll
                for (int j = 0; j < 4; j++) s[t][j] *= scale;
        }

        float mx0 = -1e30f, mx1 = -1e30f;
#pragma unroll
        for (int t = 0; t < 8; t++) {
            mx0 = fmaxf(mx0, fmaxf(s[t][0], s[t][1]));
            mx1 = fmaxf(mx1, fmaxf(s[t][2], s[t][3]));
        }
        mx0 = fmaxf(mx0, __shfl_xor_sync(0xffffffffu, mx0, 1));
        mx0 = fmaxf(mx0, __shfl_xor_sync(0xffffffffu, mx0, 2));
        mx1 = fmaxf(mx1, __shfl_xor_sync(0xffffffffu, mx1, 1));
        mx1 = fmaxf(mx1, __shfl_xor_sync(0xffffffffu, mx1, 2));

        float mn0 = fmaxf(m0r, mx0), mn1 = fmaxf(m1r, mx1);
        float al0 = __expf(m0r - mn0), al1 = __expf(m1r - mn1);
        m0r = mn0; m1r = mn1;

        float sum0 = 0.f, sum1 = 0.f;
#pragma unroll
        for (int t = 0; t < 8; t++) {
            s[t][0] = __expf(s[t][0] - mn0); sum0 += s[t][0];
            s[t][1] = __expf(s[t][1] - mn0); sum0 += s[t][1];
            s[t][2] = __expf(s[t][2] - mn1); sum1 += s[t][2];
            s[t][3] = __expf(s[t][3] - mn1); sum1 += s[t][3];
        }
        l0 = l0*al0 + sum0;
        l1 = l1*al1 + sum1;
#pragma unroll
        for (int t = 0; t < 16; t++) {
            O[t][0] *= al0; O[t][1] *= al0;
            O[t][2] *= al1; O[t][3] *= al1;
        }

        // ---- O += P V ----
#pragma unroll
        for (int kc2 = 0; kc2 < 4; kc2++) {
            uint32_t pha[4], pla[4];
            {
                const float* s0 = s[kc2*2];
                const float* s1 = s[kc2*2 + 1];
                float h00 = __bfloat162float(__float2bfloat16(s0[0]));
                float h01 = __bfloat162float(__float2bfloat16(s0[1]));
                float h02 = __bfloat162float(__float2bfloat16(s0[2]));
                float h03 = __bfloat162float(__float2bfloat16(s0[3]));
                float h10 = __bfloat162float(__float2bfloat16(s1[0]));
                float h11 = __bfloat162float(__float2bfloat16(s1[1]));
                float h12 = __bfloat162float(__float2bfloat16(s1[2]));
                float h13 = __bfloat162float(__float2bfloat16(s1[3]));
                pha[0] = pack2bf(s0[0], s0[1]);
                pha[1] = pack2bf(s0[2], s0[3]);
                pha[2] = pack2bf(s1[0], s1[1]);
                pha[3] = pack2bf(s1[2], s1[3]);
                pla[0] = pack2bf(s0[0]-h00, s0[1]-h01);
                pla[1] = pack2bf(s0[2]-h02, s0[3]-h03);
                pla[2] = pack2bf(s1[0]-h10, s1[1]-h11);
                pla[3] = pack2bf(s1[2]-h12, s1[3]-h13);
            }
#pragma unroll
            for (int dg = 0; dg < 8; dg++) {
                uint32_t vh[4], vl[4];
                int r = kc2*16 + lrow;
                int c = dg*2 + lhi;
                int cs = (c & ~7) | ((c ^ r) & 7);
                ldsm4t(vh, sb + AVB +         (r*16 + cs)*16);
                ldsm4t(vl, sb + AVB + 16384 + (r*16 + cs)*16);
                mma16816s(O[dg*2],   pha, vh[0], vh[1]);
                mma16816s(O[dg*2],   pha, vl[0], vl[1]);
                mma16816s(O[dg*2],   pla, vh[0], vh[1]);
                mma16816s(O[dg*2+1], pha, vh[2], vh[3]);
                mma16816s(O[dg*2+1], pha, vl[2], vl[3]);
                mma16816s(O[dg*2+1], pla, vh[2], vh[3]);
            }
        }
        __syncthreads();

        if (i + 1 < ntiles) {
            ldV(sb + AVB,         gVh + (size_t)(k0 + 64)*HD);
            ldV(sb + AVB + 16384, gVl + (size_t)(k0 + 64)*HD);
        }
        asm volatile("cp.async.commit_group;" ::: "memory");
        if (i + 2 < ntiles) {
            ldK(sb + AKB(i & 1),         gKh + (size_t)(k0 + 128)*DQK);
            ldK(sb + AKB(i & 1) + 24576, gKl + (size_t)(k0 + 128)*DQK);
        }
        asm volatile("cp.async.commit_group;" ::: "memory");
    }

    l0 += __shfl_xor_sync(0xffffffffu, l0, 1);
    l0 += __shfl_xor_sync(0xffffffffu, l0, 2);
    l1 += __shfl_xor_sync(0xffffffffu, l1, 1);
    l1 += __shfl_xor_sync(0xffffffffu, l1, 2);
    float inv0 = 1.f / l0, inv1 = 1.f / l1;

#pragma unroll
    for (int t = 0; t < 16; t++) {
        int d = h*HD + t*8 + ((lane & 3) << 1);
        size_t ro0 = (size_t)(b*SEQ + qr0    ) * (NHEADS*HD) + d;
        size_t ro1 = (size_t)(b*SEQ + qr0 + 8) * (NHEADS*HD) + d;
        float o0 = O[t][0]*inv0, o1 = O[t][1]*inv0;
        float o2 = O[t][2]*inv1, o3 = O[t][3]*inv1;
        wsplit2(cxh, cxl, ro0, o0, o1);
        wsplit2(cxh, cxl, ro1, o2, o3);
    }
}

// ---------------- launch -----------------------------------------------------
static inline void gemm_m(const __nv_bfloat16* Ah, const __nv_bfloat16* Al,
                          const __nv_bfloat16* Bh, const __nv_bfloat16* Bl,
                          const float* bias, float* C,
                          __nv_bfloat16* Ch, __nv_bfloat16* Cl,
                          int M, int N, int K, int mode)
{
    gemm_hmma_split<<<dim3(N/128, M/128), 256, GEMM_SMEM>>>(
        Ah, Al, Bh, Bl, bias, C, Ch, Cl, M, N, K, mode);
}

extern "C" void kernel_launch(void* const* d_in, const int* in_sizes, int n_in,
                              void* d_out, int out_size)
{
    const float* x    = (const float*)d_in[0];
    const float* kvdw = (const float*)d_in[2];
    const float* kvdb = (const float*)d_in[3];
    const float* kuw  = (const float*)d_in[4];
    const float* kub  = (const float*)d_in[5];
    const float* vuw  = (const float*)d_in[6];
    const float* vub  = (const float*)d_in[7];
    const float* krw  = (const float*)d_in[8];
    const float* krb  = (const float*)d_in[9];
    const float* qdw  = (const float*)d_in[10];
    const float* qdb  = (const float*)d_in[11];
    const float* quw  = (const float*)d_in[12];
    const float* qub  = (const float*)d_in[13];
    const float* qrw  = (const float*)d_in[14];
    const float* qrb  = (const float*)d_in[15];
    const float* ow   = (const float*)d_in[16];
    const float* obv  = (const float*)d_in[17];
    float* out = (float*)d_out;

    float *kr, *qru;
    cudaGetSymbolAddress((void**)&kr,   g_kr);
    cudaGetSymbolAddress((void**)&qru,  g_qru);

    __nv_bfloat16 *Qh,*Ql,*Kh,*Kl,*Vh,*Vl;
    cudaGetSymbolAddress((void**)&Qh, g_Qh); cudaGetSymbolAddress((void**)&Ql, g_Ql);
    cudaGetSymbolAddress((void**)&Kh, g_Kh); cudaGetSymbolAddress((void**)&Kl, g_Kl);
    cudaGetSymbolAddress((void**)&Vh, g_Vh); cudaGetSymbolAddress((void**)&Vl, g_Vl);

    __nv_bfloat16 *xh,*xl,*kvch,*kvcl,*qlh,*qll,*cxh,*cxl;
    __nv_bfloat16 *kvdwh,*kvdwl,*kuwh,*kuwl,*vuwh,*vuwl,*krwh,*krwl;
    __nv_bfloat16 *qdwh,*qdwl,*quwh,*quwl,*qrwh,*qrwl,*owh,*owl;
    cudaGetSymbolAddress((void**)&xh, g_xh);     cudaGetSymbolAddress((void**)&xl, g_xl);
    cudaGetSymbolAddress((void**)&kvch, g_kvch); cudaGetSymbolAddress((void**)&kvcl, g_kvcl);
    cudaGetSymbolAddress((void**)&qlh, g_qlh);   cudaGetSymbolAddress((void**)&qll, g_qll);
    cudaGetSymbolAddress((void**)&cxh, g_cxh);   cudaGetSymbolAddress((void**)&cxl, g_cxl);
    cudaGetSymbolAddress((void**)&kvdwh, g_kvdwh); cudaGetSymbolAddress((void**)&kvdwl, g_kvdwl);
    cudaGetSymbolAddress((void**)&kuwh, g_kuwh);   cudaGetSymbolAddress((void**)&kuwl, g_kuwl);
    cudaGetSymbolAddress((void**)&vuwh, g_vuwh);   cudaGetSymbolAddress((void**)&vuwl, g_vuwl);
    cudaGetSymbolAddress((void**)&krwh, g_krwh);   cudaGetSymbolAddress((void**)&krwl, g_krwl);
    cudaGetSymbolAddress((void**)&qdwh, g_qdwh);   cudaGetSymbolAddress((void**)&qdwl, g_qdwl);
    cudaGetSymbolAddress((void**)&quwh, g_quwh);   cudaGetSymbolAddress((void**)&quwl, g_quwl);
    cudaGetSymbolAddress((void**)&qrwh, g_qrwh);   cudaGetSymbolAddress((void**)&qrwl, g_qrwl);
    cudaGetSymbolAddress((void**)&owh, g_owh);     cudaGetSymbolAddress((void**)&owl, g_owl);

    cudaFuncSetAttribute(gemm_hmma_split, cudaFuncAttributeMaxDynamicSharedMemorySize, GEMM_SMEM);
    cudaFuncSetAttribute(attn_hmma, cudaFuncAttributeMaxDynamicSharedMemorySize, ATTN_SMEM);

    dim3 tb(32, 8);

    // weight transpose+split: src [K][N] -> [N][K] hi/lo
    transpose_split<<<dim3(KVC/32,       HIDDEN/32), tb>>>(kvdw, kvdwh, kvdwl, HIDDEN, KVC);
    transpose_split<<<dim3(NHEADS*HD/32, KVC/32),    tb>>>(kuw,  kuwh,  kuwl,  KVC, NHEADS*HD);
    transpose_split<<<dim3(NHEADS*HD/32, KVC/32),    tb>>>(vuw,  vuwh,  vuwl,  KVC, NHEADS*HD);
    transpose_split<<<dim3(NHEADS*RD/32, KVC/32),    tb>>>(krw,  krwh,  krwl,  KVC, NHEADS*RD);
    transpose_split<<<dim3(QC/32,        HIDDEN/32), tb>>>(qdw,  qdwh,  qdwl,  HIDDEN, QC);
    transpose_split<<<dim3(NHEADS*HD/32, QC/32),     tb>>>(quw,  quwh,  quwl,  QC, NHEADS*HD);
    transpose_split<<<dim3(NHEADS*RD/32, QC/32),     tb>>>(qrw,  qrwh,  qrwl,  QC, NHEADS*RD);
    transpose_split<<<dim3(HIDDEN/32,    NHEADS*HD/32), tb>>>(ow, owh, owl, NHEADS*HD, HIDDEN);

    // x split
    split_fp32<<<ROWS*HIDDEN/4/256, 256>>>(x, xh, xl, ROWS*HIDDEN);

    // kv path  (kv_down writes split kvc directly; up-projs write attention layout)
    gemm_m(xh, xl, kvdwh, kvdwl, kvdb, nullptr, kvch, kvcl, ROWS, KVC,       HIDDEN, 1);
    gemm_m(kvch, kvcl, kuwh, kuwl, kub, nullptr, Kh, Kl,    ROWS, NHEADS*HD, KVC,    2);
    gemm_m(kvch, kvcl, vuwh, vuwl, vub, nullptr, Vh, Vl,    ROWS, NHEADS*HD, KVC,    3);
    gemm_m(kvch, kvcl, krwh, krwl, krb, kr, nullptr, nullptr, ROWS, NHEADS*RD, KVC,  0);

    // q path
    gemm_m(xh, xl, qdwh, qdwl, qdb, nullptr, qlh, qll,      ROWS, QC,        HIDDEN, 1);
    gemm_m(qlh, qll, quwh, quwl, qub, nullptr, Qh, Ql,      ROWS, NHEADS*HD, QC,     2);
    gemm_m(qlh, qll, qrwh, qrwl, qrb, qru, nullptr, nullptr, ROWS, NHEADS*RD, QC,    0);

    // rope into last 64 dims of split K/Q
    rope_packsplit<<<ROWS*NHEADS*(RD/2)/256, 256>>>(kr, qru, Kh, Kl, Qh, Ql);

    // attention (HMMA split-bf16) — writes split ctx directly
    attn_hmma<<<dim3(SEQ/128, NHEADS, BATCH), 256, ATTN_SMEM>>>(Qh, Ql, Kh, Kl, Vh, Vl, cxh, cxl);

    // output projection
    gemm_m(cxh, cxl, owh, owl, obv, out, nullptr, nullptr,  ROWS, HIDDEN, NHEADS*HD, 0);
}

// round 7
// speedup vs baseline: 3.4989x; 1.3762x over previous
#include <cuda_runtime.h>
#include <cuda_fp16.h>
#include <cstdint>
#include <math.h>

#define HIDDEN 2048
#define NHEADS 16
#define HD 128
#define RD 64
#define DQK 192
#define KVC 512
#define QC 1536
#define BATCH 2
#define SEQ 2048
#define ROWS (BATCH*SEQ)   // 4096

// ---------------- scratch (static device memory; no allocation allowed) -----
__device__ float g_kr [ROWS*NHEADS*RD];
__device__ float g_qru[ROWS*NHEADS*RD];

// attention operands [B,H,S,*]: Q split hi/lo, K/V hi only
__device__ __half g_Qh[(size_t)BATCH*NHEADS*SEQ*DQK], g_Ql[(size_t)BATCH*NHEADS*SEQ*DQK];
__device__ __half g_Kh[(size_t)BATCH*NHEADS*SEQ*DQK];
__device__ __half g_Vh[(size_t)BATCH*NHEADS*SEQ*HD];

// split fp16 activations
__device__ __half g_xh [ROWS*HIDDEN],  g_xl [ROWS*HIDDEN];
__device__ __half g_kvch[ROWS*KVC],    g_kvcl[ROWS*KVC];
__device__ __half g_qlh [ROWS*QC],     g_qll [ROWS*QC];
__device__ __half g_cxh [ROWS*NHEADS*HD], g_cxl[ROWS*NHEADS*HD];

// weights transposed to [N][K], fp16 hi only
__device__ __half g_kvdwh[KVC*HIDDEN];
__device__ __half g_kuwh [NHEADS*HD*KVC];
__device__ __half g_vuwh [NHEADS*HD*KVC];
__device__ __half g_krwh [NHEADS*RD*KVC];
__device__ __half g_qdwh [QC*HIDDEN];
__device__ __half g_quwh [NHEADS*HD*QC];
__device__ __half g_qrwh [NHEADS*RD*QC];
__device__ __half g_owh  [HIDDEN*NHEADS*HD];

// ======================= mma / ldmatrix helpers =============================
__device__ __forceinline__ uint32_t s2u(const void* p) {
    return (uint32_t)__cvta_generic_to_shared(p);
}
__device__ __forceinline__ void ldsm4(uint32_t* r, uint32_t addr) {
    asm volatile("ldmatrix.sync.aligned.m8n8.x4.shared.b16 {%0,%1,%2,%3}, [%4];"
                 : "=r"(r[0]), "=r"(r[1]), "=r"(r[2]), "=r"(r[3]) : "r"(addr));
}
__device__ __forceinline__ void ldsm4t(uint32_t* r, uint32_t addr) {
    asm volatile("ldmatrix.sync.aligned.m8n8.x4.trans.shared.b16 {%0,%1,%2,%3}, [%4];"
                 : "=r"(r[0]), "=r"(r[1]), "=r"(r[2]), "=r"(r[3]) : "r"(addr));
}
__device__ __forceinline__ void mmah(float* c, const uint32_t* a, const uint32_t* b) {
    asm volatile(
        "mma.sync.aligned.m16n8k16.row.col.f32.f16.f16.f32 "
        "{%0,%1,%2,%3}, {%4,%5,%6,%7}, {%8,%9}, {%0,%1,%2,%3};"
        : "+f"(c[0]), "+f"(c[1]), "+f"(c[2]), "+f"(c[3])
        : "r"(a[0]), "r"(a[1]), "r"(a[2]), "r"(a[3]), "r"(b[0]), "r"(b[1]));
}
__device__ __forceinline__ void mmahs(float* c, const uint32_t* a, uint32_t b0, uint32_t b1) {
    asm volatile(
        "mma.sync.aligned.m16n8k16.row.col.f32.f16.f16.f32 "
        "{%0,%1,%2,%3}, {%4,%5,%6,%7}, {%8,%9}, {%0,%1,%2,%3};"
        : "+f"(c[0]), "+f"(c[1]), "+f"(c[2]), "+f"(c[3])
        : "r"(a[0]), "r"(a[1]), "r"(a[2]), "r"(a[3]), "r"(b0), "r"(b1));
}
__device__ __forceinline__ void cpasync16(uint32_t dst, const void* src) {
    asm volatile("cp.async.cg.shared.global [%0], [%1], 16;"
                 :: "r"(dst), "l"(src) : "memory");
}
__device__ __forceinline__ uint32_t pack2h(float x, float y) {
    __half2 t = __floats2half2_rn(x, y);
    return *(uint32_t*)&t;
}
__device__ __forceinline__ void wsplit2h(__half* __restrict__ H,
                                         __half* __restrict__ L,
                                         size_t o, float a, float b) {
    __half ha = __float2half_rn(a), hb = __float2half_rn(b);
    *(__half2*)&H[o] = __halves2half2(ha, hb);
    *(__half2*)&L[o] = __halves2half2(
        __float2half_rn(a - __half2float(ha)),
        __float2half_rn(b - __half2float(hb)));
}
__device__ __forceinline__ void whi2(__half* __restrict__ H, size_t o, float a, float b) {
    *(__half2*)&H[o] = __floats2half2_rn(a, b);
}

// ======================= fp32 -> fp16 hi/lo split ===========================
__global__ void split_fp32(const float* __restrict__ s,
                           __half* __restrict__ h,
                           __half* __restrict__ l, int n)
{
    int i = (blockIdx.x * blockDim.x + threadIdx.x) * 4;
    if (i >= n) return;
    float4 v = *(const float4*)(s + i);
    __half h0 = __float2half_rn(v.x), h1 = __float2half_rn(v.y);
    __half h2 = __float2half_rn(v.z), h3 = __float2half_rn(v.w);
    *(__half2*)(h + i)     = __halves2half2(h0, h1);
    *(__half2*)(h + i + 2) = __halves2half2(h2, h3);
    *(__half2*)(l + i)     = __halves2half2(
        __float2half_rn(v.x - __half2float(h0)),
        __float2half_rn(v.y - __half2float(h1)));
    *(__half2*)(l + i + 2) = __halves2half2(
        __float2half_rn(v.z - __half2float(h2)),
        __float2half_rn(v.w - __half2float(h3)));
}

// transpose: src[K][N] fp32 -> dst [N][K] fp16 (hi only)
__global__ void transpose_half(const float* __restrict__ src,
                               __half* __restrict__ dh,
                               int K, int N)
{
    __shared__ float t[32][33];
    int kb = blockIdx.y * 32, nb = blockIdx.x * 32;
    int tx = threadIdx.x, ty = threadIdx.y;    // 32 x 8
#pragma unroll
    for (int i = 0; i < 32; i += 8)
        t[ty + i][tx] = src[(size_t)(kb + ty + i) * N + nb + tx];
    __syncthreads();
#pragma unroll
    for (int i = 0; i < 32; i += 8)
        dh[(size_t)(nb + ty + i) * K + kb + tx] = __float2half_rn(t[tx][ty + i]);
}

// ======================= HMMA 2-product fp16 GEMM ===========================
// C[M,N] = (Ah+Al)[M,K] @ Bh[N,K]^T + bias.  CTA 128x128, BK=32, 8 warps,
// 3-stage cp.async.  Epilogue modes:
//   0 = fp32 C;  1 = split fp16 [M,N];  2 = split fp16 [B,H,S,192];
//   3 = hi fp16 [B,H,S,128];  4 = hi fp16 [B,H,S,192]
#define BKP 40
#define MAT_SMEM (128*BKP*2)      // 10240
#define STG_SMEM (3*MAT_SMEM)     // 30720
#define GEMM_SMEM (3*STG_SMEM)    // 92160

__global__ void __launch_bounds__(256, 1) gemm_hmma2(
    const __half* __restrict__ Ah, const __half* __restrict__ Al,
    const __half* __restrict__ Bh,
    const float* __restrict__ bias, float* __restrict__ C,
    __half* __restrict__ Ch, __half* __restrict__ Cl,
    int M, int N, int K, int mode)
{
    extern __shared__ char dsm[];
    const uint32_t sbase = s2u(dsm);

    const int tid  = threadIdx.x;
    const int warp = tid >> 5, lane = tid & 31;
    const int wm = (warp & 3) * 32;
    const int wn = (warp >> 2) * 64;
    const int m0 = blockIdx.y * 128, n0 = blockIdx.x * 128;

    const int ldrow = tid >> 2;
    const int ldchk = (tid & 3) * 8;

    const __half* gM[3] = { Ah + (size_t)m0 * K, Al + (size_t)m0 * K,
                            Bh + (size_t)n0 * K };

    const int nK = K >> 5;

    const int a_r  = lane & 15;
    const int a_c8 = (lane >> 4) << 3;
    const int b_r  = (lane & 7) + ((lane >> 4) << 3);
    const int b_c8 = (lane & 8) ? 8 : 0;

    float acc[2][8][4];
#pragma unroll
    for (int mt = 0; mt < 2; mt++)
#pragma unroll
        for (int nt = 0; nt < 8; nt++)
#pragma unroll
            for (int q = 0; q < 4; q++) acc[mt][nt][q] = 0.f;

    auto load_stage = [&](int stg, int kb) {
        uint32_t sb = sbase + stg * STG_SMEM;
#pragma unroll
        for (int mat = 0; mat < 3; mat++) {
            const __half* g = gM[mat];
#pragma unroll
            for (int j = 0; j < 2; j++) {
                int row = ldrow + j * 64;
                cpasync16(sb + mat * MAT_SMEM + (row * BKP + ldchk) * 2,
                          g + (size_t)row * K + kb + ldchk);
            }
        }
        asm volatile("cp.async.commit_group;" ::: "memory");
    };

    load_stage(0, 0);
    load_stage(1, 32);

    int cur = 0, nxt = 2;
    for (int i = 0; i < nK; i++) {
        if (i + 1 < nK) asm volatile("cp.async.wait_group 1;" ::: "memory");
        else            asm volatile("cp.async.wait_group 0;" ::: "memory");
        __syncthreads();
        if (i + 2 < nK) load_stage(nxt, (i + 2) * 32);

        const uint32_t sAh = sbase + cur * STG_SMEM;
        const uint32_t sAl = sAh + MAT_SMEM;
        const uint32_t sBh = sAh + 2 * MAT_SMEM;

#pragma unroll
        for (int kk = 0; kk < 32; kk += 16) {
            uint32_t ah[2][4], al[2][4], bh[4][4];
#pragma unroll
            for (int mt = 0; mt < 2; mt++) {
                uint32_t off = ((wm + mt * 16 + a_r) * BKP + kk + a_c8) * 2;
                ldsm4(ah[mt], sAh + off);
                ldsm4(al[mt], sAl + off);
            }
#pragma unroll
            for (int p = 0; p < 4; p++) {
                uint32_t off = ((wn + p * 16 + b_r) * BKP + kk + b_c8) * 2;
                ldsm4(bh[p], sBh + off);
            }
#pragma unroll
            for (int mt = 0; mt < 2; mt++)
#pragma unroll
                for (int nt = 0; nt < 8; nt++) {
                    const uint32_t* bhf = &bh[nt >> 1][(nt & 1) * 2];
                    mmah(acc[mt][nt], ah[mt], bhf);
                    mmah(acc[mt][nt], al[mt], bhf);
                }
        }
        cur = (cur == 2) ? 0 : cur + 1;
        nxt = (nxt == 2) ? 0 : nxt + 1;
    }

    // ---- epilogue ----
    const int er = lane >> 2, ec = (lane & 3) * 2;
#pragma unroll
    for (int mt = 0; mt < 2; mt++) {
#pragma unroll
        for (int nt = 0; nt < 8; nt++) {
            int col = n0 + wn + nt * 8 + ec;
            float b0 = bias[col], b1 = bias[col + 1];
            int r0 = m0 + wm + mt * 16 + er;
            int r1 = r0 + 8;
            float p0 = acc[mt][nt][0] + b0, p1 = acc[mt][nt][1] + b1;
            float p2 = acc[mt][nt][2] + b0, p3 = acc[mt][nt][3] + b1;
            if (mode == 0) {
                *(float2*)&C[(size_t)r0 * N + col] = make_float2(p0, p1);
                *(float2*)&C[(size_t)r1 * N + col] = make_float2(p2, p3);
            } else if (mode == 1) {
                wsplit2h(Ch, Cl, (size_t)r0 * N + col, p0, p1);
                wsplit2h(Ch, Cl, (size_t)r1 * N + col, p2, p3);
            } else {
                int hh = col >> 7, d = col & 127;
                int stride = (mode == 3) ? HD : DQK;
                size_t o0 = (((size_t)(r0 >> 11) * NHEADS + hh) * SEQ + (r0 & 2047)) * stride + d;
                size_t o1 = (((size_t)(r1 >> 11) * NHEADS + hh) * SEQ + (r1 & 2047)) * stride + d;
                if (mode == 2) {
                    wsplit2h(Ch, Cl, o0, p0, p1);
                    wsplit2h(Ch, Cl, o1, p2, p3);
                } else {
                    whi2(Ch, o0, p0, p1);
                    whi2(Ch, o1, p2, p3);
                }
            }
        }
    }
}

// ------- RoPE into last 64 dims: K hi only, Q split -------------------------
__global__ void rope_packsplit(const float* __restrict__ kr, const float* __restrict__ qr,
                               __half* __restrict__ Kh,
                               __half* __restrict__ Qh, __half* __restrict__ Ql)
{
    int idx = blockIdx.x * blockDim.x + threadIdx.x;
    if (idx >= ROWS*NHEADS*(RD/2)) return;
    int i  = idx & 31;
    int h  = (idx >> 5) & 15;
    int bs = idx >> 9;
    int b  = bs >> 11;
    int s  = bs & 2047;
    float inv_freq = powf(10000.f, -(float)(2*i) / 64.f);
    float ang = (float)s * inv_freq;
    float sn, cs;
    sincosf(ang, &sn, &cs);
    size_t ib = (size_t)bs * (NHEADS*RD) + h*RD + 2*i;
    size_t ob = (((size_t)b*NHEADS + h)*SEQ + s)*DQK + HD + 2*i;
    float x1 = kr[ib], x2 = kr[ib+1];
    whi2(Kh, ob, x1*cs - x2*sn, x1*sn + x2*cs);
    x1 = qr[ib]; x2 = qr[ib+1];
    wsplit2h(Qh, Ql, ob, x1*cs - x2*sn, x1*sn + x2*cs);
}

// ============== HMMA 2-product fp16 causal flash attention ==================
// CTA: 128 queries x full head. 8 warps, warp = 16 query rows.
// smem: Qh/Ql [128x192], K hi double-buffered [64x192]x2, V hi [64x128]
#define AQH 0
#define AQL 49152
#define AKB(buf) (98304 + (buf)*24576)
#define AVB 147456
#define ATTN_SMEM 163840

__global__ void __launch_bounds__(256, 1) attn_hmma(
    const __half* __restrict__ Qhg, const __half* __restrict__ Qlg,
    const __half* __restrict__ Khg, const __half* __restrict__ Vhg,
    __half* __restrict__ cxh, __half* __restrict__ cxl)
{
    extern __shared__ char smc[];
    const uint32_t sb = s2u(smc);
    const int b = blockIdx.z, h = blockIdx.y;
    const int q0 = blockIdx.x * 128;
    const int tid = threadIdx.x, w = tid >> 5, lane = tid & 31;
    const int ntiles = (q0 >> 6) + 2;

    const size_t hb = (size_t)(b*NHEADS + h) * SEQ;
    const __half* gQh = Qhg + (hb + q0) * DQK;
    const __half* gQl = Qlg + (hb + q0) * DQK;
    const __half* gKh = Khg + hb * DQK;
    const __half* gVh = Vhg + hb * HD;

    auto ldQ = [&](uint32_t dst, const __half* g) {
        for (int i = tid; i < 128*24; i += 256) {
            int r = i / 24, c = i % 24;
            int cs = (c & ~7) | ((c ^ r) & 7);
            cpasync16(dst + (r*24 + cs)*16, g + r*192 + c*8);
        }
    };
    auto ldK = [&](uint32_t dst, const __half* g) {
        for (int i = tid; i < 64*24; i += 256) {
            int r = i / 24, c = i % 24;
            int cs = (c & ~7) | ((c ^ r) & 7);
            cpasync16(dst + (r*24 + cs)*16, g + r*192 + c*8);
        }
    };
    auto ldV = [&](uint32_t dst, const __half* g) {
        for (int i = tid; i < 64*16; i += 256) {
            int r = i / 16, c = i % 16;
            int cs = (c & ~7) | ((c ^ r) & 7);
            cpasync16(dst + (r*16 + cs)*16, g + r*128 + c*8);
        }
    };

    // prologue: group0 = {Q, K0, V0}, group1 = {K1}
    ldQ(sb + AQH, gQh);
    ldQ(sb + AQL, gQl);
    ldK(sb + AKB(0), gKh);
    ldV(sb + AVB,    gVh);
    asm volatile("cp.async.commit_group;" ::: "memory");
    ldK(sb + AKB(1), gKh + 64*192);
    asm volatile("cp.async.commit_group;" ::: "memory");

    float O[16][4];
#pragma unroll
    for (int t = 0; t < 16; t++)
#pragma unroll
        for (int j = 0; j < 4; j++) O[t][j] = 0.f;
    float m0r = -1e30f, m1r = -1e30f, l0 = 0.f, l1 = 0.f;

    const float scale = 0.07216878364870323f;  // 1/sqrt(192)
    const int lrow = lane & 15, lhi = lane >> 4;
    const int qr0 = q0 + w*16 + (lane >> 2);

    for (int i = 0; i < ntiles; i++) {
        const int k0 = i * 64;
        asm volatile("cp.async.wait_group 1;" ::: "memory");
        __syncthreads();

        const uint32_t kbh = sb + AKB(i & 1);

        float s[8][4];
#pragma unroll
        for (int t = 0; t < 8; t++)
#pragma unroll
            for (int j = 0; j < 4; j++) s[t][j] = 0.f;

        // ---- S = (Qh+Ql) Kh^T ----
#pragma unroll
        for (int kc = 0; kc < 12; kc++) {
            uint32_t ah[4], al[4];
            {
                int r = w*16 + lrow;
                int c = kc*2 + lhi;
                int cs = (c & ~7) | ((c ^ r) & 7);
                ldsm4(ah, sb + AQH + (r*24 + cs)*16);
                ldsm4(al, sb + AQL + (r*24 + cs)*16);
            }
#pragma unroll
            for (int kg = 0; kg < 4; kg++) {
                uint32_t bh[4];
                int r = kg*16 + lrow;
                int c = kc*2 + lhi;
                int cs = (c & ~7) | ((c ^ r) & 7);
                ldsm4(bh, kbh + (r*24 + cs)*16);
                mmahs(s[kg*2],   ah, bh[0], bh[2]);
                mmahs(s[kg*2],   al, bh[0], bh[2]);
                mmahs(s[kg*2+1], ah, bh[1], bh[3]);
                mmahs(s[kg*2+1], al, bh[1], bh[3]);
            }
        }

        // ---- online softmax ----
        if (k0 + 63 > q0 + w*16) {
#pragma unroll
            for (int t = 0; t < 8; t++) {
                int kb = k0 + t*8 + ((lane & 3) << 1);
                s[t][0] = (kb     <= qr0    ) ? s[t][0]*scale : -1e30f;
                s[t][1] = (kb + 1 <= qr0    ) ? s[t][1]*scale : -1e30f;
                s[t][2] = (kb     <= qr0 + 8) ? s[t][2]*scale : -1e30f;
                s[t][3] = (kb + 1 <= qr0 + 8) ? s[t][3]*scale : -1e30f;
            }
        } else {
#pragma unroll
            for (int t = 0; t < 8; t++)
#pragma unroll
                for (int j = 0; j < 4; j++) s[t][j] *= scale;
        }

        float mx0 = -1e30f, mx1 = -1e30f;
#pragma unroll
        for (int t = 0; t < 8; t++) {
            mx0 = fmaxf(mx0, fmaxf(s[t][0], s[t][1]));
            mx1 = fmaxf(mx1, fmaxf(s[t][2], s[t][3]));
        }
        mx0 = fmaxf(mx0, __shfl_xor_sync(0xffffffffu, mx0, 1));
        mx0 = fmaxf(mx0, __shfl_xor_sync(0xffffffffu, mx0, 2));
        mx1 = fmaxf(mx1, __shfl_xor_sync(0xffffffffu, mx1, 1));
        mx1 = fmaxf(mx1, __shfl_xor_sync(0xffffffffu, mx1, 2));

        float mn0 = fmaxf(m0r, mx0), mn1 = fmaxf(m1r, mx1);
        float al0 = __expf(m0r - mn0), al1 = __expf(m1r - mn1);
        m0r = mn0; m1r = mn1;

        float sum0 = 0.f, sum1 = 0.f;
#pragma unroll
        for (int t = 0; t < 8; t++) {
            s[t][0] = __expf(s[t][0] - mn0); sum0 += s[t][0];
            s[t][1] = __expf(s[t][1] - mn0); sum0 += s[t][1];
            s[t][2] = __expf(s[t][2] - mn1); sum1 += s[t][2];
            s[t][3] = __expf(s[t][3] - mn1); sum1 += s[t][3];
        }
        l0 = l0*al0 + sum0;
        l1 = l1*al1 + sum1;
#pragma unroll
        for (int t = 0; t < 16; t++) {
            O[t][0] *= al0; O[t][1] *= al0;
            O[t][2] *= al1; O[t][3] *= al1;
        }

        // ---- O += (Ph+Pl) Vh ----
#pragma unroll
        for (int kc2 = 0; kc2 < 4; kc2++) {
            uint32_t pha[4], pla[4];
            {
                const float* s0 = s[kc2*2];
                const float* s1 = s[kc2*2 + 1];
                float h00 = __half2float(__float2half_rn(s0[0]));
                float h01 = __half2float(__float2half_rn(s0[1]));
                float h02 = __half2float(__float2half_rn(s0[2]));
                float h03 = __half2float(__float2half_rn(s0[3]));
                float h10 = __half2float(__float2half_rn(s1[0]));
                float h11 = __half2float(__float2half_rn(s1[1]));
                float h12 = __half2float(__float2half_rn(s1[2]));
                float h13 = __half2float(__float2half_rn(s1[3]));
                pha[0] = pack2h(s0[0], s0[1]);
                pha[1] = pack2h(s0[2], s0[3]);
                pha[2] = pack2h(s1[0], s1[1]);
                pha[3] = pack2h(s1[2], s1[3]);
                pla[0] = pack2h(s0[0]-h00, s0[1]-h01);
                pla[1] = pack2h(s0[2]-h02, s0[3]-h03);
                pla[2] = pack2h(s1[0]-h10, s1[1]-h11);
                pla[3] = pack2h(s1[2]-h12, s1[3]-h13);
            }
#pragma unroll
            for (int dg = 0; dg < 8; dg++) {
                uint32_t vh[4];
                int r = kc2*16 + lrow;
                int c = dg*2 + lhi;
                int cs = (c & ~7) | ((c ^ r) & 7);
                ldsm4t(vh, sb + AVB + (r*16 + cs)*16);
                mmahs(O[dg*2],   pha, vh[0], vh[1]);
                mmahs(O[dg*2],   pla, vh[0], vh[1]);
                mmahs(O[dg*2+1], pha, vh[2], vh[3]);
                mmahs(O[dg*2+1], pla, vh[2], vh[3]);
            }
        }
        __syncthreads();

        if (i + 1 < ntiles)
            ldV(sb + AVB, gVh + (size_t)(k0 + 64)*HD);
        asm volatile("cp.async.commit_group;" ::: "memory");
        if (i + 2 < ntiles)
            ldK(sb + AKB(i & 1), gKh + (size_t)(k0 + 128)*DQK);
        asm volatile("cp.async.commit_group;" ::: "memory");
    }

    l0 += __shfl_xor_sync(0xffffffffu, l0, 1);
    l0 += __shfl_xor_sync(0xffffffffu, l0, 2);
    l1 += __shfl_xor_sync(0xffffffffu, l1, 1);
    l1 += __shfl_xor_sync(0xffffffffu, l1, 2);
    float inv0 = 1.f / l0, inv1 = 1.f / l1;

#pragma unroll
    for (int t = 0; t < 16; t++) {
        int d = h*HD + t*8 + ((lane & 3) << 1);
        size_t ro0 = (size_t)(b*SEQ + qr0    ) * (NHEADS*HD) + d;
        size_t ro1 = (size_t)(b*SEQ + qr0 + 8) * (NHEADS*HD) + d;
        wsplit2h(cxh, cxl, ro0, O[t][0]*inv0, O[t][1]*inv0);
        wsplit2h(cxh, cxl, ro1, O[t][2]*inv1, O[t][3]*inv1);
    }
}

// ---------------- launch -----------------------------------------------------
static inline void gemm_m(const __half* Ah, const __half* Al, const __half* Bh,
                          const float* bias, float* C,
                          __half* Ch, __half* Cl,
                          int M, int N, int K, int mode)
{
    gemm_hmma2<<<dim3(N/128, M/128), 256, GEMM_SMEM>>>(
        Ah, Al, Bh, bias, C, Ch, Cl, M, N, K, mode);
}

extern "C" void kernel_launch(void* const* d_in, const int* in_sizes, int n_in,
                              void* d_out, int out_size)
{
    const float* x    = (const float*)d_in[0];
    const float* kvdw = (const float*)d_in[2];
    const float* kvdb = (const float*)d_in[3];
    const float* kuw  = (const float*)d_in[4];
    const float* kub  = (const float*)d_in[5];
    const float* vuw  = (const float*)d_in[6];
    const float* vub  = (const float*)d_in[7];
    const float* krw  = (const float*)d_in[8];
    const float* krb  = (const float*)d_in[9];
    const float* qdw  = (const float*)d_in[10];
    const float* qdb  = (const float*)d_in[11];
    const float* quw  = (const float*)d_in[12];
    const float* qub  = (const float*)d_in[13];
    const float* qrw  = (const float*)d_in[14];
    const float* qrb  = (const float*)d_in[15];
    const float* ow   = (const float*)d_in[16];
    const float* obv  = (const float*)d_in[17];
    float* out = (float*)d_out;

    float *kr, *qru;
    cudaGetSymbolAddress((void**)&kr,   g_kr);
    cudaGetSymbolAddress((void**)&qru,  g_qru);

    __half *Qh,*Ql,*Kh,*Vh;
    cudaGetSymbolAddress((void**)&Qh, g_Qh); cudaGetSymbolAddress((void**)&Ql, g_Ql);
    cudaGetSymbolAddress((void**)&Kh, g_Kh); cudaGetSymbolAddress((void**)&Vh, g_Vh);

    __half *xh,*xl,*kvch,*kvcl,*qlh,*qll,*cxh,*cxl;
    __half *kvdwh,*kuwh,*vuwh,*krwh,*qdwh,*quwh,*qrwh,*owh;
    cudaGetSymbolAddress((void**)&xh, g_xh);     cudaGetSymbolAddress((void**)&xl, g_xl);
    cudaGetSymbolAddress((void**)&kvch, g_kvch); cudaGetSymbolAddress((void**)&kvcl, g_kvcl);
    cudaGetSymbolAddress((void**)&qlh, g_qlh);   cudaGetSymbolAddress((void**)&qll, g_qll);
    cudaGetSymbolAddress((void**)&cxh, g_cxh);   cudaGetSymbolAddress((void**)&cxl, g_cxl);
    cudaGetSymbolAddress((void**)&kvdwh, g_kvdwh);
    cudaGetSymbolAddress((void**)&kuwh, g_kuwh);
    cudaGetSymbolAddress((void**)&vuwh, g_vuwh);
    cudaGetSymbolAddress((void**)&krwh, g_krwh);
    cudaGetSymbolAddress((void**)&qdwh, g_qdwh);
    cudaGetSymbolAddress((void**)&quwh, g_quwh);
    cudaGetSymbolAddress((void**)&qrwh, g_qrwh);
    cudaGetSymbolAddress((void**)&owh, g_owh);

    cudaFuncSetAttribute(gemm_hmma2, cudaFuncAttributeMaxDynamicSharedMemorySize, GEMM_SMEM);
    cudaFuncSetAttribute(attn_hmma, cudaFuncAttributeMaxDynamicSharedMemorySize, ATTN_SMEM);

    dim3 tb(32, 8);

    // weight transpose: src [K][N] -> [N][K] fp16 hi
    transpose_half<<<dim3(KVC/32,       HIDDEN/32), tb>>>(kvdw, kvdwh, HIDDEN, KVC);
    transpose_half<<<dim3(NHEADS*HD/32, KVC/32),    tb>>>(kuw,  kuwh,  KVC, NHEADS*HD);
    transpose_half<<<dim3(NHEADS*HD/32, KVC/32),    tb>>>(vuw,  vuwh,  KVC, NHEADS*HD);
    transpose_half<<<dim3(NHEADS*RD/32, KVC/32),    tb>>>(krw,  krwh,  KVC, NHEADS*RD);
    transpose_half<<<dim3(QC/32,        HIDDEN/32), tb>>>(qdw,  qdwh,  HIDDEN, QC);
    transpose_half<<<dim3(NHEADS*HD/32, QC/32),     tb>>>(quw,  quwh,  QC, NHEADS*HD);
    transpose_half<<<dim3(NHEADS*RD/32, QC/32),     tb>>>(qrw,  qrwh,  QC, NHEADS*RD);
    transpose_half<<<dim3(HIDDEN/32,    NHEADS*HD/32), tb>>>(ow, owh, NHEADS*HD, HIDDEN);

    // x split
    split_fp32<<<ROWS*HIDDEN/4/256, 256>>>(x, xh, xl, ROWS*HIDDEN);

    // kv path
    gemm_m(xh, xl, kvdwh, kvdb, nullptr, kvch, kvcl, ROWS, KVC,       HIDDEN, 1);
    gemm_m(kvch, kvcl, kuwh, kub, nullptr, Kh, nullptr, ROWS, NHEADS*HD, KVC, 4);
    gemm_m(kvch, kvcl, vuwh, vub, nullptr, Vh, nullptr, ROWS, NHEADS*HD, KVC, 3);
    gemm_m(kvch, kvcl, krwh, krb, kr, nullptr, nullptr, ROWS, NHEADS*RD, KVC, 0);

    // q path
    gemm_m(xh, xl, qdwh, qdb, nullptr, qlh, qll,     ROWS, QC,        HIDDEN, 1);
    gemm_m(qlh, qll, quwh, qub, nullptr, Qh, Ql,     ROWS, NHEADS*HD, QC,     2);
    gemm_m(qlh, qll, qrwh, qrb, qru, nullptr, nullptr, ROWS, NHEADS*RD, QC,   0);

    // rope into last 64 dims (K hi only, Q split)
    rope_packsplit<<<ROWS*NHEADS*(RD/2)/256, 256>>>(kr, qru, Kh, Qh, Ql);

    // attention (2-product fp16 HMMA) — writes split ctx directly
    attn_hmma<<<dim3(SEQ/128, NHEADS, BATCH), 256, ATTN_SMEM>>>(Qh, Ql, Kh, Vh, cxh, cxl);

    // output projection
    gemm_m(cxh, cxl, owh, obv, out, nullptr, nullptr, ROWS, HIDDEN, NHEADS*HD, 0);
}

// round 8
// speedup vs baseline: 6.2941x; 1.7989x over previous
#include <cuda_runtime.h>
#include <cuda_fp16.h>
#include <cstdint>
#include <math.h>

#define HIDDEN 2048
#define NHEADS 16
#define HD 128
#define RD 64
#define DQK 192
#define KVC 512
#define QC 1536
#define BATCH 2
#define SEQ 2048
#define ROWS (BATCH*SEQ)   // 4096

// ---------------- scratch (static device memory; no allocation allowed) -----
__device__ float g_kr [ROWS*NHEADS*RD];
__device__ float g_qru[ROWS*NHEADS*RD];

// attention operands [B,H,S,*], fp16
__device__ __half g_Qh[(size_t)BATCH*NHEADS*SEQ*DQK];
__device__ __half g_Kh[(size_t)BATCH*NHEADS*SEQ*DQK];
__device__ __half g_Vh[(size_t)BATCH*NHEADS*SEQ*HD];

// fp16 activations
__device__ __half g_xh [ROWS*HIDDEN];
__device__ __half g_kvch[ROWS*KVC];
__device__ __half g_qlh [ROWS*QC];
__device__ __half g_cxh [ROWS*NHEADS*HD];

// weights transposed to [N][K], fp16
__device__ __half g_kvdwh[KVC*HIDDEN];
__device__ __half g_kuwh [NHEADS*HD*KVC];
__device__ __half g_vuwh [NHEADS*HD*KVC];
__device__ __half g_krwh [NHEADS*RD*KVC];
__device__ __half g_qdwh [QC*HIDDEN];
__device__ __half g_quwh [NHEADS*HD*QC];
__device__ __half g_qrwh [NHEADS*RD*QC];
__device__ __half g_owh  [HIDDEN*NHEADS*HD];

// ======================= mma / ldmatrix helpers =============================
__device__ __forceinline__ uint32_t s2u(const void* p) {
    return (uint32_t)__cvta_generic_to_shared(p);
}
__device__ __forceinline__ void ldsm4(uint32_t* r, uint32_t addr) {
    asm volatile("ldmatrix.sync.aligned.m8n8.x4.shared.b16 {%0,%1,%2,%3}, [%4];"
                 : "=r"(r[0]), "=r"(r[1]), "=r"(r[2]), "=r"(r[3]) : "r"(addr));
}
__device__ __forceinline__ void ldsm4t(uint32_t* r, uint32_t addr) {
    asm volatile("ldmatrix.sync.aligned.m8n8.x4.trans.shared.b16 {%0,%1,%2,%3}, [%4];"
                 : "=r"(r[0]), "=r"(r[1]), "=r"(r[2]), "=r"(r[3]) : "r"(addr));
}
__device__ __forceinline__ void mmah(float* c, const uint32_t* a, const uint32_t* b) {
    asm volatile(
        "mma.sync.aligned.m16n8k16.row.col.f32.f16.f16.f32 "
        "{%0,%1,%2,%3}, {%4,%5,%6,%7}, {%8,%9}, {%0,%1,%2,%3};"
        : "+f"(c[0]), "+f"(c[1]), "+f"(c[2]), "+f"(c[3])
        : "r"(a[0]), "r"(a[1]), "r"(a[2]), "r"(a[3]), "r"(b[0]), "r"(b[1]));
}
__device__ __forceinline__ void mmahs(float* c, const uint32_t* a, uint32_t b0, uint32_t b1) {
    asm volatile(
        "mma.sync.aligned.m16n8k16.row.col.f32.f16.f16.f32 "
        "{%0,%1,%2,%3}, {%4,%5,%6,%7}, {%8,%9}, {%0,%1,%2,%3};"
        : "+f"(c[0]), "+f"(c[1]), "+f"(c[2]), "+f"(c[3])
        : "r"(a[0]), "r"(a[1]), "r"(a[2]), "r"(a[3]), "r"(b0), "r"(b1));
}
__device__ __forceinline__ void cpasync16(uint32_t dst, const void* src) {
    asm volatile("cp.async.cg.shared.global [%0], [%1], 16;"
                 :: "r"(dst), "l"(src) : "memory");
}
__device__ __forceinline__ uint32_t pack2h(float x, float y) {
    __half2 t = __floats2half2_rn(x, y);
    return *(uint32_t*)&t;
}
__device__ __forceinline__ void whi2(__half* __restrict__ H, size_t o, float a, float b) {
    *(__half2*)&H[o] = __floats2half2_rn(a, b);
}

// ======================= fp32 -> fp16 convert ===============================
__global__ void conv_half(const float* __restrict__ s, __half* __restrict__ h, int n)
{
    int i = (blockIdx.x * blockDim.x + threadIdx.x) * 4;
    if (i >= n) return;
    float4 v = *(const float4*)(s + i);
    *(__half2*)(h + i)     = __floats2half2_rn(v.x, v.y);
    *(__half2*)(h + i + 2) = __floats2half2_rn(v.z, v.w);
}

// transpose: src[K][N] fp32 -> dst [N][K] fp16
__global__ void transpose_half(const float* __restrict__ src,
                               __half* __restrict__ dh,
                               int K, int N)
{
    __shared__ float t[32][33];
    int kb = blockIdx.y * 32, nb = blockIdx.x * 32;
    int tx = threadIdx.x, ty = threadIdx.y;    // 32 x 8
#pragma unroll
    for (int i = 0; i < 32; i += 8)
        t[ty + i][tx] = src[(size_t)(kb + ty + i) * N + nb + tx];
    __syncthreads();
#pragma unroll
    for (int i = 0; i < 32; i += 8)
        dh[(size_t)(nb + ty + i) * K + kb + tx] = __float2half_rn(t[tx][ty + i]);
}

// ======================= HMMA fp16 GEMM =====================================
// C[M,N] = Ah[M,K] @ Bh[N,K]^T + bias.  CTA 128x128, BK=32, 8 warps,
// 3-stage cp.async.  Epilogue modes:
//   0 = fp32 C;  1 = fp16 [M,N];  2 = fp16 [B,H,S,192];  3 = fp16 [B,H,S,128]
#define BKP 40
#define MAT_SMEM (128*BKP*2)      // 10240
#define STG_SMEM (2*MAT_SMEM)     // 20480
#define GEMM_SMEM (3*STG_SMEM)    // 61440

__global__ void __launch_bounds__(256) gemm_hmma1(
    const __half* __restrict__ Ah, const __half* __restrict__ Bh,
    const float* __restrict__ bias, float* __restrict__ C,
    __half* __restrict__ Ch,
    int M, int N, int K, int mode)
{
    extern __shared__ char dsm[];
    const uint32_t sbase = s2u(dsm);

    const int tid  = threadIdx.x;
    const int warp = tid >> 5, lane = tid & 31;
    const int wm = (warp & 3) * 32;
    const int wn = (warp >> 2) * 64;
    const int m0 = blockIdx.y * 128, n0 = blockIdx.x * 128;

    const int ldrow = tid >> 2;
    const int ldchk = (tid & 3) * 8;

    const __half* gM[2] = { Ah + (size_t)m0 * K, Bh + (size_t)n0 * K };

    const int nK = K >> 5;

    const int a_r  = lane & 15;
    const int a_c8 = (lane >> 4) << 3;
    const int b_r  = (lane & 7) + ((lane >> 4) << 3);
    const int b_c8 = (lane & 8) ? 8 : 0;

    float acc[2][8][4];
#pragma unroll
    for (int mt = 0; mt < 2; mt++)
#pragma unroll
        for (int nt = 0; nt < 8; nt++)
#pragma unroll
            for (int q = 0; q < 4; q++) acc[mt][nt][q] = 0.f;

    auto load_stage = [&](int stg, int kb) {
        uint32_t sb = sbase + stg * STG_SMEM;
#pragma unroll
        for (int mat = 0; mat < 2; mat++) {
            const __half* g = gM[mat];
#pragma unroll
            for (int j = 0; j < 2; j++) {
                int row = ldrow + j * 64;
                cpasync16(sb + mat * MAT_SMEM + (row * BKP + ldchk) * 2,
                          g + (size_t)row * K + kb + ldchk);
            }
        }
        asm volatile("cp.async.commit_group;" ::: "memory");
    };

    load_stage(0, 0);
    load_stage(1, 32);

    int cur = 0, nxt = 2;
    for (int i = 0; i < nK; i++) {
        if (i + 1 < nK) asm volatile("cp.async.wait_group 1;" ::: "memory");
        else            asm volatile("cp.async.wait_group 0;" ::: "memory");
        __syncthreads();
        if (i + 2 < nK) load_stage(nxt, (i + 2) * 32);

        const uint32_t sAh = sbase + cur * STG_SMEM;
        const uint32_t sBh = sAh + MAT_SMEM;

#pragma unroll
        for (int kk = 0; kk < 32; kk += 16) {
            uint32_t ah[2][4], bh[4][4];
#pragma unroll
            for (int mt = 0; mt < 2; mt++) {
                uint32_t off = ((wm + mt * 16 + a_r) * BKP + kk + a_c8) * 2;
                ldsm4(ah[mt], sAh + off);
            }
#pragma unroll
            for (int p = 0; p < 4; p++) {
                uint32_t off = ((wn + p * 16 + b_r) * BKP + kk + b_c8) * 2;
                ldsm4(bh[p], sBh + off);
            }
#pragma unroll
            for (int mt = 0; mt < 2; mt++)
#pragma unroll
                for (int nt = 0; nt < 8; nt++)
                    mmah(acc[mt][nt], ah[mt], &bh[nt >> 1][(nt & 1) * 2]);
        }
        cur = (cur == 2) ? 0 : cur + 1;
        nxt = (nxt == 2) ? 0 : nxt + 1;
    }

    // ---- epilogue ----
    const int er = lane >> 2, ec = (lane & 3) * 2;
#pragma unroll
    for (int mt = 0; mt < 2; mt++) {
#pragma unroll
        for (int nt = 0; nt < 8; nt++) {
            int col = n0 + wn + nt * 8 + ec;
            float b0 = bias[col], b1 = bias[col + 1];
            int r0 = m0 + wm + mt * 16 + er;
            int r1 = r0 + 8;
            float p0 = acc[mt][nt][0] + b0, p1 = acc[mt][nt][1] + b1;
            float p2 = acc[mt][nt][2] + b0, p3 = acc[mt][nt][3] + b1;
            if (mode == 0) {
                *(float2*)&C[(size_t)r0 * N + col] = make_float2(p0, p1);
                *(float2*)&C[(size_t)r1 * N + col] = make_float2(p2, p3);
            } else if (mode == 1) {
                whi2(Ch, (size_t)r0 * N + col, p0, p1);
                whi2(Ch, (size_t)r1 * N + col, p2, p3);
            } else {
                int hh = col >> 7, d = col & 127;
                int stride = (mode == 2) ? DQK : HD;
                size_t o0 = (((size_t)(r0 >> 11) * NHEADS + hh) * SEQ + (r0 & 2047)) * stride + d;
                size_t o1 = (((size_t)(r1 >> 11) * NHEADS + hh) * SEQ + (r1 & 2047)) * stride + d;
                whi2(Ch, o0, p0, p1);
                whi2(Ch, o1, p2, p3);
            }
        }
    }
}

// ------- RoPE into last 64 dims of K/Q --------------------------------------
__global__ void rope_pack(const float* __restrict__ kr, const float* __restrict__ qr,
                          __half* __restrict__ Kh, __half* __restrict__ Qh)
{
    int idx = blockIdx.x * blockDim.x + threadIdx.x;
    if (idx >= ROWS*NHEADS*(RD/2)) return;
    int i  = idx & 31;
    int h  = (idx >> 5) & 15;
    int bs = idx >> 9;
    int b  = bs >> 11;
    int s  = bs & 2047;
    float inv_freq = powf(10000.f, -(float)(2*i) / 64.f);
    float ang = (float)s * inv_freq;
    float sn, cs;
    sincosf(ang, &sn, &cs);
    size_t ib = (size_t)bs * (NHEADS*RD) + h*RD + 2*i;
    size_t ob = (((size_t)b*NHEADS + h)*SEQ + s)*DQK + HD + 2*i;
    float x1 = kr[ib], x2 = kr[ib+1];
    whi2(Kh, ob, x1*cs - x2*sn, x1*sn + x2*cs);
    x1 = qr[ib]; x2 = qr[ib+1];
    whi2(Qh, ob, x1*cs - x2*sn, x1*sn + x2*cs);
}

// ============== HMMA fp16 causal flash attention ============================
// CTA: 128 queries x full head. 8 warps, warp = 16 query rows.
// smem: Q [128x192], K double-buffered [64x192]x2, V [64x128]
#define AQH 0
#define AKB(buf) (49152 + (buf)*24576)
#define AVB 98304
#define ATTN_SMEM 114688

__global__ void __launch_bounds__(256, 1) attn_hmma(
    const __half* __restrict__ Qhg,
    const __half* __restrict__ Khg, const __half* __restrict__ Vhg,
    __half* __restrict__ cxh)
{
    extern __shared__ char smc[];
    const uint32_t sb = s2u(smc);
    const int b = blockIdx.z, h = blockIdx.y;
    const int q0 = blockIdx.x * 128;
    const int tid = threadIdx.x, w = tid >> 5, lane = tid & 31;
    const int ntiles = (q0 >> 6) + 2;

    const size_t hb = (size_t)(b*NHEADS + h) * SEQ;
    const __half* gQh = Qhg + (hb + q0) * DQK;
    const __half* gKh = Khg + hb * DQK;
    const __half* gVh = Vhg + hb * HD;

    auto ldQ = [&](uint32_t dst, const __half* g) {
        for (int i = tid; i < 128*24; i += 256) {
            int r = i / 24, c = i % 24;
            int cs = (c & ~7) | ((c ^ r) & 7);
            cpasync16(dst + (r*24 + cs)*16, g + r*192 + c*8);
        }
    };
    auto ldK = [&](uint32_t dst, const __half* g) {
        for (int i = tid; i < 64*24; i += 256) {
            int r = i / 24, c = i % 24;
            int cs = (c & ~7) | ((c ^ r) & 7);
            cpasync16(dst + (r*24 + cs)*16, g + r*192 + c*8);
        }
    };
    auto ldV = [&](uint32_t dst, const __half* g) {
        for (int i = tid; i < 64*16; i += 256) {
            int r = i / 16, c = i % 16;
            int cs = (c & ~7) | ((c ^ r) & 7);
            cpasync16(dst + (r*16 + cs)*16, g + r*128 + c*8);
        }
    };

    // prologue: group0 = {Q, K0, V0}, group1 = {K1}
    ldQ(sb + AQH, gQh);
    ldK(sb + AKB(0), gKh);
    ldV(sb + AVB,    gVh);
    asm volatile("cp.async.commit_group;" ::: "memory");
    ldK(sb + AKB(1), gKh + 64*192);
    asm volatile("cp.async.commit_group;" ::: "memory");

    float O[16][4];
#pragma unroll
    for (int t = 0; t < 16; t++)
#pragma unroll
        for (int j = 0; j < 4; j++) O[t][j] = 0.f;
    float m0r = -1e30f, m1r = -1e30f, l0 = 0.f, l1 = 0.f;

    const float scale = 0.07216878364870323f;  // 1/sqrt(192)
    const int lrow = lane & 15, lhi = lane >> 4;
    const int qr0 = q0 + w*16 + (lane >> 2);

    for (int i = 0; i < ntiles; i++) {
        const int k0 = i * 64;
        asm volatile("cp.async.wait_group 1;" ::: "memory");
        __syncthreads();

        const uint32_t kbh = sb + AKB(i & 1);

        float s[8][4];
#pragma unroll
        for (int t = 0; t < 8; t++)
#pragma unroll
            for (int j = 0; j < 4; j++) s[t][j] = 0.f;

        // ---- S = Q K^T ----
#pragma unroll
        for (int kc = 0; kc < 12; kc++) {
            uint32_t ah[4];
            {
                int r = w*16 + lrow;
                int c = kc*2 + lhi;
                int cs = (c & ~7) | ((c ^ r) & 7);
                ldsm4(ah, sb + AQH + (r*24 + cs)*16);
            }
#pragma unroll
            for (int kg = 0; kg < 4; kg++) {
                uint32_t bh[4];
                int r = kg*16 + lrow;
                int c = kc*2 + lhi;
                int cs = (c & ~7) | ((c ^ r) & 7);
                ldsm4(bh, kbh + (r*24 + cs)*16);
                mmahs(s[kg*2],   ah, bh[0], bh[2]);
                mmahs(s[kg*2+1], ah, bh[1], bh[3]);
            }
        }

        // ---- online softmax ----
        if (k0 + 63 > q0 + w*16) {
#pragma unroll
            for (int t = 0; t < 8; t++) {
                int kb = k0 + t*8 + ((lane & 3) << 1);
                s[t][0] = (kb     <= qr0    ) ? s[t][0]*scale : -1e30f;
                s[t][1] = (kb + 1 <= qr0    ) ? s[t][1]*scale : -1e30f;
                s[t][2] = (kb     <= qr0 + 8) ? s[t][2]*scale : -1e30f;
                s[t][3] = (kb + 1 <= qr0 + 8) ? s[t][3]*scale : -1e30f;
            }
        } else {
#pragma unroll
            for (int t = 0; t < 8; t++)
#pragma unroll
                for (int j = 0; j < 4; j++) s[t][j] *= scale;
        }

        float mx0 = -1e30f, mx1 = -1e30f;
#pragma unroll
        for (int t = 0; t < 8; t++) {
            mx0 = fmaxf(mx0, fmaxf(s[t][0], s[t][1]));
            mx1 = fmaxf(mx1, fmaxf(s[t][2], s[t][3]));
        }
        mx0 = fmaxf(mx0, __shfl_xor_sync(0xffffffffu, mx0, 1));
        mx0 = fmaxf(mx0, __shfl_xor_sync(0xffffffffu, mx0, 2));
        mx1 = fmaxf(mx1, __shfl_xor_sync(0xffffffffu, mx1, 1));
        mx1 = fmaxf(mx1, __shfl_xor_sync(0xffffffffu, mx1, 2));

        float mn0 = fmaxf(m0r, mx0), mn1 = fmaxf(m1r, mx1);
        float al0 = __expf(m0r - mn0), al1 = __expf(m1r - mn1);
        m0r = mn0; m1r = mn1;

        float sum0 = 0.f, sum1 = 0.f;
#pragma unroll
        for (int t = 0; t < 8; t++) {
            s[t][0] = __expf(s[t][0] - mn0); sum0 += s[t][0];
            s[t][1] = __expf(s[t][1] - mn0); sum0 += s[t][1];
            s[t][2] = __expf(s[t][2] - mn1); sum1 += s[t][2];
            s[t][3] = __expf(s[t][3] - mn1); sum1 += s[t][3];
        }
        l0 = l0*al0 + sum0;
        l1 = l1*al1 + sum1;
#pragma unroll
        for (int t = 0; t < 16; t++) {
            O[t][0] *= al0; O[t][1] *= al0;
            O[t][2] *= al1; O[t][3] *= al1;
        }

        // ---- O += P V ----
#pragma unroll
        for (int kc2 = 0; kc2 < 4; kc2++) {
            uint32_t pha[4];
            pha[0] = pack2h(s[kc2*2][0],   s[kc2*2][1]);
            pha[1] = pack2h(s[kc2*2][2],   s[kc2*2][3]);
            pha[2] = pack2h(s[kc2*2+1][0], s[kc2*2+1][1]);
            pha[3] = pack2h(s[kc2*2+1][2], s[kc2*2+1][3]);
#pragma unroll
            for (int dg = 0; dg < 8; dg++) {
                uint32_t vh[4];
                int r = kc2*16 + lrow;
                int c = dg*2 + lhi;
                int cs = (c & ~7) | ((c ^ r) & 7);
                ldsm4t(vh, sb + AVB + (r*16 + cs)*16);
                mmahs(O[dg*2],   pha, vh[0], vh[1]);
                mmahs(O[dg*2+1], pha, vh[2], vh[3]);
            }
        }
        __syncthreads();

        if (i + 1 < ntiles)
            ldV(sb + AVB, gVh + (size_t)(k0 + 64)*HD);
        asm volatile("cp.async.commit_group;" ::: "memory");
        if (i + 2 < ntiles)
            ldK(sb + AKB(i & 1), gKh + (size_t)(k0 + 128)*DQK);
        asm volatile("cp.async.commit_group;" ::: "memory");
    }

    l0 += __shfl_xor_sync(0xffffffffu, l0, 1);
    l0 += __shfl_xor_sync(0xffffffffu, l0, 2);
    l1 += __shfl_xor_sync(0xffffffffu, l1, 1);
    l1 += __shfl_xor_sync(0xffffffffu, l1, 2);
    float inv0 = 1.f / l0, inv1 = 1.f / l1;

#pragma unroll
    for (int t = 0; t < 16; t++) {
        int d = h*HD + t*8 + ((lane & 3) << 1);
        size_t ro0 = (size_t)(b*SEQ + qr0    ) * (NHEADS*HD) + d;
        size_t ro1 = (size_t)(b*SEQ + qr0 + 8) * (NHEADS*HD) + d;
        whi2(cxh, ro0, O[t][0]*inv0, O[t][1]*inv0);
        whi2(cxh, ro1, O[t][2]*inv1, O[t][3]*inv1);
    }
}

// ---------------- launch -----------------------------------------------------
static inline void gemm_m(const __half* Ah, const __half* Bh,
                          const float* bias, float* C, __half* Ch,
                          int M, int N, int K, int mode)
{
    gemm_hmma1<<<dim3(N/128, M/128), 256, GEMM_SMEM>>>(
        Ah, Bh, bias, C, Ch, M, N, K, mode);
}

extern "C" void kernel_launch(void* const* d_in, const int* in_sizes, int n_in,
                              void* d_out, int out_size)
{
    const float* x    = (const float*)d_in[0];
    const float* kvdw = (const float*)d_in[2];
    const float* kvdb = (const float*)d_in[3];
    const float* kuw  = (const float*)d_in[4];
    const float* kub  = (const float*)d_in[5];
    const float* vuw  = (const float*)d_in[6];
    const float* vub  = (const float*)d_in[7];
    const float* krw  = (const float*)d_in[8];
    const float* krb  = (const float*)d_in[9];
    const float* qdw  = (const float*)d_in[10];
    const float* qdb  = (const float*)d_in[11];
    const float* quw  = (const float*)d_in[12];
    const float* qub  = (const float*)d_in[13];
    const float* qrw  = (const float*)d_in[14];
    const float* qrb  = (const float*)d_in[15];
    const float* ow   = (const float*)d_in[16];
    const float* obv  = (const float*)d_in[17];
    float* out = (float*)d_out;

    float *kr, *qru;
    cudaGetSymbolAddress((void**)&kr,   g_kr);
    cudaGetSymbolAddress((void**)&qru,  g_qru);

    __half *Qh,*Kh,*Vh;
    cudaGetSymbolAddress((void**)&Qh, g_Qh);
    cudaGetSymbolAddress((void**)&Kh, g_Kh);
    cudaGetSymbolAddress((void**)&Vh, g_Vh);

    __half *xh,*kvch,*qlh,*cxh;
    __half *kvdwh,*kuwh,*vuwh,*krwh,*qdwh,*quwh,*qrwh,*owh;
    cudaGetSymbolAddress((void**)&xh, g_xh);
    cudaGetSymbolAddress((void**)&kvch, g_kvch);
    cudaGetSymbolAddress((void**)&qlh, g_qlh);
    cudaGetSymbolAddress((void**)&cxh, g_cxh);
    cudaGetSymbolAddress((void**)&kvdwh, g_kvdwh);
    cudaGetSymbolAddress((void**)&kuwh, g_kuwh);
    cudaGetSymbolAddress((void**)&vuwh, g_vuwh);
    cudaGetSymbolAddress((void**)&krwh, g_krwh);
    cudaGetSymbolAddress((void**)&qdwh, g_qdwh);
    cudaGetSymbolAddress((void**)&quwh, g_quwh);
    cudaGetSymbolAddress((void**)&qrwh, g_qrwh);
    cudaGetSymbolAddress((void**)&owh, g_owh);

    cudaFuncSetAttribute(gemm_hmma1, cudaFuncAttributeMaxDynamicSharedMemorySize, GEMM_SMEM);
    cudaFuncSetAttribute(attn_hmma, cudaFuncAttributeMaxDynamicSharedMemorySize, ATTN_SMEM);

    dim3 tb(32, 8);

    // weight transpose: src [K][N] -> [N][K] fp16
    transpose_half<<<dim3(KVC/32,       HIDDEN/32), tb>>>(kvdw, kvdwh, HIDDEN, KVC);
    transpose_half<<<dim3(NHEADS*HD/32, KVC/32),    tb>>>(kuw,  kuwh,  KVC, NHEADS*HD);
    transpose_half<<<dim3(NHEADS*HD/32, KVC/32),    tb>>>(vuw,  vuwh,  KVC, NHEADS*HD);
    transpose_half<<<dim3(NHEADS*RD/32, KVC/32),    tb>>>(krw,  krwh,  KVC, NHEADS*RD);
    transpose_half<<<dim3(QC/32,        HIDDEN/32), tb>>>(qdw,  qdwh,  HIDDEN, QC);
    transpose_half<<<dim3(NHEADS*HD/32, QC/32),     tb>>>(quw,  quwh,  QC, NHEADS*HD);
    transpose_half<<<dim3(NHEADS*RD/32, QC/32),     tb>>>(qrw,  qrwh,  QC, NHEADS*RD);
    transpose_half<<<dim3(HIDDEN/32,    NHEADS*HD/32), tb>>>(ow, owh, NHEADS*HD, HIDDEN);

    // x convert
    conv_half<<<ROWS*HIDDEN/4/256, 256>>>(x, xh, ROWS*HIDDEN);

    // kv path
    gemm_m(xh,   kvdwh, kvdb, nullptr, kvch, ROWS, KVC,       HIDDEN, 1);
    gemm_m(kvch, kuwh,  kub,  nullptr, Kh,   ROWS, NHEADS*HD, KVC,    2);
    gemm_m(kvch, vuwh,  vub,  nullptr, Vh,   ROWS, NHEADS*HD, KVC,    3);
    gemm_m(kvch, krwh,  krb,  kr, nullptr,   ROWS, NHEADS*RD, KVC,    0);

    // q path
    gemm_m(xh,  qdwh, qdb, nullptr, qlh, ROWS, QC,        HIDDEN, 1);
    gemm_m(qlh, quwh, qub, nullptr, Qh,  ROWS, NHEADS*HD, QC,     2);
    gemm_m(qlh, qrwh, qrb, qru, nullptr, ROWS, NHEADS*RD, QC,     0);

    // rope into last 64 dims
    rope_pack<<<ROWS*NHEADS*(RD/2)/256, 256>>>(kr, qru, Kh, Qh);

    // attention (fp16 HMMA)
    attn_hmma<<<dim3(SEQ/128, NHEADS, BATCH), 256, ATTN_SMEM>>>(Qh, Kh, Vh, cxh);

    // output projection
    gemm_m(cxh, owh, obv, out, nullptr, ROWS, HIDDEN, NHEADS*HD, 0);
}

// round 9
// speedup vs baseline: 6.5447x; 1.0398x over previous
#include <cuda_runtime.h>
#include <cuda_fp16.h>
#include <cstdint>
#include <math.h>

#define HIDDEN 2048
#define NHEADS 16
#define HD 128
#define RD 64
#define DQK 192
#define KVC 512
#define QC 1536
#define BATCH 2
#define SEQ 2048
#define ROWS (BATCH*SEQ)   // 4096

// ---------------- scratch (static device memory; no allocation allowed) -----
__device__ float g_kr [ROWS*NHEADS*RD];
__device__ float g_qru[ROWS*NHEADS*RD];

// attention operands [B,H,S,*], fp16
__device__ __half g_Qh[(size_t)BATCH*NHEADS*SEQ*DQK];
__device__ __half g_Kh[(size_t)BATCH*NHEADS*SEQ*DQK];
__device__ __half g_Vh[(size_t)BATCH*NHEADS*SEQ*HD];

// fp16 activations
__device__ __half g_xh [ROWS*HIDDEN];
__device__ __half g_kvch[ROWS*KVC];
__device__ __half g_qlh [ROWS*QC];
__device__ __half g_cxh [ROWS*NHEADS*HD];

// weights transposed to [N][K], fp16
__device__ __half g_kvdwh[KVC*HIDDEN];
__device__ __half g_kuwh [NHEADS*HD*KVC];
__device__ __half g_vuwh [NHEADS*HD*KVC];
__device__ __half g_krwh [NHEADS*RD*KVC];
__device__ __half g_qdwh [QC*HIDDEN];
__device__ __half g_quwh [NHEADS*HD*QC];
__device__ __half g_qrwh [NHEADS*RD*QC];
__device__ __half g_owh  [HIDDEN*NHEADS*HD];

// ======================= mma / ldmatrix helpers =============================
__device__ __forceinline__ uint32_t s2u(const void* p) {
    return (uint32_t)__cvta_generic_to_shared(p);
}
__device__ __forceinline__ void ldsm4(uint32_t* r, uint32_t addr) {
    asm volatile("ldmatrix.sync.aligned.m8n8.x4.shared.b16 {%0,%1,%2,%3}, [%4];"
                 : "=r"(r[0]), "=r"(r[1]), "=r"(r[2]), "=r"(r[3]) : "r"(addr));
}
__device__ __forceinline__ void ldsm4t(uint32_t* r, uint32_t addr) {
    asm volatile("ldmatrix.sync.aligned.m8n8.x4.trans.shared.b16 {%0,%1,%2,%3}, [%4];"
                 : "=r"(r[0]), "=r"(r[1]), "=r"(r[2]), "=r"(r[3]) : "r"(addr));
}
__device__ __forceinline__ void mmah(float* c, const uint32_t* a, const uint32_t* b) {
    asm volatile(
        "mma.sync.aligned.m16n8k16.row.col.f32.f16.f16.f32 "
        "{%0,%1,%2,%3}, {%4,%5,%6,%7}, {%8,%9}, {%0,%1,%2,%3};"
        : "+f"(c[0]), "+f"(c[1]), "+f"(c[2]), "+f"(c[3])
        : "r"(a[0]), "r"(a[1]), "r"(a[2]), "r"(a[3]), "r"(b[0]), "r"(b[1]));
}
__device__ __forceinline__ void mmahs(float* c, const uint32_t* a, uint32_t b0, uint32_t b1) {
    asm volatile(
        "mma.sync.aligned.m16n8k16.row.col.f32.f16.f16.f32 "
        "{%0,%1,%2,%3}, {%4,%5,%6,%7}, {%8,%9}, {%0,%1,%2,%3};"
        : "+f"(c[0]), "+f"(c[1]), "+f"(c[2]), "+f"(c[3])
        : "r"(a[0]), "r"(a[1]), "r"(a[2]), "r"(a[3]), "r"(b0), "r"(b1));
}
__device__ __forceinline__ void cpasync16(uint32_t dst, const void* src) {
    asm volatile("cp.async.cg.shared.global [%0], [%1], 16;"
                 :: "r"(dst), "l"(src) : "memory");
}
__device__ __forceinline__ uint32_t pack2h(float x, float y) {
    __half2 t = __floats2half2_rn(x, y);
    return *(uint32_t*)&t;
}
__device__ __forceinline__ void whi2(__half* __restrict__ H, size_t o, float a, float b) {
    *(__half2*)&H[o] = __floats2half2_rn(a, b);
}

// ======================= fp32 -> fp16 convert ===============================
__global__ void conv_half(const float* __restrict__ s, __half* __restrict__ h, int n)
{
    int i = (blockIdx.x * blockDim.x + threadIdx.x) * 4;
    if (i >= n) return;
    float4 v = *(const float4*)(s + i);
    *(__half2*)(h + i)     = __floats2half2_rn(v.x, v.y);
    *(__half2*)(h + i + 2) = __floats2half2_rn(v.z, v.w);
}

// ======= fused transpose: 8 matrices, src[K][N] fp32 -> dst [N][K] fp16 =====
struct TSpec { const float* src; __half* dst; int K; int N; int blk0; };
struct TTab  { TSpec e[8]; };

__global__ void transpose_all(TTab tab)
{
    __shared__ float t[32][33];
    int b = blockIdx.x;
    // find entry (8 entries, unrolled scan)
    int ei = 0;
#pragma unroll
    for (int i = 1; i < 8; i++)
        if (b >= tab.e[i].blk0) ei = i;
    const TSpec sp = tab.e[ei];
    int lb = b - sp.blk0;
    int nbx = sp.N >> 5;
    int nb = (lb % nbx) * 32;
    int kb = (lb / nbx) * 32;

    int tx = threadIdx.x, ty = threadIdx.y;    // 32 x 8
#pragma unroll
    for (int i = 0; i < 32; i += 8)
        t[ty + i][tx] = sp.src[(size_t)(kb + ty + i) * sp.N + nb + tx];
    __syncthreads();
#pragma unroll
    for (int i = 0; i < 32; i += 8)
        sp.dst[(size_t)(nb + ty + i) * sp.K + kb + tx] = __float2half_rn(t[tx][ty + i]);
}

// ======================= HMMA fp16 GEMM =====================================
// C[M,N] = Ah[M,K] @ Bh[N,K]^T + bias.  CTA 128x128, BK=32, 8 warps,
// 3-stage cp.async, 2 CTAs/SM.  Epilogue modes:
//   0 = fp32 C;  1 = fp16 [M,N];  2 = fp16 [B,H,S,192];  3 = fp16 [B,H,S,128]
#define BKP 40
#define MAT_SMEM (128*BKP*2)      // 10240
#define STG_SMEM (2*MAT_SMEM)     // 20480
#define GEMM_SMEM (3*STG_SMEM)    // 61440

__global__ void __launch_bounds__(256, 2) gemm_hmma1(
    const __half* __restrict__ Ah, const __half* __restrict__ Bh,
    const float* __restrict__ bias, float* __restrict__ C,
    __half* __restrict__ Ch,
    int M, int N, int K, int mode)
{
    extern __shared__ char dsm[];
    const uint32_t sbase = s2u(dsm);

    const int tid  = threadIdx.x;
    const int warp = tid >> 5, lane = tid & 31;
    const int wm = (warp & 3) * 32;
    const int wn = (warp >> 2) * 64;
    const int m0 = blockIdx.y * 128, n0 = blockIdx.x * 128;

    const int ldrow = tid >> 2;
    const int ldchk = (tid & 3) * 8;

    const __half* gM[2] = { Ah + (size_t)m0 * K, Bh + (size_t)n0 * K };

    const int nK = K >> 5;

    const int a_r  = lane & 15;
    const int a_c8 = (lane >> 4) << 3;
    const int b_r  = (lane & 7) + ((lane >> 4) << 3);
    const int b_c8 = (lane & 8) ? 8 : 0;

    float acc[2][8][4];
#pragma unroll
    for (int mt = 0; mt < 2; mt++)
#pragma unroll
        for (int nt = 0; nt < 8; nt++)
#pragma unroll
            for (int q = 0; q < 4; q++) acc[mt][nt][q] = 0.f;

    auto load_stage = [&](int stg, int kb) {
        uint32_t sb = sbase + stg * STG_SMEM;
#pragma unroll
        for (int mat = 0; mat < 2; mat++) {
            const __half* g = gM[mat];
#pragma unroll
            for (int j = 0; j < 2; j++) {
                int row = ldrow + j * 64;
                cpasync16(sb + mat * MAT_SMEM + (row * BKP + ldchk) * 2,
                          g + (size_t)row * K + kb + ldchk);
            }
        }
        asm volatile("cp.async.commit_group;" ::: "memory");
    };

    load_stage(0, 0);
    load_stage(1, 32);

    int cur = 0, nxt = 2;
    for (int i = 0; i < nK; i++) {
        if (i + 1 < nK) asm volatile("cp.async.wait_group 1;" ::: "memory");
        else            asm volatile("cp.async.wait_group 0;" ::: "memory");
        __syncthreads();
        if (i + 2 < nK) load_stage(nxt, (i + 2) * 32);

        const uint32_t sAh = sbase + cur * STG_SMEM;
        const uint32_t sBh = sAh + MAT_SMEM;

#pragma unroll
        for (int kk = 0; kk < 32; kk += 16) {
            uint32_t ah[2][4], bh[4][4];
#pragma unroll
            for (int mt = 0; mt < 2; mt++) {
                uint32_t off = ((wm + mt * 16 + a_r) * BKP + kk + a_c8) * 2;
                ldsm4(ah[mt], sAh + off);
            }
#pragma unroll
            for (int p = 0; p < 4; p++) {
                uint32_t off = ((wn + p * 16 + b_r) * BKP + kk + b_c8) * 2;
                ldsm4(bh[p], sBh + off);
            }
#pragma unroll
            for (int mt = 0; mt < 2; mt++)
#pragma unroll
                for (int nt = 0; nt < 8; nt++)
                    mmah(acc[mt][nt], ah[mt], &bh[nt >> 1][(nt & 1) * 2]);
        }
        cur = (cur == 2) ? 0 : cur + 1;
        nxt = (nxt == 2) ? 0 : nxt + 1;
    }

    // ---- epilogue ----
    const int er = lane >> 2, ec = (lane & 3) * 2;
#pragma unroll
    for (int mt = 0; mt < 2; mt++) {
#pragma unroll
        for (int nt = 0; nt < 8; nt++) {
            int col = n0 + wn + nt * 8 + ec;
            float b0 = bias[col], b1 = bias[col + 1];
            int r0 = m0 + wm + mt * 16 + er;
            int r1 = r0 + 8;
            float p0 = acc[mt][nt][0] + b0, p1 = acc[mt][nt][1] + b1;
            float p2 = acc[mt][nt][2] + b0, p3 = acc[mt][nt][3] + b1;
            if (mode == 0) {
                *(float2*)&C[(size_t)r0 * N + col] = make_float2(p0, p1);
                *(float2*)&C[(size_t)r1 * N + col] = make_float2(p2, p3);
            } else if (mode == 1) {
                whi2(Ch, (size_t)r0 * N + col, p0, p1);
                whi2(Ch, (size_t)r1 * N + col, p2, p3);
            } else {
                int hh = col >> 7, d = col & 127;
                int stride = (mode == 2) ? DQK : HD;
                size_t o0 = (((size_t)(r0 >> 11) * NHEADS + hh) * SEQ + (r0 & 2047)) * stride + d;
                size_t o1 = (((size_t)(r1 >> 11) * NHEADS + hh) * SEQ + (r1 & 2047)) * stride + d;
                whi2(Ch, o0, p0, p1);
                whi2(Ch, o1, p2, p3);
            }
        }
    }
}

// ------- RoPE into last 64 dims of K/Q --------------------------------------
__global__ void rope_pack(const float* __restrict__ kr, const float* __restrict__ qr,
                          __half* __restrict__ Kh, __half* __restrict__ Qh)
{
    int idx = blockIdx.x * blockDim.x + threadIdx.x;
    if (idx >= ROWS*NHEADS*(RD/2)) return;
    int i  = idx & 31;
    int h  = (idx >> 5) & 15;
    int bs = idx >> 9;
    int b  = bs >> 11;
    int s  = bs & 2047;
    float inv_freq = powf(10000.f, -(float)(2*i) / 64.f);
    float ang = (float)s * inv_freq;
    float sn, cs;
    sincosf(ang, &sn, &cs);
    size_t ib = (size_t)bs * (NHEADS*RD) + h*RD + 2*i;
    size_t ob = (((size_t)b*NHEADS + h)*SEQ + s)*DQK + HD + 2*i;
    float x1 = kr[ib], x2 = kr[ib+1];
    whi2(Kh, ob, x1*cs - x2*sn, x1*sn + x2*cs);
    x1 = qr[ib]; x2 = qr[ib+1];
    whi2(Qh, ob, x1*cs - x2*sn, x1*sn + x2*cs);
}

// ============== HMMA fp16 causal flash attention ============================
// CTA: 128 queries x full head. 8 warps, warp = 16 query rows.
// smem: Q [128x192], K double-buffered [64x192]x2, V [64x128]
#define AQH 0
#define AKB(buf) (49152 + (buf)*24576)
#define AVB 98304
#define ATTN_SMEM 114688

__global__ void __launch_bounds__(256, 1) attn_hmma(
    const __half* __restrict__ Qhg,
    const __half* __restrict__ Khg, const __half* __restrict__ Vhg,
    __half* __restrict__ cxh)
{
    extern __shared__ char smc[];
    const uint32_t sb = s2u(smc);
    const int b = blockIdx.z, h = blockIdx.y;
    const int q0 = blockIdx.x * 128;
    const int tid = threadIdx.x, w = tid >> 5, lane = tid & 31;
    const int ntiles = (q0 >> 6) + 2;

    const size_t hb = (size_t)(b*NHEADS + h) * SEQ;
    const __half* gQh = Qhg + (hb + q0) * DQK;
    const __half* gKh = Khg + hb * DQK;
    const __half* gVh = Vhg + hb * HD;

    auto ldQ = [&](uint32_t dst, const __half* g) {
        for (int i = tid; i < 128*24; i += 256) {
            int r = i / 24, c = i % 24;
            int cs = (c & ~7) | ((c ^ r) & 7);
            cpasync16(dst + (r*24 + cs)*16, g + r*192 + c*8);
        }
    };
    auto ldK = [&](uint32_t dst, const __half* g) {
        for (int i = tid; i < 64*24; i += 256) {
            int r = i / 24, c = i % 24;
            int cs = (c & ~7) | ((c ^ r) & 7);
            cpasync16(dst + (r*24 + cs)*16, g + r*192 + c*8);
        }
    };
    auto ldV = [&](uint32_t dst, const __half* g) {
        for (int i = tid; i < 64*16; i += 256) {
            int r = i / 16, c = i % 16;
            int cs = (c & ~7) | ((c ^ r) & 7);
            cpasync16(dst + (r*16 + cs)*16, g + r*128 + c*8);
        }
    };

    // prologue: group0 = {Q, K0, V0}, group1 = {K1}
    ldQ(sb + AQH, gQh);
    ldK(sb + AKB(0), gKh);
    ldV(sb + AVB,    gVh);
    asm volatile("cp.async.commit_group;" ::: "memory");
    ldK(sb + AKB(1), gKh + 64*192);
    asm volatile("cp.async.commit_group;" ::: "memory");

    float O[16][4];
#pragma unroll
    for (int t = 0; t < 16; t++)
#pragma unroll
        for (int j = 0; j < 4; j++) O[t][j] = 0.f;
    float m0r = -1e30f, m1r = -1e30f, l0 = 0.f, l1 = 0.f;

    const float scale = 0.07216878364870323f;  // 1/sqrt(192)
    const int lrow = lane & 15, lhi = lane >> 4;
    const int qr0 = q0 + w*16 + (lane >> 2);

    for (int i = 0; i < ntiles; i++) {
        const int k0 = i * 64;
        asm volatile("cp.async.wait_group 1;" ::: "memory");
        __syncthreads();

        const uint32_t kbh = sb + AKB(i & 1);

        float s[8][4];
#pragma unroll
        for (int t = 0; t < 8; t++)
#pragma unroll
            for (int j = 0; j < 4; j++) s[t][j] = 0.f;

        // ---- S = Q K^T ----
#pragma unroll
        for (int kc = 0; kc < 12; kc++) {
            uint32_t ah[4];
            {
                int r = w*16 + lrow;
                int c = kc*2 + lhi;
                int cs = (c & ~7) | ((c ^ r) & 7);
                ldsm4(ah, sb + AQH + (r*24 + cs)*16);
            }
#pragma unroll
            for (int kg = 0; kg < 4; kg++) {
                uint32_t bh[4];
                int r = kg*16 + lrow;
                int c = kc*2 + lhi;
                int cs = (c & ~7) | ((c ^ r) & 7);
                ldsm4(bh, kbh + (r*24 + cs)*16);
                mmahs(s[kg*2],   ah, bh[0], bh[2]);
                mmahs(s[kg*2+1], ah, bh[1], bh[3]);
            }
        }

        // ---- online softmax ----
        if (k0 + 63 > q0 + w*16) {
#pragma unroll
            for (int t = 0; t < 8; t++) {
                int kb = k0 + t*8 + ((lane & 3) << 1);
                s[t][0] = (kb     <= qr0    ) ? s[t][0]*scale : -1e30f;
                s[t][1] = (kb + 1 <= qr0    ) ? s[t][1]*scale : -1e30f;
                s[t][2] = (kb     <= qr0 + 8) ? s[t][2]*scale : -1e30f;
                s[t][3] = (kb + 1 <= qr0 + 8) ? s[t][3]*scale : -1e30f;
            }
        } else {
#pragma unroll
            for (int t = 0; t < 8; t++)
#pragma unroll
                for (int j = 0; j < 4; j++) s[t][j] *= scale;
        }

        float mx0 = -1e30f, mx1 = -1e30f;
#pragma unroll
        for (int t = 0; t < 8; t++) {
            mx0 = fmaxf(mx0, fmaxf(s[t][0], s[t][1]));
            mx1 = fmaxf(mx1, fmaxf(s[t][2], s[t][3]));
        }
        mx0 = fmaxf(mx0, __shfl_xor_sync(0xffffffffu, mx0, 1));
        mx0 = fmaxf(mx0, __shfl_xor_sync(0xffffffffu, mx0, 2));
        mx1 = fmaxf(mx1, __shfl_xor_sync(0xffffffffu, mx1, 1));
        mx1 = fmaxf(mx1, __shfl_xor_sync(0xffffffffu, mx1, 2));

        float mn0 = fmaxf(m0r, mx0), mn1 = fmaxf(m1r, mx1);
        float al0 = __expf(m0r - mn0), al1 = __expf(m1r - mn1);
        m0r = mn0; m1r = mn1;

        float sum0 = 0.f, sum1 = 0.f;
#pragma unroll
        for (int t = 0; t < 8; t++) {
            s[t][0] = __expf(s[t][0] - mn0); sum0 += s[t][0];
            s[t][1] = __expf(s[t][1] - mn0); sum0 += s[t][1];
            s[t][2] = __expf(s[t][2] - mn1); sum1 += s[t][2];
            s[t][3] = __expf(s[t][3] - mn1); sum1 += s[t][3];
        }
        l0 = l0*al0 + sum0;
        l1 = l1*al1 + sum1;
#pragma unroll
        for (int t = 0; t < 16; t++) {
            O[t][0] *= al0; O[t][1] *= al0;
            O[t][2] *= al1; O[t][3] *= al1;
        }

        // ---- O += P V ----
#pragma unroll
        for (int kc2 = 0; kc2 < 4; kc2++) {
            uint32_t pha[4];
            pha[0] = pack2h(s[kc2*2][0],   s[kc2*2][1]);
            pha[1] = pack2h(s[kc2*2][2],   s[kc2*2][3]);
            pha[2] = pack2h(s[kc2*2+1][0], s[kc2*2+1][1]);
            pha[3] = pack2h(s[kc2*2+1][2], s[kc2*2+1][3]);
#pragma unroll
            for (int dg = 0; dg < 8; dg++) {
                uint32_t vh[4];
                int r = kc2*16 + lrow;
                int c = dg*2 + lhi;
                int cs = (c & ~7) | ((c ^ r) & 7);
                ldsm4t(vh, sb + AVB + (r*16 + cs)*16);
                mmahs(O[dg*2],   pha, vh[0], vh[1]);
                mmahs(O[dg*2+1], pha, vh[2], vh[3]);
            }
        }
        __syncthreads();

        if (i + 1 < ntiles)
            ldV(sb + AVB, gVh + (size_t)(k0 + 64)*HD);
        asm volatile("cp.async.commit_group;" ::: "memory");
        if (i + 2 < ntiles)
            ldK(sb + AKB(i & 1), gKh + (size_t)(k0 + 128)*DQK);
        asm volatile("cp.async.commit_group;" ::: "memory");
    }

    l0 += __shfl_xor_sync(0xffffffffu, l0, 1);
    l0 += __shfl_xor_sync(0xffffffffu, l0, 2);
    l1 += __shfl_xor_sync(0xffffffffu, l1, 1);
    l1 += __shfl_xor_sync(0xffffffffu, l1, 2);
    float inv0 = 1.f / l0, inv1 = 1.f / l1;

#pragma unroll
    for (int t = 0; t < 16; t++) {
        int d = h*HD + t*8 + ((lane & 3) << 1);
        size_t ro0 = (size_t)(b*SEQ + qr0    ) * (NHEADS*HD) + d;
        size_t ro1 = (size_t)(b*SEQ + qr0 + 8) * (NHEADS*HD) + d;
        whi2(cxh, ro0, O[t][0]*inv0, O[t][1]*inv0);
        whi2(cxh, ro1, O[t][2]*inv1, O[t][3]*inv1);
    }
}

// ---------------- launch -----------------------------------------------------
static inline void gemm_m(const __half* Ah, const __half* Bh,
                          const float* bias, float* C, __half* Ch,
                          int M, int N, int K, int mode)
{
    gemm_hmma1<<<dim3(N/128, M/128), 256, GEMM_SMEM>>>(
        Ah, Bh, bias, C, Ch, M, N, K, mode);
}

extern "C" void kernel_launch(void* const* d_in, const int* in_sizes, int n_in,
                              void* d_out, int out_size)
{
    const float* x    = (const float*)d_in[0];
    const float* kvdw = (const float*)d_in[2];
    const float* kvdb = (const float*)d_in[3];
    const float* kuw  = (const float*)d_in[4];
    const float* kub  = (const float*)d_in[5];
    const float* vuw  = (const float*)d_in[6];
    const float* vub  = (const float*)d_in[7];
    const float* krw  = (const float*)d_in[8];
    const float* krb  = (const float*)d_in[9];
    const float* qdw  = (const float*)d_in[10];
    const float* qdb  = (const float*)d_in[11];
    const float* quw  = (const float*)d_in[12];
    const float* qub  = (const float*)d_in[13];
    const float* qrw  = (const float*)d_in[14];
    const float* qrb  = (const float*)d_in[15];
    const float* ow   = (const float*)d_in[16];
    const float* obv  = (const float*)d_in[17];
    float* out = (float*)d_out;

    float *kr, *qru;
    cudaGetSymbolAddress((void**)&kr,   g_kr);
    cudaGetSymbolAddress((void**)&qru,  g_qru);

    __half *Qh,*Kh,*Vh;
    cudaGetSymbolAddress((void**)&Qh, g_Qh);
    cudaGetSymbolAddress((void**)&Kh, g_Kh);
    cudaGetSymbolAddress((void**)&Vh, g_Vh);

    __half *xh,*kvch,*qlh,*cxh;
    __half *kvdwh,*kuwh,*vuwh,*krwh,*qdwh,*quwh,*qrwh,*owh;
    cudaGetSymbolAddress((void**)&xh, g_xh);
    cudaGetSymbolAddress((void**)&kvch, g_kvch);
    cudaGetSymbolAddress((void**)&qlh, g_qlh);
    cudaGetSymbolAddress((void**)&cxh, g_cxh);
    cudaGetSymbolAddress((void**)&kvdwh, g_kvdwh);
    cudaGetSymbolAddress((void**)&kuwh, g_kuwh);
    cudaGetSymbolAddress((void**)&vuwh, g_vuwh);
    cudaGetSymbolAddress((void**)&krwh, g_krwh);
    cudaGetSymbolAddress((void**)&qdwh, g_qdwh);
    cudaGetSymbolAddress((void**)&quwh, g_quwh);
    cudaGetSymbolAddress((void**)&qrwh, g_qrwh);
    cudaGetSymbolAddress((void**)&owh, g_owh);

    cudaFuncSetAttribute(gemm_hmma1, cudaFuncAttributeMaxDynamicSharedMemorySize, GEMM_SMEM);
    cudaFuncSetAttribute(attn_hmma, cudaFuncAttributeMaxDynamicSharedMemorySize, ATTN_SMEM);

    // fused weight transpose (8 matrices in one launch)
    {
        TTab tab;
        auto set = [&](int i, const float* s, __half* d, int K, int N, int blk0) {
            tab.e[i].src = s; tab.e[i].dst = d;
            tab.e[i].K = K; tab.e[i].N = N; tab.e[i].blk0 = blk0;
        };
        int b = 0;
        set(0, kvdw, kvdwh, HIDDEN, KVC, b);       b += (KVC/32)*(HIDDEN/32);        // 1024
        set(1, kuw,  kuwh,  KVC, NHEADS*HD, b);    b += (NHEADS*HD/32)*(KVC/32);     // 1024
        set(2, vuw,  vuwh,  KVC, NHEADS*HD, b);    b += (NHEADS*HD/32)*(KVC/32);     // 1024
        set(3, krw,  krwh,  KVC, NHEADS*RD, b);    b += (NHEADS*RD/32)*(KVC/32);     // 512
        set(4, qdw,  qdwh,  HIDDEN, QC, b);        b += (QC/32)*(HIDDEN/32);         // 3072
        set(5, quw,  quwh,  QC, NHEADS*HD, b);     b += (NHEADS*HD/32)*(QC/32);      // 3072
        set(6, qrw,  qrwh,  QC, NHEADS*RD, b);     b += (NHEADS*RD/32)*(QC/32);      // 1536
        set(7, ow,   owh,   NHEADS*HD, HIDDEN, b); b += (HIDDEN/32)*(NHEADS*HD/32);  // 4096
        transpose_all<<<b, dim3(32, 8)>>>(tab);
    }

    // x convert
    conv_half<<<ROWS*HIDDEN/4/256, 256>>>(x, xh, ROWS*HIDDEN);

    // kv path
    gemm_m(xh,   kvdwh, kvdb, nullptr, kvch, ROWS, KVC,       HIDDEN, 1);
    gemm_m(kvch, kuwh,  kub,  nullptr, Kh,   ROWS, NHEADS*HD, KVC,    2);
    gemm_m(kvch, vuwh,  vub,  nullptr, Vh,   ROWS, NHEADS*HD, KVC,    3);
    gemm_m(kvch, krwh,  krb,  kr, nullptr,   ROWS, NHEADS*RD, KVC,    0);

    // q path
    gemm_m(xh,  qdwh, qdb, nullptr, qlh, ROWS, QC,        HIDDEN, 1);
    gemm_m(qlh, quwh, qub, nullptr, Qh,  ROWS, NHEADS*HD, QC,     2);
    gemm_m(qlh, qrwh, qrb, qru, nullptr, ROWS, NHEADS*RD, QC,     0);

    // rope into last 64 dims
    rope_pack<<<ROWS*NHEADS*(RD/2)/256, 256>>>(kr, qru, Kh, Qh);

    // attention (fp16 HMMA)
    attn_hmma<<<dim3(SEQ/128, NHEADS, BATCH), 256, ATTN_SMEM>>>(Qh, Kh, Vh, cxh);

    // output projection
    gemm_m(cxh, owh, obv, out, nullptr, ROWS, HIDDEN, NHEADS*HD, 0);
}

// round 10
// speedup vs baseline: 6.6780x; 1.0204x over previous
#include <cuda_runtime.h>
#include <cuda_fp16.h>
#include <cstdint>
#include <math.h>

#define HIDDEN 2048
#define NHEADS 16
#define HD 128
#define RD 64
#define DQK 192
#define KVC 512
#define QC 1536
#define BATCH 2
#define SEQ 2048
#define ROWS (BATCH*SEQ)   // 4096

// ---------------- scratch (static device memory; no allocation allowed) -----
__device__ float g_kr [ROWS*NHEADS*RD];
__device__ float g_qru[ROWS*NHEADS*RD];

// attention operands [B,H,S,*], fp16
__device__ __half g_Qh[(size_t)BATCH*NHEADS*SEQ*DQK];
__device__ __half g_Kh[(size_t)BATCH*NHEADS*SEQ*DQK];
__device__ __half g_Vh[(size_t)BATCH*NHEADS*SEQ*HD];

// fp16 activations
__device__ __half g_xh [ROWS*HIDDEN];
__device__ __half g_kvch[ROWS*KVC];
__device__ __half g_qlh [ROWS*QC];
__device__ __half g_cxh [ROWS*NHEADS*HD];

// weights transposed to [N][K], fp16
__device__ __half g_kvdwh[KVC*HIDDEN];
__device__ __half g_kuwh [NHEADS*HD*KVC];
__device__ __half g_vuwh [NHEADS*HD*KVC];
__device__ __half g_krwh [NHEADS*RD*KVC];
__device__ __half g_qdwh [QC*HIDDEN];
__device__ __half g_quwh [NHEADS*HD*QC];
__device__ __half g_qrwh [NHEADS*RD*QC];
__device__ __half g_owh  [HIDDEN*NHEADS*HD];

// ======================= mma / ldmatrix helpers =============================
__device__ __forceinline__ uint32_t s2u(const void* p) {
    return (uint32_t)__cvta_generic_to_shared(p);
}
__device__ __forceinline__ void ldsm4(uint32_t* r, uint32_t addr) {
    asm volatile("ldmatrix.sync.aligned.m8n8.x4.shared.b16 {%0,%1,%2,%3}, [%4];"
                 : "=r"(r[0]), "=r"(r[1]), "=r"(r[2]), "=r"(r[3]) : "r"(addr));
}
__device__ __forceinline__ void ldsm4t(uint32_t* r, uint32_t addr) {
    asm volatile("ldmatrix.sync.aligned.m8n8.x4.trans.shared.b16 {%0,%1,%2,%3}, [%4];"
                 : "=r"(r[0]), "=r"(r[1]), "=r"(r[2]), "=r"(r[3]) : "r"(addr));
}
__device__ __forceinline__ void mmah(float* c, const uint32_t* a, const uint32_t* b) {
    asm volatile(
        "mma.sync.aligned.m16n8k16.row.col.f32.f16.f16.f32 "
        "{%0,%1,%2,%3}, {%4,%5,%6,%7}, {%8,%9}, {%0,%1,%2,%3};"
        : "+f"(c[0]), "+f"(c[1]), "+f"(c[2]), "+f"(c[3])
        : "r"(a[0]), "r"(a[1]), "r"(a[2]), "r"(a[3]), "r"(b[0]), "r"(b[1]));
}
__device__ __forceinline__ void mmahs(float* c, const uint32_t* a, uint32_t b0, uint32_t b1) {
    asm volatile(
        "mma.sync.aligned.m16n8k16.row.col.f32.f16.f16.f32 "
        "{%0,%1,%2,%3}, {%4,%5,%6,%7}, {%8,%9}, {%0,%1,%2,%3};"
        : "+f"(c[0]), "+f"(c[1]), "+f"(c[2]), "+f"(c[3])
        : "r"(a[0]), "r"(a[1]), "r"(a[2]), "r"(a[3]), "r"(b0), "r"(b1));
}
__device__ __forceinline__ void cpasync16(uint32_t dst, const void* src) {
    asm volatile("cp.async.cg.shared.global [%0], [%1], 16;"
                 :: "r"(dst), "l"(src) : "memory");
}
__device__ __forceinline__ uint32_t pack2h(float x, float y) {
    __half2 t = __floats2half2_rn(x, y);
    return *(uint32_t*)&t;
}
__device__ __forceinline__ void whi2(__half* __restrict__ H, size_t o, float a, float b) {
    *(__half2*)&H[o] = __floats2half2_rn(a, b);
}

// ======================= fp32 -> fp16 convert ===============================
__global__ void conv_half(const float* __restrict__ s, __half* __restrict__ h, int n)
{
    int i = (blockIdx.x * blockDim.x + threadIdx.x) * 4;
    if (i >= n) return;
    float4 v = *(const float4*)(s + i);
    *(__half2*)(h + i)     = __floats2half2_rn(v.x, v.y);
    *(__half2*)(h + i + 2) = __floats2half2_rn(v.z, v.w);
}

// ======= fused transpose: 8 matrices, src[K][N] fp32 -> dst [N][K] fp16 =====
struct TSpec { const float* src; __half* dst; int K; int N; int blk0; };
struct TTab  { TSpec e[8]; };

__global__ void transpose_all(TTab tab)
{
    __shared__ float t[32][33];
    int b = blockIdx.x;
    int ei = 0;
#pragma unroll
    for (int i = 1; i < 8; i++)
        if (b >= tab.e[i].blk0) ei = i;
    const TSpec sp = tab.e[ei];
    int lb = b - sp.blk0;
    int nbx = sp.N >> 5;
    int nb = (lb % nbx) * 32;
    int kb = (lb / nbx) * 32;

    int tx = threadIdx.x, ty = threadIdx.y;    // 32 x 8
#pragma unroll
    for (int i = 0; i < 32; i += 8)
        t[ty + i][tx] = sp.src[(size_t)(kb + ty + i) * sp.N + nb + tx];
    __syncthreads();
#pragma unroll
    for (int i = 0; i < 32; i += 8)
        sp.dst[(size_t)(nb + ty + i) * sp.K + kb + tx] = __float2half_rn(t[tx][ty + i]);
}

// ======================= HMMA fp16 GEMM =====================================
// C[M,N] = Ah[M,K] @ Bh[N,K]^T + bias.  CTA 128x128, 4 warps (warp tile 64x64),
// BK=32, 3-stage cp.async, 2 CTAs/SM.  Epilogue modes:
//   0 = fp32 C;  1 = fp16 [M,N];  2 = fp16 [B,H,S,192];  3 = fp16 [B,H,S,128]
#define BKP 40
#define MAT_SMEM (128*BKP*2)      // 10240
#define STG_SMEM (2*MAT_SMEM)     // 20480
#define GEMM_SMEM (3*STG_SMEM)    // 61440

__global__ void __launch_bounds__(128, 2) gemm_hmma1(
    const __half* __restrict__ Ah, const __half* __restrict__ Bh,
    const float* __restrict__ bias, float* __restrict__ C,
    __half* __restrict__ Ch,
    int M, int N, int K, int mode)
{
    extern __shared__ char dsm[];
    const uint32_t sbase = s2u(dsm);

    const int tid  = threadIdx.x;
    const int warp = tid >> 5, lane = tid & 31;
    const int wm = (warp & 1) * 64;
    const int wn = (warp >> 1) * 64;
    const int m0 = blockIdx.y * 128, n0 = blockIdx.x * 128;

    const __half* gM[2] = { Ah + (size_t)m0 * K, Bh + (size_t)n0 * K };

    const int nK = K >> 5;

    const int a_r  = lane & 15;
    const int a_c8 = (lane >> 4) << 3;
    const int b_r  = (lane & 7) + ((lane >> 4) << 3);
    const int b_c8 = (lane & 8) ? 8 : 0;

    float acc[4][8][4];
#pragma unroll
    for (int mt = 0; mt < 4; mt++)
#pragma unroll
        for (int nt = 0; nt < 8; nt++)
#pragma unroll
            for (int q = 0; q < 4; q++) acc[mt][nt][q] = 0.f;

    // per-stage load: 2 matrices x 128 rows x 4 chunks(16B); 128 threads x 4 ea.
    auto load_stage = [&](int stg, int kb) {
        uint32_t sb = sbase + stg * STG_SMEM;
#pragma unroll
        for (int mat = 0; mat < 2; mat++) {
            const __half* g = gM[mat];
#pragma unroll
            for (int j = 0; j < 4; j++) {
                int c = tid + j * 128;
                int row = c >> 2, c16 = c & 3;
                cpasync16(sb + mat * MAT_SMEM + (row * BKP + c16 * 8) * 2,
                          g + (size_t)row * K + kb + c16 * 8);
            }
        }
        asm volatile("cp.async.commit_group;" ::: "memory");
    };

    load_stage(0, 0);
    load_stage(1, 32);

    int cur = 0, nxt = 2;
    for (int i = 0; i < nK; i++) {
        if (i + 1 < nK) asm volatile("cp.async.wait_group 1;" ::: "memory");
        else            asm volatile("cp.async.wait_group 0;" ::: "memory");
        __syncthreads();
        if (i + 2 < nK) load_stage(nxt, (i + 2) * 32);

        const uint32_t sAh = sbase + cur * STG_SMEM;
        const uint32_t sBh = sAh + MAT_SMEM;

#pragma unroll
        for (int kk = 0; kk < 32; kk += 16) {
            uint32_t ah[4][4], bh[4][4];
#pragma unroll
            for (int mt = 0; mt < 4; mt++) {
                uint32_t off = ((wm + mt * 16 + a_r) * BKP + kk + a_c8) * 2;
                ldsm4(ah[mt], sAh + off);
            }
#pragma unroll
            for (int p = 0; p < 4; p++) {
                uint32_t off = ((wn + p * 16 + b_r) * BKP + kk + b_c8) * 2;
                ldsm4(bh[p], sBh + off);
            }
#pragma unroll
            for (int mt = 0; mt < 4; mt++)
#pragma unroll
                for (int nt = 0; nt < 8; nt++)
                    mmah(acc[mt][nt], ah[mt], &bh[nt >> 1][(nt & 1) * 2]);
        }
        cur = (cur == 2) ? 0 : cur + 1;
        nxt = (nxt == 2) ? 0 : nxt + 1;
    }

    // ---- epilogue ----
    const int er = lane >> 2, ec = (lane & 3) * 2;
#pragma unroll
    for (int mt = 0; mt < 4; mt++) {
#pragma unroll
        for (int nt = 0; nt < 8; nt++) {
            int col = n0 + wn + nt * 8 + ec;
            float b0 = bias[col], b1 = bias[col + 1];
            int r0 = m0 + wm + mt * 16 + er;
            int r1 = r0 + 8;
            float p0 = acc[mt][nt][0] + b0, p1 = acc[mt][nt][1] + b1;
            float p2 = acc[mt][nt][2] + b0, p3 = acc[mt][nt][3] + b1;
            if (mode == 0) {
                *(float2*)&C[(size_t)r0 * N + col] = make_float2(p0, p1);
                *(float2*)&C[(size_t)r1 * N + col] = make_float2(p2, p3);
            } else if (mode == 1) {
                whi2(Ch, (size_t)r0 * N + col, p0, p1);
                whi2(Ch, (size_t)r1 * N + col, p2, p3);
            } else {
                int hh = col >> 7, d = col & 127;
                int stride = (mode == 2) ? DQK : HD;
                size_t o0 = (((size_t)(r0 >> 11) * NHEADS + hh) * SEQ + (r0 & 2047)) * stride + d;
                size_t o1 = (((size_t)(r1 >> 11) * NHEADS + hh) * SEQ + (r1 & 2047)) * stride + d;
                whi2(Ch, o0, p0, p1);
                whi2(Ch, o1, p2, p3);
            }
        }
    }
}

// ------- RoPE into last 64 dims of K/Q --------------------------------------
__global__ void rope_pack(const float* __restrict__ kr, const float* __restrict__ qr,
                          __half* __restrict__ Kh, __half* __restrict__ Qh)
{
    int idx = blockIdx.x * blockDim.x + threadIdx.x;
    if (idx >= ROWS*NHEADS*(RD/2)) return;
    int i  = idx & 31;
    int h  = (idx >> 5) & 15;
    int bs = idx >> 9;
    int b  = bs >> 11;
    int s  = bs & 2047;
    float inv_freq = powf(10000.f, -(float)(2*i) / 64.f);
    float ang = (float)s * inv_freq;
    float sn, cs;
    sincosf(ang, &sn, &cs);
    size_t ib = (size_t)bs * (NHEADS*RD) + h*RD + 2*i;
    size_t ob = (((size_t)b*NHEADS + h)*SEQ + s)*DQK + HD + 2*i;
    float x1 = kr[ib], x2 = kr[ib+1];
    whi2(Kh, ob, x1*cs - x2*sn, x1*sn + x2*cs);
    x1 = qr[ib]; x2 = qr[ib+1];
    whi2(Qh, ob, x1*cs - x2*sn, x1*sn + x2*cs);
}

// ============== HMMA fp16 causal flash attention ============================
// CTA: 128 queries x full head. 8 warps, warp = 16 query rows.
// LPT: blockIdx.x reversed so heavy (high-q0) CTAs schedule first.
#define AQH 0
#define AKB(buf) (49152 + (buf)*24576)
#define AVB 98304
#define ATTN_SMEM 114688

__global__ void __launch_bounds__(256, 1) attn_hmma(
    const __half* __restrict__ Qhg,
    const __half* __restrict__ Khg, const __half* __restrict__ Vhg,
    __half* __restrict__ cxh)
{
    extern __shared__ char smc[];
    const uint32_t sb = s2u(smc);
    const int b = blockIdx.z, h = blockIdx.y;
    const int q0 = (gridDim.x - 1 - blockIdx.x) * 128;   // LPT: heavy first
    const int tid = threadIdx.x, w = tid >> 5, lane = tid & 31;
    const int ntiles = (q0 >> 6) + 2;

    const size_t hb = (size_t)(b*NHEADS + h) * SEQ;
    const __half* gQh = Qhg + (hb + q0) * DQK;
    const __half* gKh = Khg + hb * DQK;
    const __half* gVh = Vhg + hb * HD;

    auto ldQ = [&](uint32_t dst, const __half* g) {
        for (int i = tid; i < 128*24; i += 256) {
            int r = i / 24, c = i % 24;
            int cs = (c & ~7) | ((c ^ r) & 7);
            cpasync16(dst + (r*24 + cs)*16, g + r*192 + c*8);
        }
    };
    auto ldK = [&](uint32_t dst, const __half* g) {
        for (int i = tid; i < 64*24; i += 256) {
            int r = i / 24, c = i % 24;
            int cs = (c & ~7) | ((c ^ r) & 7);
            cpasync16(dst + (r*24 + cs)*16, g + r*192 + c*8);
        }
    };
    auto ldV = [&](uint32_t dst, const __half* g) {
        for (int i = tid; i < 64*16; i += 256) {
            int r = i / 16, c = i % 16;
            int cs = (c & ~7) | ((c ^ r) & 7);
            cpasync16(dst + (r*16 + cs)*16, g + r*128 + c*8);
        }
    };

    // prologue: group0 = {Q, K0, V0}, group1 = {K1}
    ldQ(sb + AQH, gQh);
    ldK(sb + AKB(0), gKh);
    ldV(sb + AVB,    gVh);
    asm volatile("cp.async.commit_group;" ::: "memory");
    ldK(sb + AKB(1), gKh + 64*192);
    asm volatile("cp.async.commit_group;" ::: "memory");

    float O[16][4];
#pragma unroll
    for (int t = 0; t < 16; t++)
#pragma unroll
        for (int j = 0; j < 4; j++) O[t][j] = 0.f;
    float m0r = -1e30f, m1r = -1e30f, l0 = 0.f, l1 = 0.f;

    const float scale = 0.07216878364870323f;  // 1/sqrt(192)
    const int lrow = lane & 15, lhi = lane >> 4;
    const int qr0 = q0 + w*16 + (lane >> 2);

    for (int i = 0; i < ntiles; i++) {
        const int k0 = i * 64;
        asm volatile("cp.async.wait_group 1;" ::: "memory");
        __syncthreads();

        const uint32_t kbh = sb + AKB(i & 1);

        float s[8][4];
#pragma unroll
        for (int t = 0; t < 8; t++)
#pragma unroll
            for (int j = 0; j < 4; j++) s[t][j] = 0.f;

        // ---- S = Q K^T ----
#pragma unroll
        for (int kc = 0; kc < 12; kc++) {
            uint32_t ah[4];
            {
                int r = w*16 + lrow;
                int c = kc*2 + lhi;
                int cs = (c & ~7) | ((c ^ r) & 7);
                ldsm4(ah, sb + AQH + (r*24 + cs)*16);
            }
#pragma unroll
            for (int kg = 0; kg < 4; kg++) {
                uint32_t bh[4];
                int r = kg*16 + lrow;
                int c = kc*2 + lhi;
                int cs = (c & ~7) | ((c ^ r) & 7);
                ldsm4(bh, kbh + (r*24 + cs)*16);
                mmahs(s[kg*2],   ah, bh[0], bh[2]);
                mmahs(s[kg*2+1], ah, bh[1], bh[3]);
            }
        }

        // ---- online softmax ----
        if (k0 + 63 > q0 + w*16) {
#pragma unroll
            for (int t = 0; t < 8; t++) {
                int kb = k0 + t*8 + ((lane & 3) << 1);
                s[t][0] = (kb     <= qr0    ) ? s[t][0]*scale : -1e30f;
                s[t][1] = (kb + 1 <= qr0    ) ? s[t][1]*scale : -1e30f;
                s[t][2] = (kb     <= qr0 + 8) ? s[t][2]*scale : -1e30f;
                s[t][3] = (kb + 1 <= qr0 + 8) ? s[t][3]*scale : -1e30f;
            }
        } else {
#pragma unroll
            for (int t = 0; t < 8; t++)
#pragma unroll
                for (int j = 0; j < 4; j++) s[t][j] *= scale;
        }

        float mx0 = -1e30f, mx1 = -1e30f;
#pragma unroll
        for (int t = 0; t < 8; t++) {
            mx0 = fmaxf(mx0, fmaxf(s[t][0], s[t][1]));
            mx1 = fmaxf(mx1, fmaxf(s[t][2], s[t][3]));
        }
        mx0 = fmaxf(mx0, __shfl_xor_sync(0xffffffffu, mx0, 1));
        mx0 = fmaxf(mx0, __shfl_xor_sync(0xffffffffu, mx0, 2));
        mx1 = fmaxf(mx1, __shfl_xor_sync(0xffffffffu, mx1, 1));
        mx1 = fmaxf(mx1, __shfl_xor_sync(0xffffffffu, mx1, 2));

        float mn0 = fmaxf(m0r, mx0), mn1 = fmaxf(m1r, mx1);
        float al0 = __expf(m0r - mn0), al1 = __expf(m1r - mn1);
        m0r = mn0; m1r = mn1;

        float sum0 = 0.f, sum1 = 0.f;
#pragma unroll
        for (int t = 0; t < 8; t++) {
            s[t][0] = __expf(s[t][0] - mn0); sum0 += s[t][0];
            s[t][1] = __expf(s[t][1] - mn0); sum0 += s[t][1];
            s[t][2] = __expf(s[t][2] - mn1); sum1 += s[t][2];
            s[t][3] = __expf(s[t][3] - mn1); sum1 += s[t][3];
        }
        l0 = l0*al0 + sum0;
        l1 = l1*al1 + sum1;
#pragma unroll
        for (int t = 0; t < 16; t++) {
            O[t][0] *= al0; O[t][1] *= al0;
            O[t][2] *= al1; O[t][3] *= al1;
        }

        // ---- O += P V ----
#pragma unroll
        for (int kc2 = 0; kc2 < 4; kc2++) {
            uint32_t pha[4];
            pha[0] = pack2h(s[kc2*2][0],   s[kc2*2][1]);
            pha[1] = pack2h(s[kc2*2][2],   s[kc2*2][3]);
            pha[2] = pack2h(s[kc2*2+1][0], s[kc2*2+1][1]);
            pha[3] = pack2h(s[kc2*2+1][2], s[kc2*2+1][3]);
#pragma unroll
            for (int dg = 0; dg < 8; dg++) {
                uint32_t vh[4];
                int r = kc2*16 + lrow;
                int c = dg*2 + lhi;
                int cs = (c & ~7) | ((c ^ r) & 7);
                ldsm4t(vh, sb + AVB + (r*16 + cs)*16);
                mmahs(O[dg*2],   pha, vh[0], vh[1]);
                mmahs(O[dg*2+1], pha, vh[2], vh[3]);
            }
        }
        __syncthreads();

        if (i + 1 < ntiles)
            ldV(sb + AVB, gVh + (size_t)(k0 + 64)*HD);
        asm volatile("cp.async.commit_group;" ::: "memory");
        if (i + 2 < ntiles)
            ldK(sb + AKB(i & 1), gKh + (size_t)(k0 + 128)*DQK);
        asm volatile("cp.async.commit_group;" ::: "memory");
    }

    l0 += __shfl_xor_sync(0xffffffffu, l0, 1);
    l0 += __shfl_xor_sync(0xffffffffu, l0, 2);
    l1 += __shfl_xor_sync(0xffffffffu, l1, 1);
    l1 += __shfl_xor_sync(0xffffffffu, l1, 2);
    float inv0 = 1.f / l0, inv1 = 1.f / l1;

#pragma unroll
    for (int t = 0; t < 16; t++) {
        int d = h*HD + t*8 + ((lane & 3) << 1);
        size_t ro0 = (size_t)(b*SEQ + qr0    ) * (NHEADS*HD) + d;
        size_t ro1 = (size_t)(b*SEQ + qr0 + 8) * (NHEADS*HD) + d;
        whi2(cxh, ro0, O[t][0]*inv0, O[t][1]*inv0);
        whi2(cxh, ro1, O[t][2]*inv1, O[t][3]*inv1);
    }
}

// ---------------- launch -----------------------------------------------------
static inline void gemm_m(const __half* Ah, const __half* Bh,
                          const float* bias, float* C, __half* Ch,
                          int M, int N, int K, int mode)
{
    gemm_hmma1<<<dim3(N/128, M/128), 128, GEMM_SMEM>>>(
        Ah, Bh, bias, C, Ch, M, N, K, mode);
}

extern "C" void kernel_launch(void* const* d_in, const int* in_sizes, int n_in,
                              void* d_out, int out_size)
{
    const float* x    = (const float*)d_in[0];
    const float* kvdw = (const float*)d_in[2];
    const float* kvdb = (const float*)d_in[3];
    const float* kuw  = (const float*)d_in[4];
    const float* kub  = (const float*)d_in[5];
    const float* vuw  = (const float*)d_in[6];
    const float* vub  = (const float*)d_in[7];
    const float* krw  = (const float*)d_in[8];
    const float* krb  = (const float*)d_in[9];
    const float* qdw  = (const float*)d_in[10];
    const float* qdb  = (const float*)d_in[11];
    const float* quw  = (const float*)d_in[12];
    const float* qub  = (const float*)d_in[13];
    const float* qrw  = (const float*)d_in[14];
    const float* qrb  = (const float*)d_in[15];
    const float* ow   = (const float*)d_in[16];
    const float* obv  = (const float*)d_in[17];
    float* out = (float*)d_out;

    float *kr, *qru;
    cudaGetSymbolAddress((void**)&kr,   g_kr);
    cudaGetSymbolAddress((void**)&qru,  g_qru);

    __half *Qh,*Kh,*Vh;
    cudaGetSymbolAddress((void**)&Qh, g_Qh);
    cudaGetSymbolAddress((void**)&Kh, g_Kh);
    cudaGetSymbolAddress((void**)&Vh, g_Vh);

    __half *xh,*kvch,*qlh,*cxh;
    __half *kvdwh,*kuwh,*vuwh,*krwh,*qdwh,*quwh,*qrwh,*owh;
    cudaGetSymbolAddress((void**)&xh, g_xh);
    cudaGetSymbolAddress((void**)&kvch, g_kvch);
    cudaGetSymbolAddress((void**)&qlh, g_qlh);
    cudaGetSymbolAddress((void**)&cxh, g_cxh);
    cudaGetSymbolAddress((void**)&kvdwh, g_kvdwh);
    cudaGetSymbolAddress((void**)&kuwh, g_kuwh);
    cudaGetSymbolAddress((void**)&vuwh, g_vuwh);
    cudaGetSymbolAddress((void**)&krwh, g_krwh);
    cudaGetSymbolAddress((void**)&qdwh, g_qdwh);
    cudaGetSymbolAddress((void**)&quwh, g_quwh);
    cudaGetSymbolAddress((void**)&qrwh, g_qrwh);
    cudaGetSymbolAddress((void**)&owh, g_owh);

    cudaFuncSetAttribute(gemm_hmma1, cudaFuncAttributeMaxDynamicSharedMemorySize, GEMM_SMEM);
    cudaFuncSetAttribute(attn_hmma, cudaFuncAttributeMaxDynamicSharedMemorySize, ATTN_SMEM);

    // fused weight transpose (8 matrices in one launch)
    {
        TTab tab;
        auto set = [&](int i, const float* s, __half* d, int K, int N, int blk0) {
            tab.e[i].src = s; tab.e[i].dst = d;
            tab.e[i].K = K; tab.e[i].N = N; tab.e[i].blk0 = blk0;
        };
        int b = 0;
        set(0, kvdw, kvdwh, HIDDEN, KVC, b);       b += (KVC/32)*(HIDDEN/32);
        set(1, kuw,  kuwh,  KVC, NHEADS*HD, b);    b += (NHEADS*HD/32)*(KVC/32);
        set(2, vuw,  vuwh,  KVC, NHEADS*HD, b);    b += (NHEADS*HD/32)*(KVC/32);
        set(3, krw,  krwh,  KVC, NHEADS*RD, b);    b += (NHEADS*RD/32)*(KVC/32);
        set(4, qdw,  qdwh,  HIDDEN, QC, b);        b += (QC/32)*(HIDDEN/32);
        set(5, quw,  quwh,  QC, NHEADS*HD, b);     b += (NHEADS*HD/32)*(QC/32);
        set(6, qrw,  qrwh,  QC, NHEADS*RD, b);     b += (NHEADS*RD/32)*(QC/32);
        set(7, ow,   owh,   NHEADS*HD, HIDDEN, b); b += (HIDDEN/32)*(NHEADS*HD/32);
        transpose_all<<<b, dim3(32, 8)>>>(tab);
    }

    // x convert
    conv_half<<<ROWS*HIDDEN/4/256, 256>>>(x, xh, ROWS*HIDDEN);

    // kv path
    gemm_m(xh,   kvdwh, kvdb, nullptr, kvch, ROWS, KVC,       HIDDEN, 1);
    gemm_m(kvch, kuwh,  kub,  nullptr, Kh,   ROWS, NHEADS*HD, KVC,    2);
    gemm_m(kvch, vuwh,  vub,  nullptr, Vh,   ROWS, NHEADS*HD, KVC,    3);
    gemm_m(kvch, krwh,  krb,  kr, nullptr,   ROWS, NHEADS*RD, KVC,    0);

    // q path
    gemm_m(xh,  qdwh, qdb, nullptr, qlh, ROWS, QC,        HIDDEN, 1);
    gemm_m(qlh, quwh, qub, nullptr, Qh,  ROWS, NHEADS*HD, QC,     2);
    gemm_m(qlh, qrwh, qrb, qru, nullptr, ROWS, NHEADS*RD, QC,     0);

    // rope into last 64 dims
    rope_pack<<<ROWS*NHEADS*(RD/2)/256, 256>>>(kr, qru, Kh, Qh);

    // attention (fp16 HMMA)
    attn_hmma<<<dim3(SEQ/128, NHEADS, BATCH), 256, ATTN_SMEM>>>(Qh, Kh, Vh, cxh);

    // output projection
    gemm_m(cxh, owh, obv, out, nullptr, ROWS, HIDDEN, NHEADS*HD, 0);
}